// round 1
// baseline (speedup 1.0000x reference)
#include <cuda_runtime.h>
#include <math.h>

// Problem constants
#define SEQ   2048
#define DIM   2048
#define NH    16
#define HDIM  128
#define HIDN  8192
#define EPSV  1e-6f
#define LAMB0 0.8f

// ---------------- scratch (device globals; no allocation allowed) ----------------
__device__ float g_h0[SEQ * DIM];
__device__ float g_q1[SEQ * DIM];
__device__ float g_q2[SEQ * DIM];
__device__ float g_k1[SEQ * DIM];
__device__ float g_k2[SEQ * DIM];
__device__ float g_v [SEQ * DIM];
__device__ float g_s1[(size_t)NH * SEQ * SEQ];   // scores / combined P (in-place)
__device__ float g_s2[(size_t)NH * SEQ * SEQ];
__device__ float g_o [SEQ * DIM];
__device__ float g_h [SEQ * DIM];
__device__ float g_z [SEQ * DIM];
__device__ float g_G1[(size_t)SEQ * HIDN];
__device__ float g_G2[(size_t)SEQ * HIDN];
__device__ float g_U [(size_t)SEQ * HIDN];
__device__ float g_lam[NH];

// ---------------- block reductions (256 threads) ----------------
__device__ __forceinline__ float blockReduceSum256(float v) {
    __shared__ float sh[8];
    #pragma unroll
    for (int o = 16; o; o >>= 1) v += __shfl_xor_sync(0xffffffffu, v, o);
    __syncthreads();
    if ((threadIdx.x & 31) == 0) sh[threadIdx.x >> 5] = v;
    __syncthreads();
    float r = 0.f;
    #pragma unroll
    for (int i = 0; i < 8; i++) r += sh[i];
    return r;
}

__device__ __forceinline__ float blockReduceMax256(float v) {
    __shared__ float sh[8];
    #pragma unroll
    for (int o = 16; o; o >>= 1) v = fmaxf(v, __shfl_xor_sync(0xffffffffu, v, o));
    __syncthreads();
    if ((threadIdx.x & 31) == 0) sh[threadIdx.x >> 5] = v;
    __syncthreads();
    float r = sh[0];
    #pragma unroll
    for (int i = 1; i < 8; i++) r = fmaxf(r, sh[i]);
    return r;
}

// ---------------- RMSNorm ----------------
__global__ __launch_bounds__(256) void rmsnorm_kernel(const float* __restrict__ x,
                                                      const float* __restrict__ g,
                                                      float* __restrict__ y) {
    const long row = blockIdx.x;
    const float* xr = x + row * (long)DIM;
    float v[8];
    float ss = 0.f;
    #pragma unroll
    for (int i = 0; i < 8; i++) {
        v[i] = xr[threadIdx.x + 256 * i];
        ss += v[i] * v[i];
    }
    float tot = blockReduceSum256(ss);
    float scale = rsqrtf(tot * (1.0f / DIM) + EPSV);
    float* yr = y + row * (long)DIM;
    #pragma unroll
    for (int i = 0; i < 8; i++) {
        int c = threadIdx.x + 256 * i;
        yr[c] = v[i] * scale * g[c];
    }
}

// ---------------- per-head lambda ----------------
__global__ void lambda_kernel(const float* __restrict__ lq1, const float* __restrict__ lk1,
                              const float* __restrict__ lq2, const float* __restrict__ lk2,
                              float* __restrict__ lam) {
    __shared__ float sh1[128], sh2[128];
    int h = blockIdx.x, t = threadIdx.x;
    int i = h * HDIM + t;
    sh1[t] = lq1[i] * lk1[i];
    sh2[t] = lq2[i] * lk2[i];
    __syncthreads();
    for (int o = 64; o; o >>= 1) {
        if (t < o) { sh1[t] += sh1[t + o]; sh2[t] += sh2[t + o]; }
        __syncthreads();
    }
    if (t == 0) lam[h] = expf(sh1[0]) - expf(sh2[0]) + LAMB0;
}

// ---------------- generic tiled GEMM (128x128x16, 256 thr, 8x8/thread) ----------------
// C[z] = alpha * A[z] * B[z] (+ R[z])
// non-TRANSB: B element (k, n0+nl) = B[z*sB + (n0/128)*hsB + k*ldb + nl]
//   -> standard row-major [K,N]: hsB=128, ldb=N.  Head-blocked [H,D,DH]: hsB=D*DH, ldb=DH.
// TRANSB: B element (k, n0+nl) = B[z*sB + (n0+nl)*ldb + k]   (B^T, row-major [N,K])
template <bool TRANSB>
__global__ __launch_bounds__(256) void gemm_kernel(
    const float* __restrict__ A, int lda, long sA,
    const float* __restrict__ B, int ldb, long sB, long hsB,
    float* __restrict__ C, int ldc, long sC,
    int K, float alpha,
    const float* __restrict__ R, long sR)
{
    __shared__ float As[16][128];
    __shared__ float Bs[16][128];

    const int n0 = blockIdx.x * 128;
    const int m0 = blockIdx.y * 128;
    const int z  = blockIdx.z;

    A += (long)z * sA + (long)m0 * lda;
    if (TRANSB) B += (long)z * sB + (long)n0 * ldb;
    else        B += (long)z * sB + (long)blockIdx.x * hsB;
    C += (long)z * sC + (long)m0 * ldc + n0;
    if (R) R += (long)z * sR + (long)m0 * ldc + n0;

    const int tid = threadIdx.x;
    const int tx = tid & 15;       // 0..15 -> col group
    const int ty = tid >> 4;       // 0..15 -> row group

    float acc[8][8];
    #pragma unroll
    for (int i = 0; i < 8; i++)
        #pragma unroll
        for (int j = 0; j < 8; j++) acc[i][j] = 0.f;

    for (int k0 = 0; k0 < K; k0 += 16) {
        // load A tile 128x16 (transposed into As[k][m])
        #pragma unroll
        for (int it = 0; it < 2; it++) {
            int idx = tid + it * 256;          // 0..511
            int row = idx >> 2;                // 0..127
            int c4  = (idx & 3) * 4;           // 0,4,8,12
            float4 va = *(const float4*)(A + (long)row * lda + k0 + c4);
            As[c4 + 0][row] = va.x;
            As[c4 + 1][row] = va.y;
            As[c4 + 2][row] = va.z;
            As[c4 + 3][row] = va.w;
        }
        // load B tile 16x128
        if (TRANSB) {
            #pragma unroll
            for (int it = 0; it < 2; it++) {
                int idx = tid + it * 256;
                int nl = idx >> 2;             // 0..127
                int c4 = (idx & 3) * 4;
                float4 vb = *(const float4*)(B + (long)nl * ldb + k0 + c4);
                Bs[c4 + 0][nl] = vb.x;
                Bs[c4 + 1][nl] = vb.y;
                Bs[c4 + 2][nl] = vb.z;
                Bs[c4 + 3][nl] = vb.w;
            }
        } else {
            #pragma unroll
            for (int it = 0; it < 2; it++) {
                int idx = tid + it * 256;
                int row = idx >> 5;            // 0..15
                int c4  = (idx & 31) * 4;      // 0..124
                float4 vb = *(const float4*)(B + (long)(k0 + row) * ldb + c4);
                *(float4*)&Bs[row][c4] = vb;
            }
        }
        __syncthreads();

        #pragma unroll
        for (int k = 0; k < 16; k++) {
            float a[8], b[8];
            #pragma unroll
            for (int i = 0; i < 8; i++) a[i] = As[k][ty * 8 + i];
            #pragma unroll
            for (int j = 0; j < 8; j++) b[j] = Bs[k][tx * 8 + j];
            #pragma unroll
            for (int i = 0; i < 8; i++)
                #pragma unroll
                for (int j = 0; j < 8; j++)
                    acc[i][j] = fmaf(a[i], b[j], acc[i][j]);
        }
        __syncthreads();
    }

    // epilogue
    #pragma unroll
    for (int i = 0; i < 8; i++) {
        long roff = (long)(ty * 8 + i) * ldc + tx * 8;
        if (R) {
            #pragma unroll
            for (int j = 0; j < 8; j++)
                C[roff + j] = acc[i][j] * alpha + R[roff + j];
        } else {
            #pragma unroll
            for (int j = 0; j < 8; j++)
                C[roff + j] = acc[i][j] * alpha;
        }
    }
}

// ---------------- softmax over both branches + combine: P = softmax(S1) - lam*softmax(S2) ----------------
__global__ __launch_bounds__(256) void softmax_combine_kernel(float* __restrict__ s1,
                                                              const float* __restrict__ s2,
                                                              const float* __restrict__ lam) {
    const long off = (long)blockIdx.y * SEQ * SEQ + (long)blockIdx.x * SEQ;
    float* r1 = s1 + off;
    const float* r2 = s2 + off;
    const int t = threadIdx.x;

    float v1[8], v2[8];
    #pragma unroll
    for (int i = 0; i < 8; i++) v1[i] = r1[t + 256 * i];
    float m1 = -1e30f;
    #pragma unroll
    for (int i = 0; i < 8; i++) m1 = fmaxf(m1, v1[i]);
    m1 = blockReduceMax256(m1);
    float ps = 0.f;
    #pragma unroll
    for (int i = 0; i < 8; i++) { v1[i] = expf(v1[i] - m1); ps += v1[i]; }
    float sum1 = blockReduceSum256(ps);

    #pragma unroll
    for (int i = 0; i < 8; i++) v2[i] = r2[t + 256 * i];
    float m2 = -1e30f;
    #pragma unroll
    for (int i = 0; i < 8; i++) m2 = fmaxf(m2, v2[i]);
    m2 = blockReduceMax256(m2);
    ps = 0.f;
    #pragma unroll
    for (int i = 0; i < 8; i++) { v2[i] = expf(v2[i] - m2); ps += v2[i]; }
    float sum2 = blockReduceSum256(ps);

    const float l  = lam[blockIdx.y];
    const float i1 = 1.f / sum1;
    const float i2 = l / sum2;
    #pragma unroll
    for (int i = 0; i < 8; i++)
        r1[t + 256 * i] = v1[i] * i1 - v2[i] * i2;
}

// ---------------- SwiGLU elementwise ----------------
__global__ __launch_bounds__(256) void swiglu_kernel(const float* __restrict__ g1,
                                                     const float* __restrict__ g2,
                                                     float* __restrict__ u) {
    long i = (long)blockIdx.x * 256 + threadIdx.x;
    float a = g1[i];
    u[i] = a / (1.f + expf(-a)) * g2[i];
}

// ---------------- launcher ----------------
extern "C" void kernel_launch(void* const* d_in, const int* in_sizes, int n_in,
                              void* d_out, int out_size) {
    (void)in_sizes; (void)n_in; (void)out_size;
    const float* x   = (const float*)d_in[0];
    const float* gn  = (const float*)d_in[1];
    const float* Wq1 = (const float*)d_in[2];
    const float* Wq2 = (const float*)d_in[3];
    const float* Wk1 = (const float*)d_in[4];
    const float* Wk2 = (const float*)d_in[5];
    const float* Wv  = (const float*)d_in[6];
    const float* lq1 = (const float*)d_in[7];
    const float* lk1 = (const float*)d_in[8];
    const float* lq2 = (const float*)d_in[9];
    const float* lk2 = (const float*)d_in[10];
    const float* Wo  = (const float*)d_in[11];
    const float* W1  = (const float*)d_in[12];
    const float* W2  = (const float*)d_in[13];
    const float* W3  = (const float*)d_in[14];
    float* out = (float*)d_out;

    float *h0, *q1, *q2, *k1, *k2, *v, *s1, *s2, *o, *h, *z, *G1, *G2, *U, *lam;
    cudaGetSymbolAddress((void**)&h0, g_h0);
    cudaGetSymbolAddress((void**)&q1, g_q1);
    cudaGetSymbolAddress((void**)&q2, g_q2);
    cudaGetSymbolAddress((void**)&k1, g_k1);
    cudaGetSymbolAddress((void**)&k2, g_k2);
    cudaGetSymbolAddress((void**)&v,  g_v);
    cudaGetSymbolAddress((void**)&s1, g_s1);
    cudaGetSymbolAddress((void**)&s2, g_s2);
    cudaGetSymbolAddress((void**)&o,  g_o);
    cudaGetSymbolAddress((void**)&h,  g_h);
    cudaGetSymbolAddress((void**)&z,  g_z);
    cudaGetSymbolAddress((void**)&G1, g_G1);
    cudaGetSymbolAddress((void**)&G2, g_G2);
    cudaGetSymbolAddress((void**)&U,  g_U);
    cudaGetSymbolAddress((void**)&lam, g_lam);

    const long HS  = (long)DIM * HDIM;       // 262144 head stride in W[h,d,e]
    const long SS  = (long)SEQ * SEQ;
    const float qkscale = 0.08838834764831845f;   // 1/sqrt(128)

    // 1) h0 = rmsnorm(x)
    rmsnorm_kernel<<<SEQ, 256>>>(x, gn, h0);

    // 2) projections: [S,D] @ [H,D,DH] -> [S, H*DH]
    dim3 gproj(DIM / 128, SEQ / 128, 1);
    gemm_kernel<false><<<gproj, 256>>>(h0, DIM, 0, Wq1, HDIM, 0, HS, q1, DIM, 0, DIM, 1.f, nullptr, 0);
    gemm_kernel<false><<<gproj, 256>>>(h0, DIM, 0, Wq2, HDIM, 0, HS, q2, DIM, 0, DIM, 1.f, nullptr, 0);
    gemm_kernel<false><<<gproj, 256>>>(h0, DIM, 0, Wk1, HDIM, 0, HS, k1, DIM, 0, DIM, 1.f, nullptr, 0);
    gemm_kernel<false><<<gproj, 256>>>(h0, DIM, 0, Wk2, HDIM, 0, HS, k2, DIM, 0, DIM, 1.f, nullptr, 0);
    gemm_kernel<false><<<gproj, 256>>>(h0, DIM, 0, Wv,  HDIM, 0, HS, v,  DIM, 0, DIM, 1.f, nullptr, 0);

    // 3) per-head lambda
    lambda_kernel<<<NH, 128>>>(lq1, lk1, lq2, lk2, lam);

    // 4) scores: S1 = q1 k1^T * scale, S2 = q2 k2^T * scale   (batched over heads)
    dim3 gqk(SEQ / 128, SEQ / 128, NH);
    gemm_kernel<true><<<gqk, 256>>>(q1, DIM, HDIM, k1, DIM, HDIM, 0, s1, SEQ, SS, HDIM, qkscale, nullptr, 0);
    gemm_kernel<true><<<gqk, 256>>>(q2, DIM, HDIM, k2, DIM, HDIM, 0, s2, SEQ, SS, HDIM, qkscale, nullptr, 0);

    // 5) P = softmax(S1) - lam*softmax(S2)   (into s1)
    dim3 gsm(SEQ, NH);
    softmax_combine_kernel<<<gsm, 256>>>(s1, s2, lam);

    // 6) O = P @ V per head -> [S, H*DH]
    dim3 gpv(1, SEQ / 128, NH);
    gemm_kernel<false><<<gpv, 256>>>(s1, SEQ, SS, v, DIM, HDIM, 128, o, DIM, HDIM, SEQ, 1.f, nullptr, 0);

    // 7) h = O @ Wo + h0
    dim3 gwo(DIM / 128, SEQ / 128, 1);
    gemm_kernel<false><<<gwo, 256>>>(o, DIM, 0, Wo, DIM, 0, 128, h, DIM, 0, DIM, 1.f, h0, 0);

    // 8) z = rmsnorm(h)
    rmsnorm_kernel<<<SEQ, 256>>>(h, gn, z);

    // 9) G1 = z@W1, G2 = z@W2
    dim3 gffn(HIDN / 128, SEQ / 128, 1);
    gemm_kernel<false><<<gffn, 256>>>(z, DIM, 0, W1, HIDN, 0, 128, G1, HIDN, 0, DIM, 1.f, nullptr, 0);
    gemm_kernel<false><<<gffn, 256>>>(z, DIM, 0, W2, HIDN, 0, 128, G2, HIDN, 0, DIM, 1.f, nullptr, 0);

    // 10) U = silu(G1) * G2
    swiglu_kernel<<<(SEQ * (long)HIDN) / 256, 256>>>(G1, G2, U);

    // 11) out = U @ W3 + h
    dim3 gw3(DIM / 128, SEQ / 128, 1);
    gemm_kernel<false><<<gw3, 256>>>(U, HIDN, 0, W3, DIM, 0, 128, out, DIM, 0, HIDN, 1.f, h, 0);
}

// round 2
// speedup vs baseline: 1.0011x; 1.0011x over previous
#include <cuda_runtime.h>
#include <math.h>

// Problem constants
#define SEQ   2048
#define DIM   2048
#define NH    16
#define HDIM  128
#define HIDN  8192
#define EPSV  1e-6f
#define LAMB0 0.8f

// ---------------- scratch (device globals; no allocation allowed) ----------------
__device__ float g_h0[SEQ * DIM];
__device__ float g_q1[SEQ * DIM];
__device__ float g_q2[SEQ * DIM];
__device__ float g_k1[SEQ * DIM];
__device__ float g_k2[SEQ * DIM];
__device__ float g_v [SEQ * DIM];
__device__ float g_s1[(size_t)NH * SEQ * SEQ];   // scores / combined P (in-place)
__device__ float g_s2[(size_t)NH * SEQ * SEQ];
__device__ float g_o [SEQ * DIM];
__device__ float g_h [SEQ * DIM];
__device__ float g_z [SEQ * DIM];
__device__ float g_G1[(size_t)SEQ * HIDN];
__device__ float g_G2[(size_t)SEQ * HIDN];
__device__ float g_U [(size_t)SEQ * HIDN];
__device__ float g_lam[NH];

// ---------------- block reductions (256 threads) ----------------
__device__ __forceinline__ float blockReduceSum256(float v) {
    __shared__ float sh[8];
    #pragma unroll
    for (int o = 16; o; o >>= 1) v += __shfl_xor_sync(0xffffffffu, v, o);
    __syncthreads();
    if ((threadIdx.x & 31) == 0) sh[threadIdx.x >> 5] = v;
    __syncthreads();
    float r = 0.f;
    #pragma unroll
    for (int i = 0; i < 8; i++) r += sh[i];
    return r;
}

__device__ __forceinline__ float blockReduceMax256(float v) {
    __shared__ float sh[8];
    #pragma unroll
    for (int o = 16; o; o >>= 1) v = fmaxf(v, __shfl_xor_sync(0xffffffffu, v, o));
    __syncthreads();
    if ((threadIdx.x & 31) == 0) sh[threadIdx.x >> 5] = v;
    __syncthreads();
    float r = sh[0];
    #pragma unroll
    for (int i = 1; i < 8; i++) r = fmaxf(r, sh[i]);
    return r;
}

// ---------------- RMSNorm ----------------
__global__ __launch_bounds__(256) void rmsnorm_kernel(const float* __restrict__ x,
                                                      const float* __restrict__ g,
                                                      float* __restrict__ y) {
    const long row = blockIdx.x;
    const float* xr = x + row * (long)DIM;
    float v[8];
    float ss = 0.f;
    #pragma unroll
    for (int i = 0; i < 8; i++) {
        v[i] = xr[threadIdx.x + 256 * i];
        ss += v[i] * v[i];
    }
    float tot = blockReduceSum256(ss);
    float scale = rsqrtf(tot * (1.0f / DIM) + EPSV);
    float* yr = y + row * (long)DIM;
    #pragma unroll
    for (int i = 0; i < 8; i++) {
        int c = threadIdx.x + 256 * i;
        yr[c] = v[i] * scale * g[c];
    }
}

// ---------------- per-head lambda ----------------
__global__ void lambda_kernel(const float* __restrict__ lq1, const float* __restrict__ lk1,
                              const float* __restrict__ lq2, const float* __restrict__ lk2,
                              float* __restrict__ lam) {
    __shared__ float sh1[128], sh2[128];
    int h = blockIdx.x, t = threadIdx.x;
    int i = h * HDIM + t;
    sh1[t] = lq1[i] * lk1[i];
    sh2[t] = lq2[i] * lk2[i];
    __syncthreads();
    for (int o = 64; o; o >>= 1) {
        if (t < o) { sh1[t] += sh1[t + o]; sh2[t] += sh2[t + o]; }
        __syncthreads();
    }
    if (t == 0) lam[h] = expf(sh1[0]) - expf(sh2[0]) + LAMB0;
}

// ---------------- generic tiled GEMM (128x128x16, 256 thr, 8x8/thread) ----------------
// C[z] = alpha * A[z] * B[z] (+ R[z])
// non-TRANSB: B element (k, n0+nl) = B[z*sB + (n0/128)*hsB + k*ldb + nl]
//   -> standard row-major [K,N]: hsB=128, ldb=N.  Head-blocked [H,D,DH]: hsB=D*DH, ldb=DH.
// TRANSB: B element (k, n0+nl) = B[z*sB + (n0+nl)*ldb + k]   (B^T, row-major [N,K])
template <bool TRANSB>
__global__ __launch_bounds__(256) void gemm_kernel(
    const float* __restrict__ A, int lda, long sA,
    const float* __restrict__ B, int ldb, long sB, long hsB,
    float* __restrict__ C, int ldc, long sC,
    int K, float alpha,
    const float* __restrict__ R, long sR)
{
    __shared__ float As[16][128];
    __shared__ float Bs[16][128];

    const int n0 = blockIdx.x * 128;
    const int m0 = blockIdx.y * 128;
    const int z  = blockIdx.z;

    A += (long)z * sA + (long)m0 * lda;
    if (TRANSB) B += (long)z * sB + (long)n0 * ldb;
    else        B += (long)z * sB + (long)blockIdx.x * hsB;
    C += (long)z * sC + (long)m0 * ldc + n0;
    if (R) R += (long)z * sR + (long)m0 * ldc + n0;

    const int tid = threadIdx.x;
    const int tx = tid & 15;       // 0..15 -> col group
    const int ty = tid >> 4;       // 0..15 -> row group

    float acc[8][8];
    #pragma unroll
    for (int i = 0; i < 8; i++)
        #pragma unroll
        for (int j = 0; j < 8; j++) acc[i][j] = 0.f;

    for (int k0 = 0; k0 < K; k0 += 16) {
        // load A tile 128x16 (transposed into As[k][m])
        #pragma unroll
        for (int it = 0; it < 2; it++) {
            int idx = tid + it * 256;          // 0..511
            int row = idx >> 2;                // 0..127
            int c4  = (idx & 3) * 4;           // 0,4,8,12
            float4 va = *(const float4*)(A + (long)row * lda + k0 + c4);
            As[c4 + 0][row] = va.x;
            As[c4 + 1][row] = va.y;
            As[c4 + 2][row] = va.z;
            As[c4 + 3][row] = va.w;
        }
        // load B tile 16x128
        if (TRANSB) {
            #pragma unroll
            for (int it = 0; it < 2; it++) {
                int idx = tid + it * 256;
                int nl = idx >> 2;             // 0..127
                int c4 = (idx & 3) * 4;
                float4 vb = *(const float4*)(B + (long)nl * ldb + k0 + c4);
                Bs[c4 + 0][nl] = vb.x;
                Bs[c4 + 1][nl] = vb.y;
                Bs[c4 + 2][nl] = vb.z;
                Bs[c4 + 3][nl] = vb.w;
            }
        } else {
            #pragma unroll
            for (int it = 0; it < 2; it++) {
                int idx = tid + it * 256;
                int row = idx >> 5;            // 0..15
                int c4  = (idx & 31) * 4;      // 0..124
                float4 vb = *(const float4*)(B + (long)(k0 + row) * ldb + c4);
                *(float4*)&Bs[row][c4] = vb;
            }
        }
        __syncthreads();

        #pragma unroll
        for (int k = 0; k < 16; k++) {
            float a[8], b[8];
            #pragma unroll
            for (int i = 0; i < 8; i++) a[i] = As[k][ty * 8 + i];
            #pragma unroll
            for (int j = 0; j < 8; j++) b[j] = Bs[k][tx * 8 + j];
            #pragma unroll
            for (int i = 0; i < 8; i++)
                #pragma unroll
                for (int j = 0; j < 8; j++)
                    acc[i][j] = fmaf(a[i], b[j], acc[i][j]);
        }
        __syncthreads();
    }

    // epilogue
    #pragma unroll
    for (int i = 0; i < 8; i++) {
        long roff = (long)(ty * 8 + i) * ldc + tx * 8;
        if (R) {
            #pragma unroll
            for (int j = 0; j < 8; j++)
                C[roff + j] = acc[i][j] * alpha + R[roff + j];
        } else {
            #pragma unroll
            for (int j = 0; j < 8; j++)
                C[roff + j] = acc[i][j] * alpha;
        }
    }
}

// ---------------- softmax over both branches + combine: P = softmax(S1) - lam*softmax(S2) ----------------
__global__ __launch_bounds__(256) void softmax_combine_kernel(float* __restrict__ s1,
                                                              const float* __restrict__ s2,
                                                              const float* __restrict__ lam) {
    const long off = (long)blockIdx.y * SEQ * SEQ + (long)blockIdx.x * SEQ;
    float* r1 = s1 + off;
    const float* r2 = s2 + off;
    const int t = threadIdx.x;

    float v1[8], v2[8];
    #pragma unroll
    for (int i = 0; i < 8; i++) v1[i] = r1[t + 256 * i];
    float m1 = -1e30f;
    #pragma unroll
    for (int i = 0; i < 8; i++) m1 = fmaxf(m1, v1[i]);
    m1 = blockReduceMax256(m1);
    float ps = 0.f;
    #pragma unroll
    for (int i = 0; i < 8; i++) { v1[i] = expf(v1[i] - m1); ps += v1[i]; }
    float sum1 = blockReduceSum256(ps);

    #pragma unroll
    for (int i = 0; i < 8; i++) v2[i] = r2[t + 256 * i];
    float m2 = -1e30f;
    #pragma unroll
    for (int i = 0; i < 8; i++) m2 = fmaxf(m2, v2[i]);
    m2 = blockReduceMax256(m2);
    ps = 0.f;
    #pragma unroll
    for (int i = 0; i < 8; i++) { v2[i] = expf(v2[i] - m2); ps += v2[i]; }
    float sum2 = blockReduceSum256(ps);

    const float l  = lam[blockIdx.y];
    const float i1 = 1.f / sum1;
    const float i2 = l / sum2;
    #pragma unroll
    for (int i = 0; i < 8; i++)
        r1[t + 256 * i] = v1[i] * i1 - v2[i] * i2;
}

// ---------------- SwiGLU elementwise ----------------
__global__ __launch_bounds__(256) void swiglu_kernel(const float* __restrict__ g1,
                                                     const float* __restrict__ g2,
                                                     float* __restrict__ u) {
    long i = (long)blockIdx.x * 256 + threadIdx.x;
    float a = g1[i];
    u[i] = a / (1.f + expf(-a)) * g2[i];
}

// ---------------- launcher ----------------
extern "C" void kernel_launch(void* const* d_in, const int* in_sizes, int n_in,
                              void* d_out, int out_size) {
    (void)in_sizes; (void)n_in; (void)out_size;
    const float* x   = (const float*)d_in[0];
    const float* gn  = (const float*)d_in[1];
    const float* Wq1 = (const float*)d_in[2];
    const float* Wq2 = (const float*)d_in[3];
    const float* Wk1 = (const float*)d_in[4];
    const float* Wk2 = (const float*)d_in[5];
    const float* Wv  = (const float*)d_in[6];
    const float* lq1 = (const float*)d_in[7];
    const float* lk1 = (const float*)d_in[8];
    const float* lq2 = (const float*)d_in[9];
    const float* lk2 = (const float*)d_in[10];
    const float* Wo  = (const float*)d_in[11];
    const float* W1  = (const float*)d_in[12];
    const float* W2  = (const float*)d_in[13];
    const float* W3  = (const float*)d_in[14];
    float* out = (float*)d_out;

    float *h0, *q1, *q2, *k1, *k2, *v, *s1, *s2, *o, *h, *z, *G1, *G2, *U, *lam;
    cudaGetSymbolAddress((void**)&h0, g_h0);
    cudaGetSymbolAddress((void**)&q1, g_q1);
    cudaGetSymbolAddress((void**)&q2, g_q2);
    cudaGetSymbolAddress((void**)&k1, g_k1);
    cudaGetSymbolAddress((void**)&k2, g_k2);
    cudaGetSymbolAddress((void**)&v,  g_v);
    cudaGetSymbolAddress((void**)&s1, g_s1);
    cudaGetSymbolAddress((void**)&s2, g_s2);
    cudaGetSymbolAddress((void**)&o,  g_o);
    cudaGetSymbolAddress((void**)&h,  g_h);
    cudaGetSymbolAddress((void**)&z,  g_z);
    cudaGetSymbolAddress((void**)&G1, g_G1);
    cudaGetSymbolAddress((void**)&G2, g_G2);
    cudaGetSymbolAddress((void**)&U,  g_U);
    cudaGetSymbolAddress((void**)&lam, g_lam);

    const long HS  = (long)DIM * HDIM;       // 262144 head stride in W[h,d,e]
    const long SS  = (long)SEQ * SEQ;
    const float qkscale = 0.08838834764831845f;   // 1/sqrt(128)

    // 1) h0 = rmsnorm(x)
    rmsnorm_kernel<<<SEQ, 256>>>(x, gn, h0);

    // 2) projections: [S,D] @ [H,D,DH] -> [S, H*DH]
    dim3 gproj(DIM / 128, SEQ / 128, 1);
    gemm_kernel<false><<<gproj, 256>>>(h0, DIM, 0, Wq1, HDIM, 0, HS, q1, DIM, 0, DIM, 1.f, nullptr, 0);
    gemm_kernel<false><<<gproj, 256>>>(h0, DIM, 0, Wq2, HDIM, 0, HS, q2, DIM, 0, DIM, 1.f, nullptr, 0);
    gemm_kernel<false><<<gproj, 256>>>(h0, DIM, 0, Wk1, HDIM, 0, HS, k1, DIM, 0, DIM, 1.f, nullptr, 0);
    gemm_kernel<false><<<gproj, 256>>>(h0, DIM, 0, Wk2, HDIM, 0, HS, k2, DIM, 0, DIM, 1.f, nullptr, 0);
    gemm_kernel<false><<<gproj, 256>>>(h0, DIM, 0, Wv,  HDIM, 0, HS, v,  DIM, 0, DIM, 1.f, nullptr, 0);

    // 3) per-head lambda
    lambda_kernel<<<NH, 128>>>(lq1, lk1, lq2, lk2, lam);

    // 4) scores: S1 = q1 k1^T * scale, S2 = q2 k2^T * scale   (batched over heads)
    dim3 gqk(SEQ / 128, SEQ / 128, NH);
    gemm_kernel<true><<<gqk, 256>>>(q1, DIM, HDIM, k1, DIM, HDIM, 0, s1, SEQ, SS, HDIM, qkscale, nullptr, 0);
    gemm_kernel<true><<<gqk, 256>>>(q2, DIM, HDIM, k2, DIM, HDIM, 0, s2, SEQ, SS, HDIM, qkscale, nullptr, 0);

    // 5) P = softmax(S1) - lam*softmax(S2)   (into s1)
    dim3 gsm(SEQ, NH);
    softmax_combine_kernel<<<gsm, 256>>>(s1, s2, lam);

    // 6) O = P @ V per head -> [S, H*DH]
    dim3 gpv(1, SEQ / 128, NH);
    gemm_kernel<false><<<gpv, 256>>>(s1, SEQ, SS, v, DIM, HDIM, 128, o, DIM, HDIM, SEQ, 1.f, nullptr, 0);

    // 7) h = O @ Wo + h0
    dim3 gwo(DIM / 128, SEQ / 128, 1);
    gemm_kernel<false><<<gwo, 256>>>(o, DIM, 0, Wo, DIM, 0, 128, h, DIM, 0, DIM, 1.f, h0, 0);

    // 8) z = rmsnorm(h)
    rmsnorm_kernel<<<SEQ, 256>>>(h, gn, z);

    // 9) G1 = z@W1, G2 = z@W2
    dim3 gffn(HIDN / 128, SEQ / 128, 1);
    gemm_kernel<false><<<gffn, 256>>>(z, DIM, 0, W1, HIDN, 0, 128, G1, HIDN, 0, DIM, 1.f, nullptr, 0);
    gemm_kernel<false><<<gffn, 256>>>(z, DIM, 0, W2, HIDN, 0, 128, G2, HIDN, 0, DIM, 1.f, nullptr, 0);

    // 10) U = silu(G1) * G2
    swiglu_kernel<<<(SEQ * (long)HIDN) / 256, 256>>>(G1, G2, U);

    // 11) out = U @ W3 + h
    dim3 gw3(DIM / 128, SEQ / 128, 1);
    gemm_kernel<false><<<gw3, 256>>>(U, HIDN, 0, W3, DIM, 0, 128, out, DIM, 0, HIDN, 1.f, h, 0);
}

// round 5
// speedup vs baseline: 2.2128x; 2.2103x over previous
#include <cuda_runtime.h>
#include <cuda_bf16.h>
#include <math.h>
#include <stdint.h>

#define SEQ 2048
#define DIM 2048
#define NH 16
#define HDIM 128
#define HIDN 8192
#define EPSV 1e-6f
#define LAMB0 0.8f

typedef __nv_bfloat16 bf16;

// ---------------- scratch (device globals) ----------------
__device__ float g_h0f[SEQ * DIM];
__device__ float g_vf [SEQ * DIM];
__device__ float g_hf [SEQ * DIM];
__device__ float g_zf [SEQ * DIM];
__device__ float g_s1 [(size_t)NH * SEQ * SEQ];
__device__ float g_s2 [(size_t)NH * SEQ * SEQ];
__device__ float g_G1 [(size_t)SEQ * HIDN];
__device__ float g_G2 [(size_t)SEQ * HIDN];
__device__ float g_lam[NH];

__device__ bf16 g_h0h[SEQ*DIM], g_h0l[SEQ*DIM];
__device__ bf16 g_zh [SEQ*DIM], g_zl [SEQ*DIM];
__device__ bf16 g_q1h[SEQ*DIM], g_q1l[SEQ*DIM];
__device__ bf16 g_q2h[SEQ*DIM], g_q2l[SEQ*DIM];
__device__ bf16 g_k1h[SEQ*DIM], g_k1l[SEQ*DIM];
__device__ bf16 g_k2h[SEQ*DIM], g_k2l[SEQ*DIM];
__device__ bf16 g_vth[SEQ*DIM], g_vtl[SEQ*DIM];
__device__ bf16 g_oh [SEQ*DIM], g_ol [SEQ*DIM];
__device__ bf16 g_ph [(size_t)NH*SEQ*SEQ], g_pl [(size_t)NH*SEQ*SEQ];
__device__ bf16 g_uh [(size_t)SEQ*HIDN],  g_ul [(size_t)SEQ*HIDN];
__device__ bf16 g_wq1h[DIM*DIM], g_wq1l[DIM*DIM];
__device__ bf16 g_wq2h[DIM*DIM], g_wq2l[DIM*DIM];
__device__ bf16 g_wk1h[DIM*DIM], g_wk1l[DIM*DIM];
__device__ bf16 g_wk2h[DIM*DIM], g_wk2l[DIM*DIM];
__device__ bf16 g_wvh [DIM*DIM], g_wvl [DIM*DIM];
__device__ bf16 g_woh [DIM*DIM], g_wol [DIM*DIM];
__device__ bf16 g_w1h[(size_t)DIM*HIDN], g_w1l[(size_t)DIM*HIDN];
__device__ bf16 g_w2h[(size_t)DIM*HIDN], g_w2l[(size_t)DIM*HIDN];
__device__ bf16 g_w3h[(size_t)DIM*HIDN], g_w3l[(size_t)DIM*HIDN];

// ---------------- helpers ----------------
__device__ __forceinline__ uint32_t smem_u32(const void* p) {
    uint32_t a;
    asm("{ .reg .u64 t; cvta.to.shared.u64 t, %1; cvt.u32.u64 %0, t; }" : "=r"(a) : "l"(p));
    return a;
}
__device__ __forceinline__ void cpa16(uint32_t s, const void* g) {
    asm volatile("cp.async.cg.shared.global [%0], [%1], 16;" :: "r"(s), "l"(g));
}
#define CP_COMMIT() asm volatile("cp.async.commit_group;")
#define CP_WAIT(n)  asm volatile("cp.async.wait_group %0;" :: "n"(n))

__device__ __forceinline__ void ldm4(uint32_t* r, uint32_t addr) {
    asm volatile("ldmatrix.sync.aligned.m8n8.x4.shared.b16 {%0,%1,%2,%3}, [%4];"
        : "=r"(r[0]), "=r"(r[1]), "=r"(r[2]), "=r"(r[3]) : "r"(addr));
}
__device__ __forceinline__ void mma16816(float* d, const uint32_t* a, uint32_t b0, uint32_t b1) {
    asm volatile("mma.sync.aligned.m16n8k16.row.col.f32.bf16.bf16.f32 "
        "{%0,%1,%2,%3}, {%4,%5,%6,%7}, {%8,%9}, {%0,%1,%2,%3};"
        : "+f"(d[0]), "+f"(d[1]), "+f"(d[2]), "+f"(d[3])
        : "r"(a[0]), "r"(a[1]), "r"(a[2]), "r"(a[3]), "r"(b0), "r"(b1));
}
__device__ __forceinline__ void split2(float v, bf16* ph, bf16* pl) {
    bf16 h = __float2bfloat16(v);
    *ph = h;
    *pl = __float2bfloat16(v - __bfloat162float(h));
}

// ---------------- split-bf16 mma.sync GEMM: C = alpha*A.B^T (+R) ----------------
// A: [M,K] bf16 pairs (row stride lda, batch offset sA). B: [N,K] pairs (ldb, sB).
// MODE 0: fp32 out (+residual if Rf). MODE 1: bf16 pair out.
template <int MODE>
__global__ __launch_bounds__(256) void mma_gemm(
    const bf16* __restrict__ Ah, const bf16* __restrict__ Al, int lda, long sA,
    const bf16* __restrict__ Bh, const bf16* __restrict__ Bl, int ldb, long sB,
    float* __restrict__ Cf, const float* __restrict__ Rf,
    bf16* __restrict__ Ch, bf16* __restrict__ Cl,
    int ldc, long sC, int K, float alpha)
{
    constexpr int RSB  = 80;          // smem row stride bytes: 32 bf16 + 8 pad
    constexpr int MATB = 128 * RSB;   // 10240 per matrix
    constexpr int STG  = 4 * MATB;    // 40960 per stage (Ah,Al,Bh,Bl)
    extern __shared__ __align__(128) char dsm[];
    const uint32_t sb = smem_u32(dsm);

    const int tid = threadIdx.x;
    const int m0 = blockIdx.y * 128, n0 = blockIdx.x * 128, z = blockIdx.z;

    Ah += (long)z * sA + (long)m0 * lda;
    Al += (long)z * sA + (long)m0 * lda;
    Bh += (long)z * sB + (long)n0 * ldb;
    Bl += (long)z * sB + (long)n0 * ldb;

    const int NC = K >> 5;   // KC = 32

    auto load_chunk = [&](int c, int s) {
        const long k0 = (long)c << 5;
        const uint32_t st = sb + (uint32_t)s * STG;
        #pragma unroll
        for (int i = 0; i < 2; i++) {
            int idx = tid + 256 * i;        // 0..511
            int row = idx >> 2;             // 0..127
            int sg  = idx & 3;              // 16B segment
            uint32_t so = st + (uint32_t)row * RSB + (uint32_t)sg * 16;
            long ga = (long)row * lda + k0 + sg * 8;
            long gb = (long)row * ldb + k0 + sg * 8;
            cpa16(so,            Ah + ga);
            cpa16(so + MATB,     Al + ga);
            cpa16(so + 2*MATB,   Bh + gb);
            cpa16(so + 3*MATB,   Bl + gb);
        }
    };

    // per-thread ldmatrix lane offsets
    const int l  = tid & 31;
    const int wp = tid >> 5;
    const int wm = (wp >> 2) * 64;     // warp M origin (0 / 64)
    const int wn = (wp & 3) * 32;      // warp N origin
    const uint32_t aoff = (uint32_t)(wm + (l & 15)) * RSB + (uint32_t)((l >> 4) * 16);
    const uint32_t boff = 2u*MATB + (uint32_t)(wn + (l & 7) + ((l >> 4) << 3)) * RSB
                        + (uint32_t)(((l >> 3) & 1) * 16);

    float acc[4][4][4];
    #pragma unroll
    for (int a = 0; a < 4; a++)
        #pragma unroll
        for (int b = 0; b < 4; b++)
            #pragma unroll
            for (int c = 0; c < 4; c++) acc[a][b][c] = 0.f;

    load_chunk(0, 0); CP_COMMIT();
    load_chunk(1, 1); CP_COMMIT();
    load_chunk(2, 2); CP_COMMIT();

    for (int c = 0; c < NC; c++) {
        const int s = c % 3;
        const int rem = NC - 1 - c;
        if (rem >= 2)      { CP_WAIT(2); }
        else if (rem == 1) { CP_WAIT(1); }
        else               { CP_WAIT(0); }
        __syncthreads();

        const uint32_t stg = sb + (uint32_t)s * STG;
        #pragma unroll
        for (int ks = 0; ks < 2; ks++) {
            const uint32_t base = stg + (uint32_t)ks * 32;
            uint32_t ah[4][4], al[4][4], bh[2][4], bl[2][4];
            #pragma unroll
            for (int mi = 0; mi < 4; mi++) {
                ldm4(ah[mi], base + aoff + (uint32_t)mi * (16 * RSB));
                ldm4(al[mi], base + aoff + (uint32_t)mi * (16 * RSB) + MATB);
            }
            #pragma unroll
            for (int ng = 0; ng < 2; ng++) {
                ldm4(bh[ng], base + boff + (uint32_t)ng * (16 * RSB));
                ldm4(bl[ng], base + boff + (uint32_t)ng * (16 * RSB) + MATB);
            }
            #pragma unroll
            for (int mi = 0; mi < 4; mi++)
                #pragma unroll
                for (int ni = 0; ni < 4; ni++) {
                    uint32_t b0h = bh[ni >> 1][(ni & 1) * 2], b1h = bh[ni >> 1][(ni & 1) * 2 + 1];
                    uint32_t b0l = bl[ni >> 1][(ni & 1) * 2], b1l = bl[ni >> 1][(ni & 1) * 2 + 1];
                    mma16816(acc[mi][ni], ah[mi], b0h, b1h);
                    mma16816(acc[mi][ni], al[mi], b0h, b1h);
                    mma16816(acc[mi][ni], ah[mi], b0l, b1l);
                }
        }
        __syncthreads();
        if (c + 3 < NC) { load_chunk(c + 3, s); CP_COMMIT(); }
    }

    // epilogue (register fragments -> global)
    const int qr = l >> 2;
    const int qc = (l & 3) * 2;
    const long cbase = (long)z * sC + (long)m0 * ldc + n0;
    #pragma unroll
    for (int mi = 0; mi < 4; mi++)
        #pragma unroll
        for (int ni = 0; ni < 4; ni++)
            #pragma unroll
            for (int hr = 0; hr < 2; hr++) {
                long off = cbase + (long)(wm + mi * 16 + qr + hr * 8) * ldc + (wn + ni * 8 + qc);
                float v0 = acc[mi][ni][hr * 2 + 0] * alpha;
                float v1 = acc[mi][ni][hr * 2 + 1] * alpha;
                if (MODE == 0) {
                    if (Rf) { v0 += Rf[off]; v1 += Rf[off + 1]; }
                    Cf[off] = v0; Cf[off + 1] = v1;
                } else {
                    split2(v0, Ch + off,     Cl + off);
                    split2(v1, Ch + off + 1, Cl + off + 1);
                }
            }
}

// ---------------- transpose + split: [Z,R,C] fp32 -> [Z,C,R] bf16 pairs ----------------
__global__ __launch_bounds__(256) void transpose_split(const float* __restrict__ in,
                                                       bf16* __restrict__ oh, bf16* __restrict__ ol,
                                                       int R, int C) {
    const long zb = (long)blockIdx.z * R * C;
    in += zb; oh += zb; ol += zb;
    const int c0 = blockIdx.x * 32, r0 = blockIdx.y * 32;
    __shared__ float t[32][33];
    const int tx = threadIdx.x & 31, ty = threadIdx.x >> 5;
    #pragma unroll
    for (int i = 0; i < 4; i++)
        t[ty + 8*i][tx] = in[(long)(r0 + ty + 8*i) * C + c0 + tx];
    __syncthreads();
    #pragma unroll
    for (int i = 0; i < 4; i++) {
        float v = t[tx][ty + 8*i];
        long o = (long)(c0 + ty + 8*i) * R + r0 + tx;
        split2(v, oh + o, ol + o);
    }
}

// ---------------- fused RMSNorm -> fp32 + pairs ----------------
__global__ __launch_bounds__(256) void rmsnorm_kernel(const float* __restrict__ x,
                                                      const float* __restrict__ g,
                                                      float* __restrict__ yf,
                                                      bf16* __restrict__ yh, bf16* __restrict__ yl) {
    __shared__ float sh[8];
    const long row = blockIdx.x;
    const float* xr = x + row * (long)DIM;
    float v[8], ss = 0.f;
    #pragma unroll
    for (int i = 0; i < 8; i++) { v[i] = xr[threadIdx.x + 256*i]; ss += v[i]*v[i]; }
    #pragma unroll
    for (int o = 16; o; o >>= 1) ss += __shfl_xor_sync(0xffffffffu, ss, o);
    if ((threadIdx.x & 31) == 0) sh[threadIdx.x >> 5] = ss;
    __syncthreads();
    float tot = 0.f;
    #pragma unroll
    for (int i = 0; i < 8; i++) tot += sh[i];
    const float sc = rsqrtf(tot * (1.0f / DIM) + EPSV);
    #pragma unroll
    for (int i = 0; i < 8; i++) {
        int c = threadIdx.x + 256*i;
        float y = v[i] * sc * g[c];
        long o = row * (long)DIM + c;
        yf[o] = y;
        split2(y, yh + o, yl + o);
    }
}

// ---------------- lambda ----------------
__global__ void lambda_kernel(const float* __restrict__ lq1, const float* __restrict__ lk1,
                              const float* __restrict__ lq2, const float* __restrict__ lk2,
                              float* __restrict__ lam) {
    __shared__ float s1[128], s2[128];
    int h = blockIdx.x, t = threadIdx.x;
    int i = h * HDIM + t;
    s1[t] = lq1[i] * lk1[i];
    s2[t] = lq2[i] * lk2[i];
    __syncthreads();
    for (int o = 64; o; o >>= 1) {
        if (t < o) { s1[t] += s1[t+o]; s2[t] += s2[t+o]; }
        __syncthreads();
    }
    if (t == 0) lam[h] = expf(s1[0]) - expf(s2[0]) + LAMB0;
}

// ---------------- dual softmax + combine -> P pairs ----------------
__global__ __launch_bounds__(256) void softmax_combine(const float* __restrict__ s1,
                                                       const float* __restrict__ s2,
                                                       const float* __restrict__ lam,
                                                       bf16* __restrict__ ph, bf16* __restrict__ pl) {
    __shared__ float sh[8];
    const long off = (long)blockIdx.y * SEQ * SEQ + (long)blockIdx.x * SEQ;
    const float* r1 = s1 + off;
    const float* r2 = s2 + off;
    const int t = threadIdx.x;
    float v1[8], v2[8];
    #pragma unroll
    for (int i = 0; i < 8; i++) { v1[i] = r1[t + 256*i]; v2[i] = r2[t + 256*i]; }

    float mm = -1e30f;
    #pragma unroll
    for (int i = 0; i < 8; i++) { mm = fmaxf(mm, v1[i]); mm = fmaxf(mm, v2[i]); }
    #pragma unroll
    for (int o = 16; o; o >>= 1) mm = fmaxf(mm, __shfl_xor_sync(0xffffffffu, mm, o));
    if ((t & 31) == 0) sh[t >> 5] = mm;
    __syncthreads();
    float M = sh[0];
    #pragma unroll
    for (int i = 1; i < 8; i++) M = fmaxf(M, sh[i]);
    __syncthreads();

    float p1 = 0.f, p2 = 0.f;
    #pragma unroll
    for (int i = 0; i < 8; i++) {
        v1[i] = __expf(v1[i] - M); p1 += v1[i];
        v2[i] = __expf(v2[i] - M); p2 += v2[i];
    }
    #pragma unroll
    for (int o = 16; o; o >>= 1) {
        p1 += __shfl_xor_sync(0xffffffffu, p1, o);
        p2 += __shfl_xor_sync(0xffffffffu, p2, o);
    }
    __shared__ float sx[8], sy[8];
    if ((t & 31) == 0) { sx[t >> 5] = p1; sy[t >> 5] = p2; }
    __syncthreads();
    float S1 = 0.f, S2 = 0.f;
    #pragma unroll
    for (int i = 0; i < 8; i++) { S1 += sx[i]; S2 += sy[i]; }

    const float i1 = 1.f / S1;
    const float i2 = lam[blockIdx.y] / S2;
    #pragma unroll
    for (int i = 0; i < 8; i++) {
        long o = off + t + 256*i;
        split2(v1[i] * i1 - v2[i] * i2, ph + o, pl + o);
    }
}

// ---------------- SwiGLU -> pairs ----------------
__global__ __launch_bounds__(256) void swiglu_kernel(const float* __restrict__ g1,
                                                     const float* __restrict__ g2,
                                                     bf16* __restrict__ uh, bf16* __restrict__ ul) {
    long i = (long)blockIdx.x * 256 + threadIdx.x;
    float a = g1[i];
    float u = a / (1.f + __expf(-a)) * g2[i];
    split2(u, uh + i, ul + i);
}

// ---------------- launcher ----------------
extern "C" void kernel_launch(void* const* d_in, const int* in_sizes, int n_in,
                              void* d_out, int out_size) {
    (void)in_sizes; (void)n_in; (void)out_size;
    const float* x   = (const float*)d_in[0];
    const float* gn  = (const float*)d_in[1];
    const float* Wq1 = (const float*)d_in[2];
    const float* Wq2 = (const float*)d_in[3];
    const float* Wk1 = (const float*)d_in[4];
    const float* Wk2 = (const float*)d_in[5];
    const float* Wv  = (const float*)d_in[6];
    const float* lq1 = (const float*)d_in[7];
    const float* lk1 = (const float*)d_in[8];
    const float* lq2 = (const float*)d_in[9];
    const float* lk2 = (const float*)d_in[10];
    const float* Wo  = (const float*)d_in[11];
    const float* W1  = (const float*)d_in[12];
    const float* W2  = (const float*)d_in[13];
    const float* W3  = (const float*)d_in[14];
    float* out = (float*)d_out;

    const int SMEM = 3 * 40960;   // 122880
    cudaFuncSetAttribute(mma_gemm<0>, cudaFuncAttributeMaxDynamicSharedMemorySize, SMEM);
    cudaFuncSetAttribute(mma_gemm<1>, cudaFuncAttributeMaxDynamicSharedMemorySize, SMEM);

#define SYM(v, s) cudaGetSymbolAddress((void**)&v, s)
    float *h0f, *vf, *hf, *zf, *s1, *s2, *G1, *G2, *lam;
    SYM(h0f, g_h0f); SYM(vf, g_vf); SYM(hf, g_hf); SYM(zf, g_zf);
    SYM(s1, g_s1); SYM(s2, g_s2); SYM(G1, g_G1); SYM(G2, g_G2); SYM(lam, g_lam);
    bf16 *h0h,*h0l,*zh,*zl,*q1h,*q1l,*q2h,*q2l,*k1h,*k1l,*k2h,*k2l,*vth,*vtl,*oh,*ol,*ph,*pl,*uh,*ul;
    SYM(h0h, g_h0h); SYM(h0l, g_h0l); SYM(zh, g_zh); SYM(zl, g_zl);
    SYM(q1h, g_q1h); SYM(q1l, g_q1l); SYM(q2h, g_q2h); SYM(q2l, g_q2l);
    SYM(k1h, g_k1h); SYM(k1l, g_k1l); SYM(k2h, g_k2h); SYM(k2l, g_k2l);
    SYM(vth, g_vth); SYM(vtl, g_vtl); SYM(oh, g_oh); SYM(ol, g_ol);
    SYM(ph, g_ph); SYM(pl, g_pl); SYM(uh, g_uh); SYM(ul, g_ul);
    bf16 *wq1h,*wq1l,*wq2h,*wq2l,*wk1h,*wk1l,*wk2h,*wk2l,*wvh,*wvl,*woh,*wol,*w1h,*w1l,*w2h,*w2l,*w3h,*w3l;
    SYM(wq1h, g_wq1h); SYM(wq1l, g_wq1l); SYM(wq2h, g_wq2h); SYM(wq2l, g_wq2l);
    SYM(wk1h, g_wk1h); SYM(wk1l, g_wk1l); SYM(wk2h, g_wk2h); SYM(wk2l, g_wk2l);
    SYM(wvh, g_wvh); SYM(wvl, g_wvl); SYM(woh, g_woh); SYM(wol, g_wol);
    SYM(w1h, g_w1h); SYM(w1l, g_w1l); SYM(w2h, g_w2h); SYM(w2l, g_w2l);
    SYM(w3h, g_w3h); SYM(w3l, g_w3l);
#undef SYM

    const long SS = (long)SEQ * SEQ;
    const float qkscale = 0.08838834764831845f; // 1/sqrt(128)

    // weight transposes -> [N,K] K-major bf16 pairs
    dim3 gtA(HDIM/32, DIM/32, NH);          // [H,D,DH] -> per-head [DH,D]
    transpose_split<<<gtA, 256>>>(Wq1, wq1h, wq1l, DIM, HDIM);
    transpose_split<<<gtA, 256>>>(Wq2, wq2h, wq2l, DIM, HDIM);
    transpose_split<<<gtA, 256>>>(Wk1, wk1h, wk1l, DIM, HDIM);
    transpose_split<<<gtA, 256>>>(Wk2, wk2h, wk2l, DIM, HDIM);
    transpose_split<<<gtA, 256>>>(Wv,  wvh,  wvl,  DIM, HDIM);
    dim3 gtO(DIM/32, DIM/32, 1);
    transpose_split<<<gtO, 256>>>(Wo, woh, wol, DIM, DIM);
    dim3 gt1(HIDN/32, DIM/32, 1);
    transpose_split<<<gt1, 256>>>(W1, w1h, w1l, DIM, HIDN);
    transpose_split<<<gt1, 256>>>(W2, w2h, w2l, DIM, HIDN);
    dim3 gt3(DIM/32, HIDN/32, 1);
    transpose_split<<<gt3, 256>>>(W3, w3h, w3l, HIDN, DIM);

    // 1) h0 = rmsnorm(x)
    rmsnorm_kernel<<<SEQ, 256>>>(x, gn, h0f, h0h, h0l);
    lambda_kernel<<<NH, 128>>>(lq1, lk1, lq2, lk2, lam);

    // 2) projections (pairs out for q/k, fp32 for v)
    dim3 gproj(DIM/128, SEQ/128, 1);
    mma_gemm<1><<<gproj, 256, SMEM>>>(h0h, h0l, DIM, 0, wq1h, wq1l, DIM, 0, nullptr, nullptr, q1h, q1l, DIM, 0, DIM, 1.f);
    mma_gemm<1><<<gproj, 256, SMEM>>>(h0h, h0l, DIM, 0, wq2h, wq2l, DIM, 0, nullptr, nullptr, q2h, q2l, DIM, 0, DIM, 1.f);
    mma_gemm<1><<<gproj, 256, SMEM>>>(h0h, h0l, DIM, 0, wk1h, wk1l, DIM, 0, nullptr, nullptr, k1h, k1l, DIM, 0, DIM, 1.f);
    mma_gemm<1><<<gproj, 256, SMEM>>>(h0h, h0l, DIM, 0, wk2h, wk2l, DIM, 0, nullptr, nullptr, k2h, k2l, DIM, 0, DIM, 1.f);
    mma_gemm<0><<<gproj, 256, SMEM>>>(h0h, h0l, DIM, 0, wvh,  wvl,  DIM, 0, vf, nullptr, nullptr, nullptr, DIM, 0, DIM, 1.f);

    // 3) V^T pairs
    dim3 gtV(DIM/32, SEQ/32, 1);
    transpose_split<<<gtV, 256>>>(vf, vth, vtl, SEQ, DIM);

    // 4) scores
    dim3 gqk(SEQ/128, SEQ/128, NH);
    mma_gemm<0><<<gqk, 256, SMEM>>>(q1h, q1l, DIM, HDIM, k1h, k1l, DIM, HDIM, s1, nullptr, nullptr, nullptr, SEQ, SS, HDIM, qkscale);
    mma_gemm<0><<<gqk, 256, SMEM>>>(q2h, q2l, DIM, HDIM, k2h, k2l, DIM, HDIM, s2, nullptr, nullptr, nullptr, SEQ, SS, HDIM, qkscale);

    // 5) P = softmax(S1) - lam*softmax(S2) -> pairs
    dim3 gsm(SEQ, NH);
    softmax_combine<<<gsm, 256>>>(s1, s2, lam, ph, pl);

    // 6) O = P @ V (pairs out)
    dim3 gpv(1, SEQ/128, NH);
    mma_gemm<1><<<gpv, 256, SMEM>>>(ph, pl, SEQ, SS, vth, vtl, SEQ, (long)HDIM*SEQ, nullptr, nullptr, oh, ol, DIM, HDIM, SEQ, 1.f);

    // 7) h = O @ Wo + h0
    dim3 gwo(DIM/128, SEQ/128, 1);
    mma_gemm<0><<<gwo, 256, SMEM>>>(oh, ol, DIM, 0, woh, wol, DIM, 0, hf, h0f, nullptr, nullptr, DIM, 0, DIM, 1.f);

    // 8) z = rmsnorm(h)
    rmsnorm_kernel<<<SEQ, 256>>>(hf, gn, zf, zh, zl);

    // 9) G1, G2
    dim3 gffn(HIDN/128, SEQ/128, 1);
    mma_gemm<0><<<gffn, 256, SMEM>>>(zh, zl, DIM, 0, w1h, w1l, DIM, 0, G1, nullptr, nullptr, nullptr, HIDN, 0, DIM, 1.f);
    mma_gemm<0><<<gffn, 256, SMEM>>>(zh, zl, DIM, 0, w2h, w2l, DIM, 0, G2, nullptr, nullptr, nullptr, HIDN, 0, DIM, 1.f);

    // 10) U = silu(G1)*G2 -> pairs
    swiglu_kernel<<<(SEQ * (long)HIDN) / 256, 256>>>(G1, G2, uh, ul);

    // 11) out = U @ W3 + h
    dim3 gw3(DIM/128, SEQ/128, 1);
    mma_gemm<0><<<gw3, 256, SMEM>>>(uh, ul, HIDN, 0, w3h, w3l, HIDN, 0, out, hf, nullptr, nullptr, DIM, 0, HIDN, 1.f);
}

// round 6
// speedup vs baseline: 2.2286x; 1.0072x over previous
#include <cuda_runtime.h>
#include <cuda_bf16.h>
#include <math.h>
#include <stdint.h>

#define SEQ 2048
#define DIM 2048
#define NH 16
#define HDIM 128
#define HIDN 8192
#define EPSV 1e-6f
#define LAMB0 0.8f

typedef __nv_bfloat16 bf16;

// ---------------- scratch (device globals) ----------------
__device__ float g_h0f[SEQ * DIM];
__device__ float g_vf [SEQ * DIM];
__device__ float g_hf [SEQ * DIM];
__device__ float g_zf [SEQ * DIM];
__device__ float g_s1 [(size_t)NH * SEQ * SEQ];
__device__ float g_s2 [(size_t)NH * SEQ * SEQ];
__device__ float g_G1 [(size_t)SEQ * HIDN];
__device__ float g_G2 [(size_t)SEQ * HIDN];
__device__ float g_lam[NH];

__device__ bf16 g_h0h[SEQ*DIM], g_h0l[SEQ*DIM];
__device__ bf16 g_zh [SEQ*DIM], g_zl [SEQ*DIM];
__device__ bf16 g_q1h[SEQ*DIM], g_q1l[SEQ*DIM];
__device__ bf16 g_q2h[SEQ*DIM], g_q2l[SEQ*DIM];
__device__ bf16 g_k1h[SEQ*DIM], g_k1l[SEQ*DIM];
__device__ bf16 g_k2h[SEQ*DIM], g_k2l[SEQ*DIM];
__device__ bf16 g_vth[SEQ*DIM], g_vtl[SEQ*DIM];
__device__ bf16 g_oh [SEQ*DIM], g_ol [SEQ*DIM];
__device__ bf16 g_ph [(size_t)NH*SEQ*SEQ], g_pl [(size_t)NH*SEQ*SEQ];
__device__ bf16 g_uh [(size_t)SEQ*HIDN],  g_ul [(size_t)SEQ*HIDN];
__device__ bf16 g_wq1h[DIM*DIM], g_wq1l[DIM*DIM];
__device__ bf16 g_wq2h[DIM*DIM], g_wq2l[DIM*DIM];
__device__ bf16 g_wk1h[DIM*DIM], g_wk1l[DIM*DIM];
__device__ bf16 g_wk2h[DIM*DIM], g_wk2l[DIM*DIM];
__device__ bf16 g_wvh [DIM*DIM], g_wvl [DIM*DIM];
__device__ bf16 g_woh [DIM*DIM], g_wol [DIM*DIM];
__device__ bf16 g_w1h[(size_t)DIM*HIDN], g_w1l[(size_t)DIM*HIDN];
__device__ bf16 g_w2h[(size_t)DIM*HIDN], g_w2l[(size_t)DIM*HIDN];
__device__ bf16 g_w3h[(size_t)DIM*HIDN], g_w3l[(size_t)DIM*HIDN];

// ---------------- helpers ----------------
__device__ __forceinline__ uint32_t smem_u32(const void* p) {
    uint32_t a;
    asm("{ .reg .u64 t; cvta.to.shared.u64 t, %1; cvt.u32.u64 %0, t; }" : "=r"(a) : "l"(p));
    return a;
}
__device__ __forceinline__ void cpa16(uint32_t s, const void* g) {
    asm volatile("cp.async.cg.shared.global [%0], [%1], 16;" :: "r"(s), "l"(g));
}
#define CP_COMMIT() asm volatile("cp.async.commit_group;")
#define CP_WAIT(n)  asm volatile("cp.async.wait_group %0;" :: "n"(n))

__device__ __forceinline__ void ldm4(uint32_t* r, uint32_t addr) {
    asm volatile("ldmatrix.sync.aligned.m8n8.x4.shared.b16 {%0,%1,%2,%3}, [%4];"
        : "=r"(r[0]), "=r"(r[1]), "=r"(r[2]), "=r"(r[3]) : "r"(addr));
}
__device__ __forceinline__ void mma16816(float* d, const uint32_t* a, uint32_t b0, uint32_t b1) {
    asm volatile("mma.sync.aligned.m16n8k16.row.col.f32.bf16.bf16.f32 "
        "{%0,%1,%2,%3}, {%4,%5,%6,%7}, {%8,%9}, {%0,%1,%2,%3};"
        : "+f"(d[0]), "+f"(d[1]), "+f"(d[2]), "+f"(d[3])
        : "r"(a[0]), "r"(a[1]), "r"(a[2]), "r"(a[3]), "r"(b0), "r"(b1));
}
__device__ __forceinline__ void split2(float v, bf16* ph, bf16* pl) {
    bf16 h = __float2bfloat16(v);
    *ph = h;
    *pl = __float2bfloat16(v - __bfloat162float(h));
}

// ---------------- split-bf16 mma.sync GEMM: C = alpha*A.B^T (+R) ----------------
// 4-stage cp.async ring, single syncthreads per chunk, loads overlap compute.
// MODE 0: fp32 out (+residual if Rf). MODE 1: bf16 pair out.
template <int MODE>
__global__ __launch_bounds__(256) void mma_gemm(
    const bf16* __restrict__ Ah, const bf16* __restrict__ Al, int lda, long sA,
    const bf16* __restrict__ Bh, const bf16* __restrict__ Bl, int ldb, long sB,
    float* __restrict__ Cf, const float* __restrict__ Rf,
    bf16* __restrict__ Ch, bf16* __restrict__ Cl,
    int ldc, long sC, int K, float alpha)
{
    constexpr int RSB  = 80;          // smem row stride bytes: 32 bf16 + 8 pad
    constexpr int MATB = 128 * RSB;   // 10240 per matrix
    constexpr int STG  = 4 * MATB;    // 40960 per stage (Ah,Al,Bh,Bl)
    extern __shared__ __align__(128) char dsm[];
    const uint32_t sb = smem_u32(dsm);

    const int tid = threadIdx.x;
    const int m0 = blockIdx.y * 128, n0 = blockIdx.x * 128, z = blockIdx.z;

    Ah += (long)z * sA + (long)m0 * lda;
    Al += (long)z * sA + (long)m0 * lda;
    Bh += (long)z * sB + (long)n0 * ldb;
    Bl += (long)z * sB + (long)n0 * ldb;

    const int NC = K >> 5;   // KC = 32

    auto load_chunk = [&](int c, int s) {
        const long k0 = (long)c << 5;
        const uint32_t st = sb + (uint32_t)s * STG;
        #pragma unroll
        for (int i = 0; i < 2; i++) {
            int idx = tid + 256 * i;        // 0..511
            int row = idx >> 2;             // 0..127
            int sg  = idx & 3;              // 16B segment
            uint32_t so = st + (uint32_t)row * RSB + (uint32_t)sg * 16;
            long ga = (long)row * lda + k0 + sg * 8;
            long gb = (long)row * ldb + k0 + sg * 8;
            cpa16(so,            Ah + ga);
            cpa16(so + MATB,     Al + ga);
            cpa16(so + 2*MATB,   Bh + gb);
            cpa16(so + 3*MATB,   Bl + gb);
        }
    };

    // per-thread ldmatrix lane offsets
    const int l  = tid & 31;
    const int wp = tid >> 5;
    const int wm = (wp >> 2) * 64;     // warp M origin (0 / 64)
    const int wn = (wp & 3) * 32;      // warp N origin
    const uint32_t aoff = (uint32_t)(wm + (l & 15)) * RSB + (uint32_t)((l >> 4) * 16);
    const uint32_t boff = 2u*MATB + (uint32_t)(wn + (l & 7) + ((l >> 4) << 3)) * RSB
                        + (uint32_t)(((l >> 3) & 1) * 16);

    float acc[4][4][4];
    #pragma unroll
    for (int a = 0; a < 4; a++)
        #pragma unroll
        for (int b = 0; b < 4; b++)
            #pragma unroll
            for (int c = 0; c < 4; c++) acc[a][b][c] = 0.f;

    load_chunk(0, 0); CP_COMMIT();
    load_chunk(1, 1); CP_COMMIT();
    load_chunk(2, 2); CP_COMMIT();

    for (int c = 0; c < NC; c++) {
        const int s = c & 3;
        const int rem = NC - 1 - c;
        if (rem >= 2)      { CP_WAIT(2); }
        else if (rem == 1) { CP_WAIT(1); }
        else               { CP_WAIT(0); }
        // one barrier: data for chunk c arrived AND stage (c+3)&3 (used by chunk
        // c-1) is no longer being read by any warp.
        __syncthreads();
        if (c + 3 < NC) { load_chunk(c + 3, (c + 3) & 3); CP_COMMIT(); }

        const uint32_t stg = sb + (uint32_t)s * STG;
        #pragma unroll
        for (int ks = 0; ks < 2; ks++) {
            const uint32_t base = stg + (uint32_t)ks * 32;
            uint32_t ah[4][4], al[4][4], bh[2][4], bl[2][4];
            #pragma unroll
            for (int mi = 0; mi < 4; mi++) {
                ldm4(ah[mi], base + aoff + (uint32_t)mi * (16 * RSB));
                ldm4(al[mi], base + aoff + (uint32_t)mi * (16 * RSB) + MATB);
            }
            #pragma unroll
            for (int ng = 0; ng < 2; ng++) {
                ldm4(bh[ng], base + boff + (uint32_t)ng * (16 * RSB));
                ldm4(bl[ng], base + boff + (uint32_t)ng * (16 * RSB) + MATB);
            }
            // 3 passes over 16 independent tiles: consecutive HMMAs never share
            // an accumulator -> no RAW stalls on the tensor pipe.
            #pragma unroll
            for (int mi = 0; mi < 4; mi++)
                #pragma unroll
                for (int ni = 0; ni < 4; ni++)
                    mma16816(acc[mi][ni], ah[mi],
                             bh[ni >> 1][(ni & 1) * 2], bh[ni >> 1][(ni & 1) * 2 + 1]);
            #pragma unroll
            for (int mi = 0; mi < 4; mi++)
                #pragma unroll
                for (int ni = 0; ni < 4; ni++)
                    mma16816(acc[mi][ni], al[mi],
                             bh[ni >> 1][(ni & 1) * 2], bh[ni >> 1][(ni & 1) * 2 + 1]);
            #pragma unroll
            for (int mi = 0; mi < 4; mi++)
                #pragma unroll
                for (int ni = 0; ni < 4; ni++)
                    mma16816(acc[mi][ni], ah[mi],
                             bl[ni >> 1][(ni & 1) * 2], bl[ni >> 1][(ni & 1) * 2 + 1]);
        }
    }

    // epilogue (register fragments -> global)
    const int qr = l >> 2;
    const int qc = (l & 3) * 2;
    const long cbase = (long)z * sC + (long)m0 * ldc + n0;
    #pragma unroll
    for (int mi = 0; mi < 4; mi++)
        #pragma unroll
        for (int ni = 0; ni < 4; ni++)
            #pragma unroll
            for (int hr = 0; hr < 2; hr++) {
                long off = cbase + (long)(wm + mi * 16 + qr + hr * 8) * ldc + (wn + ni * 8 + qc);
                float v0 = acc[mi][ni][hr * 2 + 0] * alpha;
                float v1 = acc[mi][ni][hr * 2 + 1] * alpha;
                if (MODE == 0) {
                    if (Rf) { v0 += Rf[off]; v1 += Rf[off + 1]; }
                    Cf[off] = v0; Cf[off + 1] = v1;
                } else {
                    split2(v0, Ch + off,     Cl + off);
                    split2(v1, Ch + off + 1, Cl + off + 1);
                }
            }
}

// ---------------- transpose + split: [Z,R,C] fp32 -> [Z,C,R] bf16 pairs ----------------
__global__ __launch_bounds__(256) void transpose_split(const float* __restrict__ in,
                                                       bf16* __restrict__ oh, bf16* __restrict__ ol,
                                                       int R, int C) {
    const long zb = (long)blockIdx.z * R * C;
    in += zb; oh += zb; ol += zb;
    const int c0 = blockIdx.x * 32, r0 = blockIdx.y * 32;
    __shared__ float t[32][33];
    const int tx = threadIdx.x & 31, ty = threadIdx.x >> 5;
    #pragma unroll
    for (int i = 0; i < 4; i++)
        t[ty + 8*i][tx] = in[(long)(r0 + ty + 8*i) * C + c0 + tx];
    __syncthreads();
    #pragma unroll
    for (int i = 0; i < 4; i++) {
        float v = t[tx][ty + 8*i];
        long o = (long)(c0 + ty + 8*i) * R + r0 + tx;
        split2(v, oh + o, ol + o);
    }
}

// ---------------- fused RMSNorm -> fp32 + pairs ----------------
__global__ __launch_bounds__(256) void rmsnorm_kernel(const float* __restrict__ x,
                                                      const float* __restrict__ g,
                                                      float* __restrict__ yf,
                                                      bf16* __restrict__ yh, bf16* __restrict__ yl) {
    __shared__ float sh[8];
    const long row = blockIdx.x;
    const float* xr = x + row * (long)DIM;
    float v[8], ss = 0.f;
    #pragma unroll
    for (int i = 0; i < 8; i++) { v[i] = xr[threadIdx.x + 256*i]; ss += v[i]*v[i]; }
    #pragma unroll
    for (int o = 16; o; o >>= 1) ss += __shfl_xor_sync(0xffffffffu, ss, o);
    if ((threadIdx.x & 31) == 0) sh[threadIdx.x >> 5] = ss;
    __syncthreads();
    float tot = 0.f;
    #pragma unroll
    for (int i = 0; i < 8; i++) tot += sh[i];
    const float sc = rsqrtf(tot * (1.0f / DIM) + EPSV);
    #pragma unroll
    for (int i = 0; i < 8; i++) {
        int c = threadIdx.x + 256*i;
        float y = v[i] * sc * g[c];
        long o = row * (long)DIM + c;
        yf[o] = y;
        split2(y, yh + o, yl + o);
    }
}

// ---------------- lambda ----------------
__global__ void lambda_kernel(const float* __restrict__ lq1, const float* __restrict__ lk1,
                              const float* __restrict__ lq2, const float* __restrict__ lk2,
                              float* __restrict__ lam) {
    __shared__ float s1[128], s2[128];
    int h = blockIdx.x, t = threadIdx.x;
    int i = h * HDIM + t;
    s1[t] = lq1[i] * lk1[i];
    s2[t] = lq2[i] * lk2[i];
    __syncthreads();
    for (int o = 64; o; o >>= 1) {
        if (t < o) { s1[t] += s1[t+o]; s2[t] += s2[t+o]; }
        __syncthreads();
    }
    if (t == 0) lam[h] = expf(s1[0]) - expf(s2[0]) + LAMB0;
}

// ---------------- dual softmax + combine -> P pairs ----------------
__global__ __launch_bounds__(256) void softmax_combine(const float* __restrict__ s1,
                                                       const float* __restrict__ s2,
                                                       const float* __restrict__ lam,
                                                       bf16* __restrict__ ph, bf16* __restrict__ pl) {
    __shared__ float sh[8];
    const long off = (long)blockIdx.y * SEQ * SEQ + (long)blockIdx.x * SEQ;
    const float* r1 = s1 + off;
    const float* r2 = s2 + off;
    const int t = threadIdx.x;
    float v1[8], v2[8];
    #pragma unroll
    for (int i = 0; i < 8; i++) { v1[i] = r1[t + 256*i]; v2[i] = r2[t + 256*i]; }

    float mm = -1e30f;
    #pragma unroll
    for (int i = 0; i < 8; i++) { mm = fmaxf(mm, v1[i]); mm = fmaxf(mm, v2[i]); }
    #pragma unroll
    for (int o = 16; o; o >>= 1) mm = fmaxf(mm, __shfl_xor_sync(0xffffffffu, mm, o));
    if ((t & 31) == 0) sh[t >> 5] = mm;
    __syncthreads();
    float M = sh[0];
    #pragma unroll
    for (int i = 1; i < 8; i++) M = fmaxf(M, sh[i]);
    __syncthreads();

    float p1 = 0.f, p2 = 0.f;
    #pragma unroll
    for (int i = 0; i < 8; i++) {
        v1[i] = __expf(v1[i] - M); p1 += v1[i];
        v2[i] = __expf(v2[i] - M); p2 += v2[i];
    }
    #pragma unroll
    for (int o = 16; o; o >>= 1) {
        p1 += __shfl_xor_sync(0xffffffffu, p1, o);
        p2 += __shfl_xor_sync(0xffffffffu, p2, o);
    }
    __shared__ float sx[8], sy[8];
    if ((t & 31) == 0) { sx[t >> 5] = p1; sy[t >> 5] = p2; }
    __syncthreads();
    float S1 = 0.f, S2 = 0.f;
    #pragma unroll
    for (int i = 0; i < 8; i++) { S1 += sx[i]; S2 += sy[i]; }

    const float i1 = 1.f / S1;
    const float i2 = lam[blockIdx.y] / S2;
    #pragma unroll
    for (int i = 0; i < 8; i++) {
        long o = off + t + 256*i;
        split2(v1[i] * i1 - v2[i] * i2, ph + o, pl + o);
    }
}

// ---------------- SwiGLU -> pairs ----------------
__global__ __launch_bounds__(256) void swiglu_kernel(const float* __restrict__ g1,
                                                     const float* __restrict__ g2,
                                                     bf16* __restrict__ uh, bf16* __restrict__ ul) {
    long i = (long)blockIdx.x * 256 + threadIdx.x;
    float a = g1[i];
    float u = a / (1.f + __expf(-a)) * g2[i];
    split2(u, uh + i, ul + i);
}

// ---------------- launcher ----------------
extern "C" void kernel_launch(void* const* d_in, const int* in_sizes, int n_in,
                              void* d_out, int out_size) {
    (void)in_sizes; (void)n_in; (void)out_size;
    const float* x   = (const float*)d_in[0];
    const float* gn  = (const float*)d_in[1];
    const float* Wq1 = (const float*)d_in[2];
    const float* Wq2 = (const float*)d_in[3];
    const float* Wk1 = (const float*)d_in[4];
    const float* Wk2 = (const float*)d_in[5];
    const float* Wv  = (const float*)d_in[6];
    const float* lq1 = (const float*)d_in[7];
    const float* lk1 = (const float*)d_in[8];
    const float* lq2 = (const float*)d_in[9];
    const float* lk2 = (const float*)d_in[10];
    const float* Wo  = (const float*)d_in[11];
    const float* W1  = (const float*)d_in[12];
    const float* W2  = (const float*)d_in[13];
    const float* W3  = (const float*)d_in[14];
    float* out = (float*)d_out;

    const int SMEM = 4 * 40960;   // 163840 (4 stages)
    cudaFuncSetAttribute(mma_gemm<0>, cudaFuncAttributeMaxDynamicSharedMemorySize, SMEM);
    cudaFuncSetAttribute(mma_gemm<1>, cudaFuncAttributeMaxDynamicSharedMemorySize, SMEM);

#define SYM(v, s) cudaGetSymbolAddress((void**)&v, s)
    float *h0f, *vf, *hf, *zf, *s1, *s2, *G1, *G2, *lam;
    SYM(h0f, g_h0f); SYM(vf, g_vf); SYM(hf, g_hf); SYM(zf, g_zf);
    SYM(s1, g_s1); SYM(s2, g_s2); SYM(G1, g_G1); SYM(G2, g_G2); SYM(lam, g_lam);
    bf16 *h0h,*h0l,*zh,*zl,*q1h,*q1l,*q2h,*q2l,*k1h,*k1l,*k2h,*k2l,*vth,*vtl,*oh,*ol,*ph,*pl,*uh,*ul;
    SYM(h0h, g_h0h); SYM(h0l, g_h0l); SYM(zh, g_zh); SYM(zl, g_zl);
    SYM(q1h, g_q1h); SYM(q1l, g_q1l); SYM(q2h, g_q2h); SYM(q2l, g_q2l);
    SYM(k1h, g_k1h); SYM(k1l, g_k1l); SYM(k2h, g_k2h); SYM(k2l, g_k2l);
    SYM(vth, g_vth); SYM(vtl, g_vtl); SYM(oh, g_oh); SYM(ol, g_ol);
    SYM(ph, g_ph); SYM(pl, g_pl); SYM(uh, g_uh); SYM(ul, g_ul);
    bf16 *wq1h,*wq1l,*wq2h,*wq2l,*wk1h,*wk1l,*wk2h,*wk2l,*wvh,*wvl,*woh,*wol,*w1h,*w1l,*w2h,*w2l,*w3h,*w3l;
    SYM(wq1h, g_wq1h); SYM(wq1l, g_wq1l); SYM(wq2h, g_wq2h); SYM(wq2l, g_wq2l);
    SYM(wk1h, g_wk1h); SYM(wk1l, g_wk1l); SYM(wk2h, g_wk2h); SYM(wk2l, g_wk2l);
    SYM(wvh, g_wvh); SYM(wvl, g_wvl); SYM(woh, g_woh); SYM(wol, g_wol);
    SYM(w1h, g_w1h); SYM(w1l, g_w1l); SYM(w2h, g_w2h); SYM(w2l, g_w2l);
    SYM(w3h, g_w3h); SYM(w3l, g_w3l);
#undef SYM

    const long SS = (long)SEQ * SEQ;
    const float qkscale = 0.08838834764831845f; // 1/sqrt(128)

    // weight transposes -> [N,K] K-major bf16 pairs
    dim3 gtA(HDIM/32, DIM/32, NH);          // [H,D,DH] -> per-head [DH,D]
    transpose_split<<<gtA, 256>>>(Wq1, wq1h, wq1l, DIM, HDIM);
    transpose_split<<<gtA, 256>>>(Wq2, wq2h, wq2l, DIM, HDIM);
    transpose_split<<<gtA, 256>>>(Wk1, wk1h, wk1l, DIM, HDIM);
    transpose_split<<<gtA, 256>>>(Wk2, wk2h, wk2l, DIM, HDIM);
    transpose_split<<<gtA, 256>>>(Wv,  wvh,  wvl,  DIM, HDIM);
    dim3 gtO(DIM/32, DIM/32, 1);
    transpose_split<<<gtO, 256>>>(Wo, woh, wol, DIM, DIM);
    dim3 gt1(HIDN/32, DIM/32, 1);
    transpose_split<<<gt1, 256>>>(W1, w1h, w1l, DIM, HIDN);
    transpose_split<<<gt1, 256>>>(W2, w2h, w2l, DIM, HIDN);
    dim3 gt3(DIM/32, HIDN/32, 1);
    transpose_split<<<gt3, 256>>>(W3, w3h, w3l, HIDN, DIM);

    // 1) h0 = rmsnorm(x)
    rmsnorm_kernel<<<SEQ, 256>>>(x, gn, h0f, h0h, h0l);
    lambda_kernel<<<NH, 128>>>(lq1, lk1, lq2, lk2, lam);

    // 2) projections (pairs out for q/k, fp32 for v)
    dim3 gproj(DIM/128, SEQ/128, 1);
    mma_gemm<1><<<gproj, 256, SMEM>>>(h0h, h0l, DIM, 0, wq1h, wq1l, DIM, 0, nullptr, nullptr, q1h, q1l, DIM, 0, DIM, 1.f);
    mma_gemm<1><<<gproj, 256, SMEM>>>(h0h, h0l, DIM, 0, wq2h, wq2l, DIM, 0, nullptr, nullptr, q2h, q2l, DIM, 0, DIM, 1.f);
    mma_gemm<1><<<gproj, 256, SMEM>>>(h0h, h0l, DIM, 0, wk1h, wk1l, DIM, 0, nullptr, nullptr, k1h, k1l, DIM, 0, DIM, 1.f);
    mma_gemm<1><<<gproj, 256, SMEM>>>(h0h, h0l, DIM, 0, wk2h, wk2l, DIM, 0, nullptr, nullptr, k2h, k2l, DIM, 0, DIM, 1.f);
    mma_gemm<0><<<gproj, 256, SMEM>>>(h0h, h0l, DIM, 0, wvh,  wvl,  DIM, 0, vf, nullptr, nullptr, nullptr, DIM, 0, DIM, 1.f);

    // 3) V^T pairs
    dim3 gtV(DIM/32, SEQ/32, 1);
    transpose_split<<<gtV, 256>>>(vf, vth, vtl, SEQ, DIM);

    // 4) scores
    dim3 gqk(SEQ/128, SEQ/128, NH);
    mma_gemm<0><<<gqk, 256, SMEM>>>(q1h, q1l, DIM, HDIM, k1h, k1l, DIM, HDIM, s1, nullptr, nullptr, nullptr, SEQ, SS, HDIM, qkscale);
    mma_gemm<0><<<gqk, 256, SMEM>>>(q2h, q2l, DIM, HDIM, k2h, k2l, DIM, HDIM, s2, nullptr, nullptr, nullptr, SEQ, SS, HDIM, qkscale);

    // 5) P = softmax(S1) - lam*softmax(S2) -> pairs
    dim3 gsm(SEQ, NH);
    softmax_combine<<<gsm, 256>>>(s1, s2, lam, ph, pl);

    // 6) O = P @ V (pairs out)
    dim3 gpv(1, SEQ/128, NH);
    mma_gemm<1><<<gpv, 256, SMEM>>>(ph, pl, SEQ, SS, vth, vtl, SEQ, (long)HDIM*SEQ, nullptr, nullptr, oh, ol, DIM, HDIM, SEQ, 1.f);

    // 7) h = O @ Wo + h0
    dim3 gwo(DIM/128, SEQ/128, 1);
    mma_gemm<0><<<gwo, 256, SMEM>>>(oh, ol, DIM, 0, woh, wol, DIM, 0, hf, h0f, nullptr, nullptr, DIM, 0, DIM, 1.f);

    // 8) z = rmsnorm(h)
    rmsnorm_kernel<<<SEQ, 256>>>(hf, gn, zf, zh, zl);

    // 9) G1, G2
    dim3 gffn(HIDN/128, SEQ/128, 1);
    mma_gemm<0><<<gffn, 256, SMEM>>>(zh, zl, DIM, 0, w1h, w1l, DIM, 0, G1, nullptr, nullptr, nullptr, HIDN, 0, DIM, 1.f);
    mma_gemm<0><<<gffn, 256, SMEM>>>(zh, zl, DIM, 0, w2h, w2l, DIM, 0, G2, nullptr, nullptr, nullptr, HIDN, 0, DIM, 1.f);

    // 10) U = silu(G1)*G2 -> pairs
    swiglu_kernel<<<(SEQ * (long)HIDN) / 256, 256>>>(G1, G2, uh, ul);

    // 11) out = U @ W3 + h
    dim3 gw3(DIM/128, SEQ/128, 1);
    mma_gemm<0><<<gw3, 256, SMEM>>>(uh, ul, HIDN, 0, w3h, w3l, HIDN, 0, out, hf, nullptr, nullptr, DIM, 0, HIDN, 1.f);
}

// round 7
// speedup vs baseline: 2.8134x; 1.2624x over previous
#include <cuda_runtime.h>
#include <cuda_bf16.h>
#include <cuda_fp16.h>
#include <math.h>
#include <stdint.h>

#define SEQ 2048
#define DIM 2048
#define NH 16
#define HDIM 128
#define HIDN 8192
#define EPSV 1e-6f
#define LAMB0 0.8f

typedef __nv_bfloat16 bf16;
typedef __half fp16;

// ---------------- scratch (device globals) ----------------
__device__ float g_h0f[SEQ * DIM];
__device__ float g_vf [SEQ * DIM];
__device__ float g_hf [SEQ * DIM];
__device__ float g_s1 [(size_t)NH * SEQ * SEQ];
__device__ float g_s2 [(size_t)NH * SEQ * SEQ];
__device__ float g_G1 [(size_t)SEQ * HIDN];
__device__ float g_G2 [(size_t)SEQ * HIDN];
__device__ float g_lam[NH];

// bf16 pair operands (3-product path: QK, PV, Wo)
__device__ bf16 g_q1h[SEQ*DIM], g_q1l[SEQ*DIM];
__device__ bf16 g_q2h[SEQ*DIM], g_q2l[SEQ*DIM];
__device__ bf16 g_k1h[SEQ*DIM], g_k1l[SEQ*DIM];
__device__ bf16 g_k2h[SEQ*DIM], g_k2l[SEQ*DIM];
__device__ bf16 g_vth[SEQ*DIM], g_vtl[SEQ*DIM];
__device__ bf16 g_oh [SEQ*DIM], g_ol [SEQ*DIM];
__device__ bf16 g_ph [(size_t)NH*SEQ*SEQ], g_pl [(size_t)NH*SEQ*SEQ];
__device__ bf16 g_woh[DIM*DIM], g_wol[DIM*DIM];

// fp16 operands (2-product path: projections + FFN)
__device__ fp16 g_h0a[SEQ*DIM], g_h0b[SEQ*DIM];
__device__ fp16 g_za [SEQ*DIM], g_zb [SEQ*DIM];
__device__ fp16 g_ua [(size_t)SEQ*HIDN], g_ub[(size_t)SEQ*HIDN];
__device__ fp16 g_fwq1[DIM*DIM], g_fwq2[DIM*DIM];
__device__ fp16 g_fwk1[DIM*DIM], g_fwk2[DIM*DIM];
__device__ fp16 g_fwv [DIM*DIM];
__device__ fp16 g_fw1[(size_t)DIM*HIDN], g_fw2[(size_t)DIM*HIDN];
__device__ fp16 g_fw3[(size_t)DIM*HIDN];

// ---------------- helpers ----------------
__device__ __forceinline__ uint32_t smem_u32(const void* p) {
    uint32_t a;
    asm("{ .reg .u64 t; cvta.to.shared.u64 t, %1; cvt.u32.u64 %0, t; }" : "=r"(a) : "l"(p));
    return a;
}
__device__ __forceinline__ void cpa16(uint32_t s, const void* g) {
    asm volatile("cp.async.cg.shared.global [%0], [%1], 16;" :: "r"(s), "l"(g));
}
#define CP_COMMIT() asm volatile("cp.async.commit_group;")
#define CP_WAIT(n)  asm volatile("cp.async.wait_group %0;" :: "n"(n))

__device__ __forceinline__ void ldm4(uint32_t* r, uint32_t addr) {
    asm volatile("ldmatrix.sync.aligned.m8n8.x4.shared.b16 {%0,%1,%2,%3}, [%4];"
        : "=r"(r[0]), "=r"(r[1]), "=r"(r[2]), "=r"(r[3]) : "r"(addr));
}
__device__ __forceinline__ void mma_bf(float* d, const uint32_t* a, uint32_t b0, uint32_t b1) {
    asm volatile("mma.sync.aligned.m16n8k16.row.col.f32.bf16.bf16.f32 "
        "{%0,%1,%2,%3}, {%4,%5,%6,%7}, {%8,%9}, {%0,%1,%2,%3};"
        : "+f"(d[0]), "+f"(d[1]), "+f"(d[2]), "+f"(d[3])
        : "r"(a[0]), "r"(a[1]), "r"(a[2]), "r"(a[3]), "r"(b0), "r"(b1));
}
__device__ __forceinline__ void mma_hf(float* d, const uint32_t* a, uint32_t b0, uint32_t b1) {
    asm volatile("mma.sync.aligned.m16n8k16.row.col.f32.f16.f16.f32 "
        "{%0,%1,%2,%3}, {%4,%5,%6,%7}, {%8,%9}, {%0,%1,%2,%3};"
        : "+f"(d[0]), "+f"(d[1]), "+f"(d[2]), "+f"(d[3])
        : "r"(a[0]), "r"(a[1]), "r"(a[2]), "r"(a[3]), "r"(b0), "r"(b1));
}
__device__ __forceinline__ void split2(float v, bf16* ph, bf16* pl) {
    bf16 h = __float2bfloat16(v);
    *ph = h;
    *pl = __float2bfloat16(v - __bfloat162float(h));
}
__device__ __forceinline__ void split2h(float v, fp16* ph, fp16* pl) {
    fp16 h = __float2half(v);
    *ph = h;
    *pl = __float2half(v - __half2float(h));
}

// ---------------- split mma.sync GEMM: C = alpha*A.B^T (+R) ----------------
// PROD==3: bf16, A pair + B pair, 3 products (AhBh+AlBh+AhBl).
// PROD==2: fp16, A pair + B single (Bl unused), 2 products (AhBh+AlBh).
// MODE 0: fp32 out (+residual if Rf). MODE 1: bf16 pair out.
// A/B are 16-bit element buffers, used for addressing only.
template <int MODE, int PROD>
__global__ __launch_bounds__(256) void mma_gemm(
    const uint16_t* __restrict__ Ah, const uint16_t* __restrict__ Al, int lda, long sA,
    const uint16_t* __restrict__ Bh, const uint16_t* __restrict__ Bl, int ldb, long sB,
    float* __restrict__ Cf, const float* __restrict__ Rf,
    bf16* __restrict__ Ch, bf16* __restrict__ Cl,
    int ldc, long sC, int K, float alpha)
{
    constexpr int RSB  = 80;               // 32 elems*2B + 8B pad
    constexpr int MATB = 128 * RSB;        // 10240
    constexpr int NMAT = (PROD == 3) ? 4 : 3;
    constexpr int STG  = NMAT * MATB;
    extern __shared__ __align__(128) char dsm[];
    const uint32_t sb = smem_u32(dsm);

    const int tid = threadIdx.x;
    const int m0 = blockIdx.y * 128, n0 = blockIdx.x * 128, z = blockIdx.z;

    Ah += (long)z * sA + (long)m0 * lda;
    Al += (long)z * sA + (long)m0 * lda;
    Bh += (long)z * sB + (long)n0 * ldb;
    if (PROD == 3) Bl += (long)z * sB + (long)n0 * ldb;

    const int NC = K >> 5;   // KC = 32

    auto load_chunk = [&](int c, int s) {
        const long k0 = (long)c << 5;
        const uint32_t st = sb + (uint32_t)s * STG;
        #pragma unroll
        for (int i = 0; i < 2; i++) {
            int idx = tid + 256 * i;
            int row = idx >> 2;
            int sg  = idx & 3;
            uint32_t so = st + (uint32_t)row * RSB + (uint32_t)sg * 16;
            long ga = (long)row * lda + k0 + sg * 8;
            long gb = (long)row * ldb + k0 + sg * 8;
            cpa16(so,          Ah + ga);
            cpa16(so + MATB,   Al + ga);
            cpa16(so + 2*MATB, Bh + gb);
            if (PROD == 3) cpa16(so + 3*MATB, Bl + gb);
        }
    };

    const int l  = tid & 31;
    const int wp = tid >> 5;
    const int wm = (wp >> 2) * 64;
    const int wn = (wp & 3) * 32;
    const uint32_t aoff = (uint32_t)(wm + (l & 15)) * RSB + (uint32_t)((l >> 4) * 16);
    const uint32_t boff = 2u*MATB + (uint32_t)(wn + (l & 7) + ((l >> 4) << 3)) * RSB
                        + (uint32_t)(((l >> 3) & 1) * 16);

    float acc[4][4][4];
    #pragma unroll
    for (int a = 0; a < 4; a++)
        #pragma unroll
        for (int b = 0; b < 4; b++)
            #pragma unroll
            for (int c = 0; c < 4; c++) acc[a][b][c] = 0.f;

    load_chunk(0, 0); CP_COMMIT();
    load_chunk(1, 1); CP_COMMIT();
    load_chunk(2, 2); CP_COMMIT();

    for (int c = 0; c < NC; c++) {
        const int s = c & 3;
        const int rem = NC - 1 - c;
        if (rem >= 2)      { CP_WAIT(2); }
        else if (rem == 1) { CP_WAIT(1); }
        else               { CP_WAIT(0); }
        __syncthreads();
        if (c + 3 < NC) { load_chunk(c + 3, (c + 3) & 3); CP_COMMIT(); }

        const uint32_t stg = sb + (uint32_t)s * STG;
        #pragma unroll
        for (int ks = 0; ks < 2; ks++) {
            const uint32_t base = stg + (uint32_t)ks * 32;
            uint32_t ah[4][4], al[4][4], bh[2][4];
            #pragma unroll
            for (int mi = 0; mi < 4; mi++) {
                ldm4(ah[mi], base + aoff + (uint32_t)mi * (16 * RSB));
                ldm4(al[mi], base + aoff + (uint32_t)mi * (16 * RSB) + MATB);
            }
            #pragma unroll
            for (int ng = 0; ng < 2; ng++)
                ldm4(bh[ng], base + boff + (uint32_t)ng * (16 * RSB));

            if (PROD == 3) {
                uint32_t bl[2][4];
                #pragma unroll
                for (int ng = 0; ng < 2; ng++)
                    ldm4(bl[ng], base + boff + (uint32_t)ng * (16 * RSB) + MATB);
                #pragma unroll
                for (int mi = 0; mi < 4; mi++)
                    #pragma unroll
                    for (int ni = 0; ni < 4; ni++)
                        mma_bf(acc[mi][ni], ah[mi],
                               bh[ni >> 1][(ni & 1) * 2], bh[ni >> 1][(ni & 1) * 2 + 1]);
                #pragma unroll
                for (int mi = 0; mi < 4; mi++)
                    #pragma unroll
                    for (int ni = 0; ni < 4; ni++)
                        mma_bf(acc[mi][ni], al[mi],
                               bh[ni >> 1][(ni & 1) * 2], bh[ni >> 1][(ni & 1) * 2 + 1]);
                #pragma unroll
                for (int mi = 0; mi < 4; mi++)
                    #pragma unroll
                    for (int ni = 0; ni < 4; ni++)
                        mma_bf(acc[mi][ni], ah[mi],
                               bl[ni >> 1][(ni & 1) * 2], bl[ni >> 1][(ni & 1) * 2 + 1]);
            } else {
                #pragma unroll
                for (int mi = 0; mi < 4; mi++)
                    #pragma unroll
                    for (int ni = 0; ni < 4; ni++)
                        mma_hf(acc[mi][ni], ah[mi],
                               bh[ni >> 1][(ni & 1) * 2], bh[ni >> 1][(ni & 1) * 2 + 1]);
                #pragma unroll
                for (int mi = 0; mi < 4; mi++)
                    #pragma unroll
                    for (int ni = 0; ni < 4; ni++)
                        mma_hf(acc[mi][ni], al[mi],
                               bh[ni >> 1][(ni & 1) * 2], bh[ni >> 1][(ni & 1) * 2 + 1]);
            }
        }
    }

    const int qr = l >> 2;
    const int qc = (l & 3) * 2;
    const long cbase = (long)z * sC + (long)m0 * ldc + n0;
    #pragma unroll
    for (int mi = 0; mi < 4; mi++)
        #pragma unroll
        for (int ni = 0; ni < 4; ni++)
            #pragma unroll
            for (int hr = 0; hr < 2; hr++) {
                long off = cbase + (long)(wm + mi * 16 + qr + hr * 8) * ldc + (wn + ni * 8 + qc);
                float v0 = acc[mi][ni][hr * 2 + 0] * alpha;
                float v1 = acc[mi][ni][hr * 2 + 1] * alpha;
                if (MODE == 0) {
                    if (Rf) { v0 += Rf[off]; v1 += Rf[off + 1]; }
                    Cf[off] = v0; Cf[off + 1] = v1;
                } else {
                    split2(v0, Ch + off,     Cl + off);
                    split2(v1, Ch + off + 1, Cl + off + 1);
                }
            }
}

// ---------------- transpose kernels ----------------
__global__ __launch_bounds__(256) void transpose_split(const float* __restrict__ in,
                                                       bf16* __restrict__ oh, bf16* __restrict__ ol,
                                                       int R, int C) {
    const long zb = (long)blockIdx.z * R * C;
    in += zb; oh += zb; ol += zb;
    const int c0 = blockIdx.x * 32, r0 = blockIdx.y * 32;
    __shared__ float t[32][33];
    const int tx = threadIdx.x & 31, ty = threadIdx.x >> 5;
    #pragma unroll
    for (int i = 0; i < 4; i++)
        t[ty + 8*i][tx] = in[(long)(r0 + ty + 8*i) * C + c0 + tx];
    __syncthreads();
    #pragma unroll
    for (int i = 0; i < 4; i++) {
        float v = t[tx][ty + 8*i];
        long o = (long)(c0 + ty + 8*i) * R + r0 + tx;
        split2(v, oh + o, ol + o);
    }
}

__global__ __launch_bounds__(256) void transpose_half(const float* __restrict__ in,
                                                      fp16* __restrict__ oh,
                                                      int R, int C) {
    const long zb = (long)blockIdx.z * R * C;
    in += zb; oh += zb;
    const int c0 = blockIdx.x * 32, r0 = blockIdx.y * 32;
    __shared__ float t[32][33];
    const int tx = threadIdx.x & 31, ty = threadIdx.x >> 5;
    #pragma unroll
    for (int i = 0; i < 4; i++)
        t[ty + 8*i][tx] = in[(long)(r0 + ty + 8*i) * C + c0 + tx];
    __syncthreads();
    #pragma unroll
    for (int i = 0; i < 4; i++)
        oh[(long)(c0 + ty + 8*i) * R + r0 + tx] = __float2half(t[tx][ty + 8*i]);
}

// ---------------- fused RMSNorm -> optional fp32 + fp16 pair ----------------
__global__ __launch_bounds__(256) void rmsnorm_kernel(const float* __restrict__ x,
                                                      const float* __restrict__ g,
                                                      float* __restrict__ yf,
                                                      fp16* __restrict__ ya, fp16* __restrict__ yb) {
    __shared__ float sh[8];
    const long row = blockIdx.x;
    const float* xr = x + row * (long)DIM;
    float v[8], ss = 0.f;
    #pragma unroll
    for (int i = 0; i < 8; i++) { v[i] = xr[threadIdx.x + 256*i]; ss += v[i]*v[i]; }
    #pragma unroll
    for (int o = 16; o; o >>= 1) ss += __shfl_xor_sync(0xffffffffu, ss, o);
    if ((threadIdx.x & 31) == 0) sh[threadIdx.x >> 5] = ss;
    __syncthreads();
    float tot = 0.f;
    #pragma unroll
    for (int i = 0; i < 8; i++) tot += sh[i];
    const float sc = rsqrtf(tot * (1.0f / DIM) + EPSV);
    #pragma unroll
    for (int i = 0; i < 8; i++) {
        int c = threadIdx.x + 256*i;
        float y = v[i] * sc * g[c];
        long o = row * (long)DIM + c;
        if (yf) yf[o] = y;
        split2h(y, ya + o, yb + o);
    }
}

// ---------------- lambda ----------------
__global__ void lambda_kernel(const float* __restrict__ lq1, const float* __restrict__ lk1,
                              const float* __restrict__ lq2, const float* __restrict__ lk2,
                              float* __restrict__ lam) {
    __shared__ float s1[128], s2[128];
    int h = blockIdx.x, t = threadIdx.x;
    int i = h * HDIM + t;
    s1[t] = lq1[i] * lk1[i];
    s2[t] = lq2[i] * lk2[i];
    __syncthreads();
    for (int o = 64; o; o >>= 1) {
        if (t < o) { s1[t] += s1[t+o]; s2[t] += s2[t+o]; }
        __syncthreads();
    }
    if (t == 0) lam[h] = expf(s1[0]) - expf(s2[0]) + LAMB0;
}

// ---------------- dual softmax + combine -> P bf16 pairs ----------------
__global__ __launch_bounds__(256) void softmax_combine(const float* __restrict__ s1,
                                                       const float* __restrict__ s2,
                                                       const float* __restrict__ lam,
                                                       bf16* __restrict__ ph, bf16* __restrict__ pl) {
    __shared__ float sh[8];
    const long off = (long)blockIdx.y * SEQ * SEQ + (long)blockIdx.x * SEQ;
    const float* r1 = s1 + off;
    const float* r2 = s2 + off;
    const int t = threadIdx.x;
    float v1[8], v2[8];
    #pragma unroll
    for (int i = 0; i < 8; i++) { v1[i] = r1[t + 256*i]; v2[i] = r2[t + 256*i]; }

    float mm = -1e30f;
    #pragma unroll
    for (int i = 0; i < 8; i++) { mm = fmaxf(mm, v1[i]); mm = fmaxf(mm, v2[i]); }
    #pragma unroll
    for (int o = 16; o; o >>= 1) mm = fmaxf(mm, __shfl_xor_sync(0xffffffffu, mm, o));
    if ((t & 31) == 0) sh[t >> 5] = mm;
    __syncthreads();
    float M = sh[0];
    #pragma unroll
    for (int i = 1; i < 8; i++) M = fmaxf(M, sh[i]);
    __syncthreads();

    float p1 = 0.f, p2 = 0.f;
    #pragma unroll
    for (int i = 0; i < 8; i++) {
        v1[i] = __expf(v1[i] - M); p1 += v1[i];
        v2[i] = __expf(v2[i] - M); p2 += v2[i];
    }
    #pragma unroll
    for (int o = 16; o; o >>= 1) {
        p1 += __shfl_xor_sync(0xffffffffu, p1, o);
        p2 += __shfl_xor_sync(0xffffffffu, p2, o);
    }
    __shared__ float sx[8], sy[8];
    if ((t & 31) == 0) { sx[t >> 5] = p1; sy[t >> 5] = p2; }
    __syncthreads();
    float S1 = 0.f, S2 = 0.f;
    #pragma unroll
    for (int i = 0; i < 8; i++) { S1 += sx[i]; S2 += sy[i]; }

    const float i1 = 1.f / S1;
    const float i2 = lam[blockIdx.y] / S2;
    #pragma unroll
    for (int i = 0; i < 8; i++) {
        long o = off + t + 256*i;
        split2(v1[i] * i1 - v2[i] * i2, ph + o, pl + o);
    }
}

// ---------------- SwiGLU -> fp16 pairs ----------------
__global__ __launch_bounds__(256) void swiglu_kernel(const float* __restrict__ g1,
                                                     const float* __restrict__ g2,
                                                     fp16* __restrict__ ua, fp16* __restrict__ ub) {
    long i = (long)blockIdx.x * 256 + threadIdx.x;
    float a = g1[i];
    float u = a / (1.f + __expf(-a)) * g2[i];
    split2h(u, ua + i, ub + i);
}

// ---------------- launcher ----------------
extern "C" void kernel_launch(void* const* d_in, const int* in_sizes, int n_in,
                              void* d_out, int out_size) {
    (void)in_sizes; (void)n_in; (void)out_size;
    const float* x   = (const float*)d_in[0];
    const float* gn  = (const float*)d_in[1];
    const float* Wq1 = (const float*)d_in[2];
    const float* Wq2 = (const float*)d_in[3];
    const float* Wk1 = (const float*)d_in[4];
    const float* Wk2 = (const float*)d_in[5];
    const float* Wv  = (const float*)d_in[6];
    const float* lq1 = (const float*)d_in[7];
    const float* lk1 = (const float*)d_in[8];
    const float* lq2 = (const float*)d_in[9];
    const float* lk2 = (const float*)d_in[10];
    const float* Wo  = (const float*)d_in[11];
    const float* W1  = (const float*)d_in[12];
    const float* W2  = (const float*)d_in[13];
    const float* W3  = (const float*)d_in[14];
    float* out = (float*)d_out;

    const int SMEM3 = 4 * 4 * 10240;   // 163840 (4 matrices)
    const int SMEM2 = 4 * 3 * 10240;   // 122880 (3 matrices)
    cudaFuncSetAttribute(mma_gemm<0,3>, cudaFuncAttributeMaxDynamicSharedMemorySize, SMEM3);
    cudaFuncSetAttribute(mma_gemm<1,3>, cudaFuncAttributeMaxDynamicSharedMemorySize, SMEM3);
    cudaFuncSetAttribute(mma_gemm<0,2>, cudaFuncAttributeMaxDynamicSharedMemorySize, SMEM2);
    cudaFuncSetAttribute(mma_gemm<1,2>, cudaFuncAttributeMaxDynamicSharedMemorySize, SMEM2);

#define SYM(v, s) cudaGetSymbolAddress((void**)&v, s)
    float *h0f, *vf, *hf, *s1, *s2, *G1, *G2, *lam;
    SYM(h0f, g_h0f); SYM(vf, g_vf); SYM(hf, g_hf);
    SYM(s1, g_s1); SYM(s2, g_s2); SYM(G1, g_G1); SYM(G2, g_G2); SYM(lam, g_lam);
    bf16 *q1h,*q1l,*q2h,*q2l,*k1h,*k1l,*k2h,*k2l,*vth,*vtl,*oh,*ol,*ph,*pl,*woh,*wol;
    SYM(q1h, g_q1h); SYM(q1l, g_q1l); SYM(q2h, g_q2h); SYM(q2l, g_q2l);
    SYM(k1h, g_k1h); SYM(k1l, g_k1l); SYM(k2h, g_k2h); SYM(k2l, g_k2l);
    SYM(vth, g_vth); SYM(vtl, g_vtl); SYM(oh, g_oh); SYM(ol, g_ol);
    SYM(ph, g_ph); SYM(pl, g_pl); SYM(woh, g_woh); SYM(wol, g_wol);
    fp16 *h0a,*h0b,*za,*zb,*ua,*ub,*fwq1,*fwq2,*fwk1,*fwk2,*fwv,*fw1,*fw2,*fw3;
    SYM(h0a, g_h0a); SYM(h0b, g_h0b); SYM(za, g_za); SYM(zb, g_zb);
    SYM(ua, g_ua); SYM(ub, g_ub);
    SYM(fwq1, g_fwq1); SYM(fwq2, g_fwq2); SYM(fwk1, g_fwk1); SYM(fwk2, g_fwk2);
    SYM(fwv, g_fwv); SYM(fw1, g_fw1); SYM(fw2, g_fw2); SYM(fw3, g_fw3);
#undef SYM

    const long SS = (long)SEQ * SEQ;
    const float qkscale = 0.08838834764831845f; // 1/sqrt(128)
#define U16(p) ((const uint16_t*)(p))

    // weight conversions
    dim3 gtA(HDIM/32, DIM/32, NH);          // [H,D,DH] -> per-head [DH,D]
    transpose_half<<<gtA, 256>>>(Wq1, fwq1, DIM, HDIM);
    transpose_half<<<gtA, 256>>>(Wq2, fwq2, DIM, HDIM);
    transpose_half<<<gtA, 256>>>(Wk1, fwk1, DIM, HDIM);
    transpose_half<<<gtA, 256>>>(Wk2, fwk2, DIM, HDIM);
    transpose_half<<<gtA, 256>>>(Wv,  fwv,  DIM, HDIM);
    dim3 gtO(DIM/32, DIM/32, 1);
    transpose_split<<<gtO, 256>>>(Wo, woh, wol, DIM, DIM);
    dim3 gt1(HIDN/32, DIM/32, 1);
    transpose_half<<<gt1, 256>>>(W1, fw1, DIM, HIDN);
    transpose_half<<<gt1, 256>>>(W2, fw2, DIM, HIDN);
    dim3 gt3(DIM/32, HIDN/32, 1);
    transpose_half<<<gt3, 256>>>(W3, fw3, HIDN, DIM);

    // 1) h0 = rmsnorm(x): fp32 + fp16 pair
    rmsnorm_kernel<<<SEQ, 256>>>(x, gn, h0f, h0a, h0b);
    lambda_kernel<<<NH, 128>>>(lq1, lk1, lq2, lk2, lam);

    // 2) projections: fp16 2-product; q/k out as bf16 pairs, v as fp32
    dim3 gproj(DIM/128, SEQ/128, 1);
    mma_gemm<1,2><<<gproj, 256, SMEM2>>>(U16(h0a), U16(h0b), DIM, 0, U16(fwq1), nullptr, DIM, 0, nullptr, nullptr, q1h, q1l, DIM, 0, DIM, 1.f);
    mma_gemm<1,2><<<gproj, 256, SMEM2>>>(U16(h0a), U16(h0b), DIM, 0, U16(fwq2), nullptr, DIM, 0, nullptr, nullptr, q2h, q2l, DIM, 0, DIM, 1.f);
    mma_gemm<1,2><<<gproj, 256, SMEM2>>>(U16(h0a), U16(h0b), DIM, 0, U16(fwk1), nullptr, DIM, 0, nullptr, nullptr, k1h, k1l, DIM, 0, DIM, 1.f);
    mma_gemm<1,2><<<gproj, 256, SMEM2>>>(U16(h0a), U16(h0b), DIM, 0, U16(fwk2), nullptr, DIM, 0, nullptr, nullptr, k2h, k2l, DIM, 0, DIM, 1.f);
    mma_gemm<0,2><<<gproj, 256, SMEM2>>>(U16(h0a), U16(h0b), DIM, 0, U16(fwv),  nullptr, DIM, 0, vf, nullptr, nullptr, nullptr, DIM, 0, DIM, 1.f);

    // 3) V^T bf16 pairs
    dim3 gtV(DIM/32, SEQ/32, 1);
    transpose_split<<<gtV, 256>>>(vf, vth, vtl, SEQ, DIM);

    // 4) scores: bf16 3-product
    dim3 gqk(SEQ/128, SEQ/128, NH);
    mma_gemm<0,3><<<gqk, 256, SMEM3>>>(U16(q1h), U16(q1l), DIM, HDIM, U16(k1h), U16(k1l), DIM, HDIM, s1, nullptr, nullptr, nullptr, SEQ, SS, HDIM, qkscale);
    mma_gemm<0,3><<<gqk, 256, SMEM3>>>(U16(q2h), U16(q2l), DIM, HDIM, U16(k2h), U16(k2l), DIM, HDIM, s2, nullptr, nullptr, nullptr, SEQ, SS, HDIM, qkscale);

    // 5) P = softmax(S1) - lam*softmax(S2) -> bf16 pairs
    dim3 gsm(SEQ, NH);
    softmax_combine<<<gsm, 256>>>(s1, s2, lam, ph, pl);

    // 6) O = P @ V (bf16 3-product, pair out)
    dim3 gpv(1, SEQ/128, NH);
    mma_gemm<1,3><<<gpv, 256, SMEM3>>>(U16(ph), U16(pl), SEQ, SS, U16(vth), U16(vtl), SEQ, (long)HDIM*SEQ, nullptr, nullptr, oh, ol, DIM, HDIM, SEQ, 1.f);

    // 7) h = O @ Wo + h0 (bf16 3-product)
    dim3 gwo(DIM/128, SEQ/128, 1);
    mma_gemm<0,3><<<gwo, 256, SMEM3>>>(U16(oh), U16(ol), DIM, 0, U16(woh), U16(wol), DIM, 0, hf, h0f, nullptr, nullptr, DIM, 0, DIM, 1.f);

    // 8) z = rmsnorm(h): fp16 pair only
    rmsnorm_kernel<<<SEQ, 256>>>(hf, gn, nullptr, za, zb);

    // 9) G1, G2: fp16 2-product
    dim3 gffn(HIDN/128, SEQ/128, 1);
    mma_gemm<0,2><<<gffn, 256, SMEM2>>>(U16(za), U16(zb), DIM, 0, U16(fw1), nullptr, DIM, 0, G1, nullptr, nullptr, nullptr, HIDN, 0, DIM, 1.f);
    mma_gemm<0,2><<<gffn, 256, SMEM2>>>(U16(za), U16(zb), DIM, 0, U16(fw2), nullptr, DIM, 0, G2, nullptr, nullptr, nullptr, HIDN, 0, DIM, 1.f);

    // 10) U = silu(G1)*G2 -> fp16 pairs
    swiglu_kernel<<<(SEQ * (long)HIDN) / 256, 256>>>(G1, G2, ua, ub);

    // 11) out = U @ W3 + h (fp16 2-product)
    dim3 gw3(DIM/128, SEQ/128, 1);
    mma_gemm<0,2><<<gw3, 256, SMEM2>>>(U16(ua), U16(ub), HIDN, 0, U16(fw3), nullptr, HIDN, 0, out, hf, nullptr, nullptr, DIM, 0, HIDN, 1.f);
#undef U16
}

// round 8
// speedup vs baseline: 2.9906x; 1.0630x over previous
#include <cuda_runtime.h>
#include <cuda_fp16.h>
#include <math.h>
#include <stdint.h>

#define SEQ 2048
#define DIM 2048
#define NH 16
#define HDIM 128
#define HIDN 8192
#define EPSV 1e-6f
#define LAMB0 0.8f

typedef __half fp16;

// ---------------- scratch (device globals) ----------------
__device__ float g_h0f[SEQ * DIM];
__device__ float g_vf [SEQ * DIM];
__device__ float g_hf [SEQ * DIM];
__device__ float g_s1 [(size_t)NH * SEQ * SEQ];
__device__ float g_s2 [(size_t)NH * SEQ * SEQ];
__device__ float g_G1 [(size_t)SEQ * HIDN];
__device__ float g_G2 [(size_t)SEQ * HIDN];
__device__ float g_lam[NH];

// fp16 operands
__device__ fp16 g_h0a[SEQ*DIM], g_h0b[SEQ*DIM];
__device__ fp16 g_za [SEQ*DIM], g_zb [SEQ*DIM];
__device__ fp16 g_q1a[SEQ*DIM], g_q1b[SEQ*DIM];
__device__ fp16 g_q2a[SEQ*DIM], g_q2b[SEQ*DIM];
__device__ fp16 g_k1 [SEQ*DIM], g_k2 [SEQ*DIM];
__device__ fp16 g_vt [SEQ*DIM];
__device__ fp16 g_oa [SEQ*DIM], g_ob [SEQ*DIM];
__device__ fp16 g_pa [(size_t)NH*SEQ*SEQ], g_pb [(size_t)NH*SEQ*SEQ];
__device__ fp16 g_ua [(size_t)SEQ*HIDN], g_ub[(size_t)SEQ*HIDN];
__device__ fp16 g_fwq1[DIM*DIM], g_fwq2[DIM*DIM];
__device__ fp16 g_fwk1[DIM*DIM], g_fwk2[DIM*DIM];
__device__ fp16 g_fwv [DIM*DIM], g_fwo [DIM*DIM];
__device__ fp16 g_fw1[(size_t)DIM*HIDN], g_fw2[(size_t)DIM*HIDN];
__device__ fp16 g_fw3[(size_t)DIM*HIDN];

// ---------------- helpers ----------------
__device__ __forceinline__ uint32_t smem_u32(const void* p) {
    uint32_t a;
    asm("{ .reg .u64 t; cvta.to.shared.u64 t, %1; cvt.u32.u64 %0, t; }" : "=r"(a) : "l"(p));
    return a;
}
__device__ __forceinline__ void cpa16(uint32_t s, const void* g) {
    asm volatile("cp.async.cg.shared.global [%0], [%1], 16;" :: "r"(s), "l"(g));
}
#define CP_COMMIT() asm volatile("cp.async.commit_group;")
#define CP_WAIT(n)  asm volatile("cp.async.wait_group %0;" :: "n"(n))

__device__ __forceinline__ void ldm4(uint32_t* r, uint32_t addr) {
    asm volatile("ldmatrix.sync.aligned.m8n8.x4.shared.b16 {%0,%1,%2,%3}, [%4];"
        : "=r"(r[0]), "=r"(r[1]), "=r"(r[2]), "=r"(r[3]) : "r"(addr));
}
__device__ __forceinline__ void mma_hf(float* d, const uint32_t* a, uint32_t b0, uint32_t b1) {
    asm volatile("mma.sync.aligned.m16n8k16.row.col.f32.f16.f16.f32 "
        "{%0,%1,%2,%3}, {%4,%5,%6,%7}, {%8,%9}, {%0,%1,%2,%3};"
        : "+f"(d[0]), "+f"(d[1]), "+f"(d[2]), "+f"(d[3])
        : "r"(a[0]), "r"(a[1]), "r"(a[2]), "r"(a[3]), "r"(b0), "r"(b1));
}
__device__ __forceinline__ void split2h(float v, fp16* ph, fp16* pl) {
    fp16 h = __float2half(v);
    *ph = h;
    *pl = __float2half(v - __half2float(h));
}

// ---------------- fp16 2-product mma.sync GEMM: C = alpha*A.B^T (+R) ----------------
// A = Ah+Al (fp16 pair, ~22-bit), B = single fp16. acc = Ah.B + Al.B.
// MODE 0: fp32 out (+residual if Rf). MODE 1: fp16 pair out. MODE 2: fp16 single out.
template <int MODE>
__global__ __launch_bounds__(256) void mma_gemm(
    const fp16* __restrict__ Ah, const fp16* __restrict__ Al, int lda, long sA,
    const fp16* __restrict__ B, int ldb, long sB,
    float* __restrict__ Cf, const float* __restrict__ Rf,
    fp16* __restrict__ Ch, fp16* __restrict__ Cl,
    int ldc, long sC, int K, float alpha)
{
    constexpr int RSB  = 80;               // 32 elems*2B + 8B pad
    constexpr int MATB = 128 * RSB;        // 10240
    constexpr int STG  = 3 * MATB;         // Ah, Al, B
    extern __shared__ __align__(128) char dsm[];
    const uint32_t sb = smem_u32(dsm);

    const int tid = threadIdx.x;
    const int m0 = blockIdx.y * 128, n0 = blockIdx.x * 128, z = blockIdx.z;

    Ah += (long)z * sA + (long)m0 * lda;
    Al += (long)z * sA + (long)m0 * lda;
    B  += (long)z * sB + (long)n0 * ldb;

    const int NC = K >> 5;   // KC = 32

    auto load_chunk = [&](int c, int s) {
        const long k0 = (long)c << 5;
        const uint32_t st = sb + (uint32_t)s * STG;
        #pragma unroll
        for (int i = 0; i < 2; i++) {
            int idx = tid + 256 * i;
            int row = idx >> 2;
            int sg  = idx & 3;
            uint32_t so = st + (uint32_t)row * RSB + (uint32_t)sg * 16;
            long ga = (long)row * lda + k0 + sg * 8;
            long gb = (long)row * ldb + k0 + sg * 8;
            cpa16(so,          Ah + ga);
            cpa16(so + MATB,   Al + ga);
            cpa16(so + 2*MATB, B + gb);
        }
    };

    const int l  = tid & 31;
    const int wp = tid >> 5;
    const int wm = (wp >> 2) * 64;
    const int wn = (wp & 3) * 32;
    const uint32_t aoff = (uint32_t)(wm + (l & 15)) * RSB + (uint32_t)((l >> 4) * 16);
    const uint32_t boff = 2u*MATB + (uint32_t)(wn + (l & 7) + ((l >> 4) << 3)) * RSB
                        + (uint32_t)(((l >> 3) & 1) * 16);

    float acc[4][4][4];
    #pragma unroll
    for (int a = 0; a < 4; a++)
        #pragma unroll
        for (int b = 0; b < 4; b++)
            #pragma unroll
            for (int c = 0; c < 4; c++) acc[a][b][c] = 0.f;

    load_chunk(0, 0); CP_COMMIT();
    load_chunk(1, 1); CP_COMMIT();
    load_chunk(2, 2); CP_COMMIT();

    for (int c = 0; c < NC; c++) {
        const int s = c & 3;
        const int rem = NC - 1 - c;
        if (rem >= 2)      { CP_WAIT(2); }
        else if (rem == 1) { CP_WAIT(1); }
        else               { CP_WAIT(0); }
        __syncthreads();
        if (c + 3 < NC) { load_chunk(c + 3, (c + 3) & 3); CP_COMMIT(); }

        const uint32_t stg = sb + (uint32_t)s * STG;
        #pragma unroll
        for (int ks = 0; ks < 2; ks++) {
            const uint32_t base = stg + (uint32_t)ks * 32;
            uint32_t ah[4][4], al[4][4], bh[2][4];
            #pragma unroll
            for (int mi = 0; mi < 4; mi++) {
                ldm4(ah[mi], base + aoff + (uint32_t)mi * (16 * RSB));
                ldm4(al[mi], base + aoff + (uint32_t)mi * (16 * RSB) + MATB);
            }
            #pragma unroll
            for (int ng = 0; ng < 2; ng++)
                ldm4(bh[ng], base + boff + (uint32_t)ng * (16 * RSB));

            #pragma unroll
            for (int mi = 0; mi < 4; mi++)
                #pragma unroll
                for (int ni = 0; ni < 4; ni++)
                    mma_hf(acc[mi][ni], ah[mi],
                           bh[ni >> 1][(ni & 1) * 2], bh[ni >> 1][(ni & 1) * 2 + 1]);
            #pragma unroll
            for (int mi = 0; mi < 4; mi++)
                #pragma unroll
                for (int ni = 0; ni < 4; ni++)
                    mma_hf(acc[mi][ni], al[mi],
                           bh[ni >> 1][(ni & 1) * 2], bh[ni >> 1][(ni & 1) * 2 + 1]);
        }
    }

    const int qr = l >> 2;
    const int qc = (l & 3) * 2;
    const long cbase = (long)z * sC + (long)m0 * ldc + n0;
    #pragma unroll
    for (int mi = 0; mi < 4; mi++)
        #pragma unroll
        for (int ni = 0; ni < 4; ni++)
            #pragma unroll
            for (int hr = 0; hr < 2; hr++) {
                long off = cbase + (long)(wm + mi * 16 + qr + hr * 8) * ldc + (wn + ni * 8 + qc);
                float v0 = acc[mi][ni][hr * 2 + 0] * alpha;
                float v1 = acc[mi][ni][hr * 2 + 1] * alpha;
                if (MODE == 0) {
                    if (Rf) { v0 += Rf[off]; v1 += Rf[off + 1]; }
                    Cf[off] = v0; Cf[off + 1] = v1;
                } else if (MODE == 1) {
                    split2h(v0, Ch + off,     Cl + off);
                    split2h(v1, Ch + off + 1, Cl + off + 1);
                } else {
                    Ch[off]     = __float2half(v0);
                    Ch[off + 1] = __float2half(v1);
                }
            }
}

// ---------------- transpose: [Z,R,C] fp32 -> [Z,C,R] fp16 ----------------
__global__ __launch_bounds__(256) void transpose_half(const float* __restrict__ in,
                                                      fp16* __restrict__ oh,
                                                      int R, int C) {
    const long zb = (long)blockIdx.z * R * C;
    in += zb; oh += zb;
    const int c0 = blockIdx.x * 32, r0 = blockIdx.y * 32;
    __shared__ float t[32][33];
    const int tx = threadIdx.x & 31, ty = threadIdx.x >> 5;
    #pragma unroll
    for (int i = 0; i < 4; i++)
        t[ty + 8*i][tx] = in[(long)(r0 + ty + 8*i) * C + c0 + tx];
    __syncthreads();
    #pragma unroll
    for (int i = 0; i < 4; i++)
        oh[(long)(c0 + ty + 8*i) * R + r0 + tx] = __float2half(t[tx][ty + 8*i]);
}

// ---------------- fused RMSNorm -> optional fp32 + fp16 pair ----------------
__global__ __launch_bounds__(256) void rmsnorm_kernel(const float* __restrict__ x,
                                                      const float* __restrict__ g,
                                                      float* __restrict__ yf,
                                                      fp16* __restrict__ ya, fp16* __restrict__ yb) {
    __shared__ float sh[8];
    const long row = blockIdx.x;
    const float* xr = x + row * (long)DIM;
    float v[8], ss = 0.f;
    #pragma unroll
    for (int i = 0; i < 8; i++) { v[i] = xr[threadIdx.x + 256*i]; ss += v[i]*v[i]; }
    #pragma unroll
    for (int o = 16; o; o >>= 1) ss += __shfl_xor_sync(0xffffffffu, ss, o);
    if ((threadIdx.x & 31) == 0) sh[threadIdx.x >> 5] = ss;
    __syncthreads();
    float tot = 0.f;
    #pragma unroll
    for (int i = 0; i < 8; i++) tot += sh[i];
    const float sc = rsqrtf(tot * (1.0f / DIM) + EPSV);
    #pragma unroll
    for (int i = 0; i < 8; i++) {
        int c = threadIdx.x + 256*i;
        float y = v[i] * sc * g[c];
        long o = row * (long)DIM + c;
        if (yf) yf[o] = y;
        split2h(y, ya + o, yb + o);
    }
}

// ---------------- lambda ----------------
__global__ void lambda_kernel(const float* __restrict__ lq1, const float* __restrict__ lk1,
                              const float* __restrict__ lq2, const float* __restrict__ lk2,
                              float* __restrict__ lam) {
    __shared__ float s1[128], s2[128];
    int h = blockIdx.x, t = threadIdx.x;
    int i = h * HDIM + t;
    s1[t] = lq1[i] * lk1[i];
    s2[t] = lq2[i] * lk2[i];
    __syncthreads();
    for (int o = 64; o; o >>= 1) {
        if (t < o) { s1[t] += s1[t+o]; s2[t] += s2[t+o]; }
        __syncthreads();
    }
    if (t == 0) lam[h] = expf(s1[0]) - expf(s2[0]) + LAMB0;
}

// ---------------- dual softmax + combine -> P fp16 pairs ----------------
__global__ __launch_bounds__(256) void softmax_combine(const float* __restrict__ s1,
                                                       const float* __restrict__ s2,
                                                       const float* __restrict__ lam,
                                                       fp16* __restrict__ pa, fp16* __restrict__ pb) {
    __shared__ float sh[8];
    const long off = (long)blockIdx.y * SEQ * SEQ + (long)blockIdx.x * SEQ;
    const float* r1 = s1 + off;
    const float* r2 = s2 + off;
    const int t = threadIdx.x;
    float v1[8], v2[8];
    #pragma unroll
    for (int i = 0; i < 8; i++) { v1[i] = r1[t + 256*i]; v2[i] = r2[t + 256*i]; }

    float mm = -1e30f;
    #pragma unroll
    for (int i = 0; i < 8; i++) { mm = fmaxf(mm, v1[i]); mm = fmaxf(mm, v2[i]); }
    #pragma unroll
    for (int o = 16; o; o >>= 1) mm = fmaxf(mm, __shfl_xor_sync(0xffffffffu, mm, o));
    if ((t & 31) == 0) sh[t >> 5] = mm;
    __syncthreads();
    float M = sh[0];
    #pragma unroll
    for (int i = 1; i < 8; i++) M = fmaxf(M, sh[i]);
    __syncthreads();

    float p1 = 0.f, p2 = 0.f;
    #pragma unroll
    for (int i = 0; i < 8; i++) {
        v1[i] = __expf(v1[i] - M); p1 += v1[i];
        v2[i] = __expf(v2[i] - M); p2 += v2[i];
    }
    #pragma unroll
    for (int o = 16; o; o >>= 1) {
        p1 += __shfl_xor_sync(0xffffffffu, p1, o);
        p2 += __shfl_xor_sync(0xffffffffu, p2, o);
    }
    __shared__ float sx[8], sy[8];
    if ((t & 31) == 0) { sx[t >> 5] = p1; sy[t >> 5] = p2; }
    __syncthreads();
    float S1 = 0.f, S2 = 0.f;
    #pragma unroll
    for (int i = 0; i < 8; i++) { S1 += sx[i]; S2 += sy[i]; }

    const float i1 = 1.f / S1;
    const float i2 = lam[blockIdx.y] / S2;
    #pragma unroll
    for (int i = 0; i < 8; i++) {
        long o = off + t + 256*i;
        split2h(v1[i] * i1 - v2[i] * i2, pa + o, pb + o);
    }
}

// ---------------- SwiGLU -> fp16 pairs ----------------
__global__ __launch_bounds__(256) void swiglu_kernel(const float* __restrict__ g1,
                                                     const float* __restrict__ g2,
                                                     fp16* __restrict__ ua, fp16* __restrict__ ub) {
    long i = (long)blockIdx.x * 256 + threadIdx.x;
    float a = g1[i];
    float u = a / (1.f + __expf(-a)) * g2[i];
    split2h(u, ua + i, ub + i);
}

// ---------------- launcher ----------------
extern "C" void kernel_launch(void* const* d_in, const int* in_sizes, int n_in,
                              void* d_out, int out_size) {
    (void)in_sizes; (void)n_in; (void)out_size;
    const float* x   = (const float*)d_in[0];
    const float* gn  = (const float*)d_in[1];
    const float* Wq1 = (const float*)d_in[2];
    const float* Wq2 = (const float*)d_in[3];
    const float* Wk1 = (const float*)d_in[4];
    const float* Wk2 = (const float*)d_in[5];
    const float* Wv  = (const float*)d_in[6];
    const float* lq1 = (const float*)d_in[7];
    const float* lk1 = (const float*)d_in[8];
    const float* lq2 = (const float*)d_in[9];
    const float* lk2 = (const float*)d_in[10];
    const float* Wo  = (const float*)d_in[11];
    const float* W1  = (const float*)d_in[12];
    const float* W2  = (const float*)d_in[13];
    const float* W3  = (const float*)d_in[14];
    float* out = (float*)d_out;

    const int SMEM = 4 * 3 * 10240;   // 122880
    cudaFuncSetAttribute(mma_gemm<0>, cudaFuncAttributeMaxDynamicSharedMemorySize, SMEM);
    cudaFuncSetAttribute(mma_gemm<1>, cudaFuncAttributeMaxDynamicSharedMemorySize, SMEM);
    cudaFuncSetAttribute(mma_gemm<2>, cudaFuncAttributeMaxDynamicSharedMemorySize, SMEM);

#define SYM(v, s) cudaGetSymbolAddress((void**)&v, s)
    float *h0f, *vf, *hf, *s1, *s2, *G1, *G2, *lam;
    SYM(h0f, g_h0f); SYM(vf, g_vf); SYM(hf, g_hf);
    SYM(s1, g_s1); SYM(s2, g_s2); SYM(G1, g_G1); SYM(G2, g_G2); SYM(lam, g_lam);
    fp16 *h0a,*h0b,*za,*zb,*q1a,*q1b,*q2a,*q2b,*k1,*k2,*vt,*oa,*ob,*pa,*pb,*ua,*ub;
    fp16 *fwq1,*fwq2,*fwk1,*fwk2,*fwv,*fwo,*fw1,*fw2,*fw3;
    SYM(h0a, g_h0a); SYM(h0b, g_h0b); SYM(za, g_za); SYM(zb, g_zb);
    SYM(q1a, g_q1a); SYM(q1b, g_q1b); SYM(q2a, g_q2a); SYM(q2b, g_q2b);
    SYM(k1, g_k1); SYM(k2, g_k2); SYM(vt, g_vt);
    SYM(oa, g_oa); SYM(ob, g_ob); SYM(pa, g_pa); SYM(pb, g_pb);
    SYM(ua, g_ua); SYM(ub, g_ub);
    SYM(fwq1, g_fwq1); SYM(fwq2, g_fwq2); SYM(fwk1, g_fwk1); SYM(fwk2, g_fwk2);
    SYM(fwv, g_fwv); SYM(fwo, g_fwo); SYM(fw1, g_fw1); SYM(fw2, g_fw2); SYM(fw3, g_fw3);
#undef SYM

    const long SS = (long)SEQ * SEQ;
    const float qkscale = 0.08838834764831845f; // 1/sqrt(128)

    // weight conversions -> [N,K] K-major fp16
    dim3 gtA(HDIM/32, DIM/32, NH);          // [H,D,DH] -> per-head [DH,D]
    transpose_half<<<gtA, 256>>>(Wq1, fwq1, DIM, HDIM);
    transpose_half<<<gtA, 256>>>(Wq2, fwq2, DIM, HDIM);
    transpose_half<<<gtA, 256>>>(Wk1, fwk1, DIM, HDIM);
    transpose_half<<<gtA, 256>>>(Wk2, fwk2, DIM, HDIM);
    transpose_half<<<gtA, 256>>>(Wv,  fwv,  DIM, HDIM);
    dim3 gtO(DIM/32, DIM/32, 1);
    transpose_half<<<gtO, 256>>>(Wo, fwo, DIM, DIM);
    dim3 gt1(HIDN/32, DIM/32, 1);
    transpose_half<<<gt1, 256>>>(W1, fw1, DIM, HIDN);
    transpose_half<<<gt1, 256>>>(W2, fw2, DIM, HIDN);
    dim3 gt3(DIM/32, HIDN/32, 1);
    transpose_half<<<gt3, 256>>>(W3, fw3, HIDN, DIM);

    // 1) h0 = rmsnorm(x): fp32 + fp16 pair
    rmsnorm_kernel<<<SEQ, 256>>>(x, gn, h0f, h0a, h0b);
    lambda_kernel<<<NH, 128>>>(lq1, lk1, lq2, lk2, lam);

    // 2) projections: q pair-out, k single-out, v fp32-out
    dim3 gproj(DIM/128, SEQ/128, 1);
    mma_gemm<1><<<gproj, 256, SMEM>>>(h0a, h0b, DIM, 0, fwq1, DIM, 0, nullptr, nullptr, q1a, q1b, DIM, 0, DIM, 1.f);
    mma_gemm<1><<<gproj, 256, SMEM>>>(h0a, h0b, DIM, 0, fwq2, DIM, 0, nullptr, nullptr, q2a, q2b, DIM, 0, DIM, 1.f);
    mma_gemm<2><<<gproj, 256, SMEM>>>(h0a, h0b, DIM, 0, fwk1, DIM, 0, nullptr, nullptr, k1, nullptr, DIM, 0, DIM, 1.f);
    mma_gemm<2><<<gproj, 256, SMEM>>>(h0a, h0b, DIM, 0, fwk2, DIM, 0, nullptr, nullptr, k2, nullptr, DIM, 0, DIM, 1.f);
    mma_gemm<0><<<gproj, 256, SMEM>>>(h0a, h0b, DIM, 0, fwv,  DIM, 0, vf, nullptr, nullptr, nullptr, DIM, 0, DIM, 1.f);

    // 3) V^T single fp16
    dim3 gtV(DIM/32, SEQ/32, 1);
    transpose_half<<<gtV, 256>>>(vf, vt, SEQ, DIM);

    // 4) scores
    dim3 gqk(SEQ/128, SEQ/128, NH);
    mma_gemm<0><<<gqk, 256, SMEM>>>(q1a, q1b, DIM, HDIM, k1, DIM, HDIM, s1, nullptr, nullptr, nullptr, SEQ, SS, HDIM, qkscale);
    mma_gemm<0><<<gqk, 256, SMEM>>>(q2a, q2b, DIM, HDIM, k2, DIM, HDIM, s2, nullptr, nullptr, nullptr, SEQ, SS, HDIM, qkscale);

    // 5) P = softmax(S1) - lam*softmax(S2) -> fp16 pairs
    dim3 gsm(SEQ, NH);
    softmax_combine<<<gsm, 256>>>(s1, s2, lam, pa, pb);

    // 6) O = P @ V (pair out)
    dim3 gpv(1, SEQ/128, NH);
    mma_gemm<1><<<gpv, 256, SMEM>>>(pa, pb, SEQ, SS, vt, SEQ, (long)HDIM*SEQ, nullptr, nullptr, oa, ob, DIM, HDIM, SEQ, 1.f);

    // 7) h = O @ Wo + h0
    dim3 gwo(DIM/128, SEQ/128, 1);
    mma_gemm<0><<<gwo, 256, SMEM>>>(oa, ob, DIM, 0, fwo, DIM, 0, hf, h0f, nullptr, nullptr, DIM, 0, DIM, 1.f);

    // 8) z = rmsnorm(h): fp16 pair only
    rmsnorm_kernel<<<SEQ, 256>>>(hf, gn, nullptr, za, zb);

    // 9) G1, G2
    dim3 gffn(HIDN/128, SEQ/128, 1);
    mma_gemm<0><<<gffn, 256, SMEM>>>(za, zb, DIM, 0, fw1, DIM, 0, G1, nullptr, nullptr, nullptr, HIDN, 0, DIM, 1.f);
    mma_gemm<0><<<gffn, 256, SMEM>>>(za, zb, DIM, 0, fw2, DIM, 0, G2, nullptr, nullptr, nullptr, HIDN, 0, DIM, 1.f);

    // 10) U = silu(G1)*G2 -> fp16 pairs
    swiglu_kernel<<<(SEQ * (long)HIDN) / 256, 256>>>(G1, G2, ua, ub);

    // 11) out = U @ W3 + h
    dim3 gw3(DIM/128, SEQ/128, 1);
    mma_gemm<0><<<gw3, 256, SMEM>>>(ua, ub, HIDN, 0, fw3, HIDN, 0, out, hf, nullptr, nullptr, DIM, 0, HIDN, 1.f);
}

// round 9
// speedup vs baseline: 3.2601x; 1.0901x over previous
#include <cuda_runtime.h>
#include <cuda_fp16.h>
#include <math.h>
#include <stdint.h>

#define SEQ 2048
#define DIM 2048
#define NH 16
#define HDIM 128
#define HIDN 8192
#define EPSV 1e-6f
#define LAMB0 0.8f

typedef __half fp16;

// ---------------- scratch (device globals) ----------------
__device__ float g_h0f[SEQ * DIM];
__device__ float g_vf [SEQ * DIM];
__device__ float g_hf [SEQ * DIM];
__device__ float g_s1 [(size_t)NH * SEQ * SEQ];
__device__ float g_s2 [(size_t)NH * SEQ * SEQ];
__device__ float g_G1 [(size_t)SEQ * HIDN];
__device__ float g_G2 [(size_t)SEQ * HIDN];
__device__ float g_lam[NH];

// fp16 operands
__device__ fp16 g_h0a[SEQ*DIM], g_h0b[SEQ*DIM];
__device__ fp16 g_za [SEQ*DIM], g_zb [SEQ*DIM];
__device__ fp16 g_q1a[SEQ*DIM], g_q1b[SEQ*DIM];
__device__ fp16 g_q2a[SEQ*DIM], g_q2b[SEQ*DIM];
__device__ fp16 g_k1 [SEQ*DIM], g_k2 [SEQ*DIM];
__device__ fp16 g_vt [SEQ*DIM];
__device__ fp16 g_oa [SEQ*DIM], g_ob [SEQ*DIM];
__device__ fp16 g_pa [(size_t)NH*SEQ*SEQ], g_pb [(size_t)NH*SEQ*SEQ];
__device__ fp16 g_ua [(size_t)SEQ*HIDN];
__device__ fp16 g_fwq1[DIM*DIM], g_fwq2[DIM*DIM];
__device__ fp16 g_fwk1[DIM*DIM], g_fwk2[DIM*DIM];
__device__ fp16 g_fwv [DIM*DIM], g_fwo [DIM*DIM];
__device__ fp16 g_fw1[(size_t)DIM*HIDN], g_fw2[(size_t)DIM*HIDN];
__device__ fp16 g_fw3[(size_t)DIM*HIDN];

// ---------------- helpers ----------------
__device__ __forceinline__ uint32_t smem_u32(const void* p) {
    uint32_t a;
    asm("{ .reg .u64 t; cvta.to.shared.u64 t, %1; cvt.u32.u64 %0, t; }" : "=r"(a) : "l"(p));
    return a;
}
__device__ __forceinline__ void cpa16(uint32_t s, const void* g) {
    asm volatile("cp.async.cg.shared.global [%0], [%1], 16;" :: "r"(s), "l"(g));
}
#define CP_COMMIT() asm volatile("cp.async.commit_group;")
#define CP_WAIT(n)  asm volatile("cp.async.wait_group %0;" :: "n"(n))

__device__ __forceinline__ void ldm4(uint32_t* r, uint32_t addr) {
    asm volatile("ldmatrix.sync.aligned.m8n8.x4.shared.b16 {%0,%1,%2,%3}, [%4];"
        : "=r"(r[0]), "=r"(r[1]), "=r"(r[2]), "=r"(r[3]) : "r"(addr));
}
__device__ __forceinline__ void mma_hf(float* d, const uint32_t* a, uint32_t b0, uint32_t b1) {
    asm volatile("mma.sync.aligned.m16n8k16.row.col.f32.f16.f16.f32 "
        "{%0,%1,%2,%3}, {%4,%5,%6,%7}, {%8,%9}, {%0,%1,%2,%3};"
        : "+f"(d[0]), "+f"(d[1]), "+f"(d[2]), "+f"(d[3])
        : "r"(a[0]), "r"(a[1]), "r"(a[2]), "r"(a[3]), "r"(b0), "r"(b1));
}
__device__ __forceinline__ void split2h(float v, fp16* ph, fp16* pl) {
    fp16 h = __float2half(v);
    *ph = h;
    *pl = __float2half(v - __half2float(h));
}

// FMA-pipe exp (no MUFU): exp(x) = 2^(x*log2e), exact range reduction,
// degree-5 Taylor for 2^f on [-0.5,0.5]. rel err ~2.4e-6.
__device__ __forceinline__ float fexp(float x) {
    float y = x * 1.44269504089f;
    y = fmaxf(fminf(y, 126.0f), -125.0f);
    float z = __fadd_rn(y, 12582912.0f);      // RN round-to-int in mantissa
    float n = __fsub_rn(z, 12582912.0f);
    float f = __fsub_rn(y, n);
    float p =            1.33335581e-3f;
    p = fmaf(p, f, 9.61812911e-3f);
    p = fmaf(p, f, 5.55041087e-2f);
    p = fmaf(p, f, 2.40226507e-1f);
    p = fmaf(p, f, 6.93147181e-1f);
    p = fmaf(p, f, 1.0f);
    int i = __float_as_int(z);
    float s = __int_as_float((i << 23) + 0x3F800000);
    return p * s;
}

// ---------------- fp16 mma.sync GEMM: C = alpha*A.B^T (+R) ----------------
// NA==2: A = Ah+Al pair (2 products). NA==1: A single (1 product).
// MODE 0: fp32 out (+residual if Rf). MODE 1: fp16 pair out. MODE 2: fp16 single out.
template <int MODE, int NA>
__global__ __launch_bounds__(256) void mma_gemm(
    const fp16* __restrict__ Ah, const fp16* __restrict__ Al, int lda, long sA,
    const fp16* __restrict__ B, int ldb, long sB,
    float* __restrict__ Cf, const float* __restrict__ Rf,
    fp16* __restrict__ Ch, fp16* __restrict__ Cl,
    int ldc, long sC, int K, float alpha)
{
    constexpr int RSB  = 80;               // 32 elems*2B + 8B pad
    constexpr int MATB = 128 * RSB;        // 10240
    constexpr int STG  = (NA + 1) * MATB;
    extern __shared__ __align__(128) char dsm[];
    const uint32_t sb = smem_u32(dsm);

    const int tid = threadIdx.x;
    const int m0 = blockIdx.y * 128, n0 = blockIdx.x * 128, z = blockIdx.z;

    Ah += (long)z * sA + (long)m0 * lda;
    if (NA == 2) Al += (long)z * sA + (long)m0 * lda;
    B  += (long)z * sB + (long)n0 * ldb;

    const int NC = K >> 5;   // KC = 32

    auto load_chunk = [&](int c, int s) {
        const long k0 = (long)c << 5;
        const uint32_t st = sb + (uint32_t)s * STG;
        #pragma unroll
        for (int i = 0; i < 2; i++) {
            int idx = tid + 256 * i;
            int row = idx >> 2;
            int sg  = idx & 3;
            uint32_t so = st + (uint32_t)row * RSB + (uint32_t)sg * 16;
            long ga = (long)row * lda + k0 + sg * 8;
            long gb = (long)row * ldb + k0 + sg * 8;
            cpa16(so, Ah + ga);
            if (NA == 2) cpa16(so + MATB, Al + ga);
            cpa16(so + NA*MATB, B + gb);
        }
    };

    const int l  = tid & 31;
    const int wp = tid >> 5;
    const int wm = (wp >> 2) * 64;
    const int wn = (wp & 3) * 32;
    const uint32_t aoff = (uint32_t)(wm + (l & 15)) * RSB + (uint32_t)((l >> 4) * 16);
    const uint32_t boff = (uint32_t)NA*MATB + (uint32_t)(wn + (l & 7) + ((l >> 4) << 3)) * RSB
                        + (uint32_t)(((l >> 3) & 1) * 16);

    float acc[4][4][4];
    #pragma unroll
    for (int a = 0; a < 4; a++)
        #pragma unroll
        for (int b = 0; b < 4; b++)
            #pragma unroll
            for (int c = 0; c < 4; c++) acc[a][b][c] = 0.f;

    load_chunk(0, 0); CP_COMMIT();
    load_chunk(1, 1); CP_COMMIT();
    load_chunk(2, 2); CP_COMMIT();

    for (int c = 0; c < NC; c++) {
        const int s = c & 3;
        const int rem = NC - 1 - c;
        if (rem >= 2)      { CP_WAIT(2); }
        else if (rem == 1) { CP_WAIT(1); }
        else               { CP_WAIT(0); }
        __syncthreads();
        if (c + 3 < NC) { load_chunk(c + 3, (c + 3) & 3); CP_COMMIT(); }

        const uint32_t stg = sb + (uint32_t)s * STG;
        #pragma unroll
        for (int ks = 0; ks < 2; ks++) {
            const uint32_t base = stg + (uint32_t)ks * 32;
            uint32_t ah[4][4], al[4][4], bh[2][4];
            #pragma unroll
            for (int mi = 0; mi < 4; mi++) {
                ldm4(ah[mi], base + aoff + (uint32_t)mi * (16 * RSB));
                if (NA == 2) ldm4(al[mi], base + aoff + (uint32_t)mi * (16 * RSB) + MATB);
            }
            #pragma unroll
            for (int ng = 0; ng < 2; ng++)
                ldm4(bh[ng], base + boff + (uint32_t)ng * (16 * RSB));

            #pragma unroll
            for (int mi = 0; mi < 4; mi++)
                #pragma unroll
                for (int ni = 0; ni < 4; ni++)
                    mma_hf(acc[mi][ni], ah[mi],
                           bh[ni >> 1][(ni & 1) * 2], bh[ni >> 1][(ni & 1) * 2 + 1]);
            if (NA == 2) {
                #pragma unroll
                for (int mi = 0; mi < 4; mi++)
                    #pragma unroll
                    for (int ni = 0; ni < 4; ni++)
                        mma_hf(acc[mi][ni], al[mi],
                               bh[ni >> 1][(ni & 1) * 2], bh[ni >> 1][(ni & 1) * 2 + 1]);
            }
        }
    }

    const int qr = l >> 2;
    const int qc = (l & 3) * 2;
    const long cbase = (long)z * sC + (long)m0 * ldc + n0;
    #pragma unroll
    for (int mi = 0; mi < 4; mi++)
        #pragma unroll
        for (int ni = 0; ni < 4; ni++)
            #pragma unroll
            for (int hr = 0; hr < 2; hr++) {
                long off = cbase + (long)(wm + mi * 16 + qr + hr * 8) * ldc + (wn + ni * 8 + qc);
                float v0 = acc[mi][ni][hr * 2 + 0] * alpha;
                float v1 = acc[mi][ni][hr * 2 + 1] * alpha;
                if (MODE == 0) {
                    if (Rf) { v0 += Rf[off]; v1 += Rf[off + 1]; }
                    Cf[off] = v0; Cf[off + 1] = v1;
                } else if (MODE == 1) {
                    split2h(v0, Ch + off,     Cl + off);
                    split2h(v1, Ch + off + 1, Cl + off + 1);
                } else {
                    Ch[off]     = __float2half(v0);
                    Ch[off + 1] = __float2half(v1);
                }
            }
}

// ---------------- transpose: [Z,R,C] fp32 -> [Z,C,R] fp16 ----------------
__global__ __launch_bounds__(256) void transpose_half(const float* __restrict__ in,
                                                      fp16* __restrict__ oh,
                                                      int R, int C) {
    const long zb = (long)blockIdx.z * R * C;
    in += zb; oh += zb;
    const int c0 = blockIdx.x * 32, r0 = blockIdx.y * 32;
    __shared__ float t[32][33];
    const int tx = threadIdx.x & 31, ty = threadIdx.x >> 5;
    #pragma unroll
    for (int i = 0; i < 4; i++)
        t[ty + 8*i][tx] = in[(long)(r0 + ty + 8*i) * C + c0 + tx];
    __syncthreads();
    #pragma unroll
    for (int i = 0; i < 4; i++)
        oh[(long)(c0 + ty + 8*i) * R + r0 + tx] = __float2half(t[tx][ty + 8*i]);
}

// ---------------- fused RMSNorm -> optional fp32 + fp16 pair ----------------
__global__ __launch_bounds__(256) void rmsnorm_kernel(const float* __restrict__ x,
                                                      const float* __restrict__ g,
                                                      float* __restrict__ yf,
                                                      fp16* __restrict__ ya, fp16* __restrict__ yb) {
    __shared__ float sh[8];
    const long row = blockIdx.x;
    const float* xr = x + row * (long)DIM;
    float v[8], ss = 0.f;
    #pragma unroll
    for (int i = 0; i < 8; i++) { v[i] = xr[threadIdx.x + 256*i]; ss += v[i]*v[i]; }
    #pragma unroll
    for (int o = 16; o; o >>= 1) ss += __shfl_xor_sync(0xffffffffu, ss, o);
    if ((threadIdx.x & 31) == 0) sh[threadIdx.x >> 5] = ss;
    __syncthreads();
    float tot = 0.f;
    #pragma unroll
    for (int i = 0; i < 8; i++) tot += sh[i];
    const float sc = rsqrtf(tot * (1.0f / DIM) + EPSV);
    #pragma unroll
    for (int i = 0; i < 8; i++) {
        int c = threadIdx.x + 256*i;
        float y = v[i] * sc * g[c];
        long o = row * (long)DIM + c;
        if (yf) yf[o] = y;
        split2h(y, ya + o, yb + o);
    }
}

// ---------------- lambda ----------------
__global__ void lambda_kernel(const float* __restrict__ lq1, const float* __restrict__ lk1,
                              const float* __restrict__ lq2, const float* __restrict__ lk2,
                              float* __restrict__ lam) {
    __shared__ float s1[128], s2[128];
    int h = blockIdx.x, t = threadIdx.x;
    int i = h * HDIM + t;
    s1[t] = lq1[i] * lk1[i];
    s2[t] = lq2[i] * lk2[i];
    __syncthreads();
    for (int o = 64; o; o >>= 1) {
        if (t < o) { s1[t] += s1[t+o]; s2[t] += s2[t+o]; }
        __syncthreads();
    }
    if (t == 0) lam[h] = expf(s1[0]) - expf(s2[0]) + LAMB0;
}

// ---------------- dual softmax + combine -> P fp16 pairs ----------------
__global__ __launch_bounds__(256) void softmax_combine(const float* __restrict__ s1,
                                                       const float* __restrict__ s2,
                                                       const float* __restrict__ lam,
                                                       fp16* __restrict__ pa, fp16* __restrict__ pb) {
    __shared__ float sh[8];
    const long off = (long)blockIdx.y * SEQ * SEQ + (long)blockIdx.x * SEQ;
    const float* r1 = s1 + off;
    const float* r2 = s2 + off;
    const int t = threadIdx.x;
    float v1[8], v2[8];
    #pragma unroll
    for (int i = 0; i < 8; i++) { v1[i] = r1[t + 256*i]; v2[i] = r2[t + 256*i]; }

    float mm = -1e30f;
    #pragma unroll
    for (int i = 0; i < 8; i++) { mm = fmaxf(mm, v1[i]); mm = fmaxf(mm, v2[i]); }
    #pragma unroll
    for (int o = 16; o; o >>= 1) mm = fmaxf(mm, __shfl_xor_sync(0xffffffffu, mm, o));
    if ((t & 31) == 0) sh[t >> 5] = mm;
    __syncthreads();
    float M = sh[0];
    #pragma unroll
    for (int i = 1; i < 8; i++) M = fmaxf(M, sh[i]);
    __syncthreads();

    float p1 = 0.f, p2 = 0.f;
    #pragma unroll
    for (int i = 0; i < 8; i++) {
        v1[i] = fexp(v1[i] - M); p1 += v1[i];
        v2[i] = fexp(v2[i] - M); p2 += v2[i];
    }
    #pragma unroll
    for (int o = 16; o; o >>= 1) {
        p1 += __shfl_xor_sync(0xffffffffu, p1, o);
        p2 += __shfl_xor_sync(0xffffffffu, p2, o);
    }
    __shared__ float sx[8], sy[8];
    if ((t & 31) == 0) { sx[t >> 5] = p1; sy[t >> 5] = p2; }
    __syncthreads();
    float S1 = 0.f, S2 = 0.f;
    #pragma unroll
    for (int i = 0; i < 8; i++) { S1 += sx[i]; S2 += sy[i]; }

    const float i1 = 1.f / S1;
    const float i2 = lam[blockIdx.y] / S2;
    #pragma unroll
    for (int i = 0; i < 8; i++) {
        long o = off + t + 256*i;
        split2h(v1[i] * i1 - v2[i] * i2, pa + o, pb + o);
    }
}

// ---------------- SwiGLU -> single fp16 ----------------
__global__ __launch_bounds__(256) void swiglu_kernel(const float* __restrict__ g1,
                                                     const float* __restrict__ g2,
                                                     fp16* __restrict__ ua) {
    long i = (long)blockIdx.x * 256 + threadIdx.x;
    float a = g1[i];
    float u = a / (1.f + fexp(-a)) * g2[i];
    ua[i] = __float2half(u);
}

// ---------------- launcher ----------------
extern "C" void kernel_launch(void* const* d_in, const int* in_sizes, int n_in,
                              void* d_out, int out_size) {
    (void)in_sizes; (void)n_in; (void)out_size;
    const float* x   = (const float*)d_in[0];
    const float* gn  = (const float*)d_in[1];
    const float* Wq1 = (const float*)d_in[2];
    const float* Wq2 = (const float*)d_in[3];
    const float* Wk1 = (const float*)d_in[4];
    const float* Wk2 = (const float*)d_in[5];
    const float* Wv  = (const float*)d_in[6];
    const float* lq1 = (const float*)d_in[7];
    const float* lk1 = (const float*)d_in[8];
    const float* lq2 = (const float*)d_in[9];
    const float* lk2 = (const float*)d_in[10];
    const float* Wo  = (const float*)d_in[11];
    const float* W1  = (const float*)d_in[12];
    const float* W2  = (const float*)d_in[13];
    const float* W3  = (const float*)d_in[14];
    float* out = (float*)d_out;

    const int SMEM2 = 4 * 3 * 10240;   // 122880 (A pair + B)
    const int SMEM1 = 4 * 2 * 10240;   // 81920  (A single + B)
    cudaFuncSetAttribute(mma_gemm<0,2>, cudaFuncAttributeMaxDynamicSharedMemorySize, SMEM2);
    cudaFuncSetAttribute(mma_gemm<1,2>, cudaFuncAttributeMaxDynamicSharedMemorySize, SMEM2);
    cudaFuncSetAttribute(mma_gemm<2,2>, cudaFuncAttributeMaxDynamicSharedMemorySize, SMEM2);
    cudaFuncSetAttribute(mma_gemm<0,1>, cudaFuncAttributeMaxDynamicSharedMemorySize, SMEM1);

#define SYM(v, s) cudaGetSymbolAddress((void**)&v, s)
    float *h0f, *vf, *hf, *s1, *s2, *G1, *G2, *lam;
    SYM(h0f, g_h0f); SYM(vf, g_vf); SYM(hf, g_hf);
    SYM(s1, g_s1); SYM(s2, g_s2); SYM(G1, g_G1); SYM(G2, g_G2); SYM(lam, g_lam);
    fp16 *h0a,*h0b,*za,*zb,*q1a,*q1b,*q2a,*q2b,*k1,*k2,*vt,*oa,*ob,*pa,*pb,*ua;
    fp16 *fwq1,*fwq2,*fwk1,*fwk2,*fwv,*fwo,*fw1,*fw2,*fw3;
    SYM(h0a, g_h0a); SYM(h0b, g_h0b); SYM(za, g_za); SYM(zb, g_zb);
    SYM(q1a, g_q1a); SYM(q1b, g_q1b); SYM(q2a, g_q2a); SYM(q2b, g_q2b);
    SYM(k1, g_k1); SYM(k2, g_k2); SYM(vt, g_vt);
    SYM(oa, g_oa); SYM(ob, g_ob); SYM(pa, g_pa); SYM(pb, g_pb);
    SYM(ua, g_ua);
    SYM(fwq1, g_fwq1); SYM(fwq2, g_fwq2); SYM(fwk1, g_fwk1); SYM(fwk2, g_fwk2);
    SYM(fwv, g_fwv); SYM(fwo, g_fwo); SYM(fw1, g_fw1); SYM(fw2, g_fw2); SYM(fw3, g_fw3);
#undef SYM

    const long SS = (long)SEQ * SEQ;
    const float qkscale = 0.08838834764831845f; // 1/sqrt(128)

    // weight conversions -> [N,K] K-major fp16
    dim3 gtA(HDIM/32, DIM/32, NH);          // [H,D,DH] -> per-head [DH,D]
    transpose_half<<<gtA, 256>>>(Wq1, fwq1, DIM, HDIM);
    transpose_half<<<gtA, 256>>>(Wq2, fwq2, DIM, HDIM);
    transpose_half<<<gtA, 256>>>(Wk1, fwk1, DIM, HDIM);
    transpose_half<<<gtA, 256>>>(Wk2, fwk2, DIM, HDIM);
    transpose_half<<<gtA, 256>>>(Wv,  fwv,  DIM, HDIM);
    dim3 gtO(DIM/32, DIM/32, 1);
    transpose_half<<<gtO, 256>>>(Wo, fwo, DIM, DIM);
    dim3 gt1(HIDN/32, DIM/32, 1);
    transpose_half<<<gt1, 256>>>(W1, fw1, DIM, HIDN);
    transpose_half<<<gt1, 256>>>(W2, fw2, DIM, HIDN);
    dim3 gt3(DIM/32, HIDN/32, 1);
    transpose_half<<<gt3, 256>>>(W3, fw3, HIDN, DIM);

    // 1) h0 = rmsnorm(x): fp32 + fp16 pair
    rmsnorm_kernel<<<SEQ, 256>>>(x, gn, h0f, h0a, h0b);
    lambda_kernel<<<NH, 128>>>(lq1, lk1, lq2, lk2, lam);

    // 2) projections: q pair-out, k single-out, v fp32-out
    dim3 gproj(DIM/128, SEQ/128, 1);
    mma_gemm<1,2><<<gproj, 256, SMEM2>>>(h0a, h0b, DIM, 0, fwq1, DIM, 0, nullptr, nullptr, q1a, q1b, DIM, 0, DIM, 1.f);
    mma_gemm<1,2><<<gproj, 256, SMEM2>>>(h0a, h0b, DIM, 0, fwq2, DIM, 0, nullptr, nullptr, q2a, q2b, DIM, 0, DIM, 1.f);
    mma_gemm<2,2><<<gproj, 256, SMEM2>>>(h0a, h0b, DIM, 0, fwk1, DIM, 0, nullptr, nullptr, k1, nullptr, DIM, 0, DIM, 1.f);
    mma_gemm<2,2><<<gproj, 256, SMEM2>>>(h0a, h0b, DIM, 0, fwk2, DIM, 0, nullptr, nullptr, k2, nullptr, DIM, 0, DIM, 1.f);
    mma_gemm<0,2><<<gproj, 256, SMEM2>>>(h0a, h0b, DIM, 0, fwv,  DIM, 0, vf, nullptr, nullptr, nullptr, DIM, 0, DIM, 1.f);

    // 3) V^T single fp16
    dim3 gtV(DIM/32, SEQ/32, 1);
    transpose_half<<<gtV, 256>>>(vf, vt, SEQ, DIM);

    // 4) scores
    dim3 gqk(SEQ/128, SEQ/128, NH);
    mma_gemm<0,2><<<gqk, 256, SMEM2>>>(q1a, q1b, DIM, HDIM, k1, DIM, HDIM, s1, nullptr, nullptr, nullptr, SEQ, SS, HDIM, qkscale);
    mma_gemm<0,2><<<gqk, 256, SMEM2>>>(q2a, q2b, DIM, HDIM, k2, DIM, HDIM, s2, nullptr, nullptr, nullptr, SEQ, SS, HDIM, qkscale);

    // 5) P = softmax(S1) - lam*softmax(S2) -> fp16 pairs (FMA exp)
    dim3 gsm(SEQ, NH);
    softmax_combine<<<gsm, 256>>>(s1, s2, lam, pa, pb);

    // 6) O = P @ V (pair out)
    dim3 gpv(1, SEQ/128, NH);
    mma_gemm<1,2><<<gpv, 256, SMEM2>>>(pa, pb, SEQ, SS, vt, SEQ, (long)HDIM*SEQ, nullptr, nullptr, oa, ob, DIM, HDIM, SEQ, 1.f);

    // 7) h = O @ Wo + h0
    dim3 gwo(DIM/128, SEQ/128, 1);
    mma_gemm<0,2><<<gwo, 256, SMEM2>>>(oa, ob, DIM, 0, fwo, DIM, 0, hf, h0f, nullptr, nullptr, DIM, 0, DIM, 1.f);

    // 8) z = rmsnorm(h): fp16 pair only
    rmsnorm_kernel<<<SEQ, 256>>>(hf, gn, nullptr, za, zb);

    // 9) G1, G2
    dim3 gffn(HIDN/128, SEQ/128, 1);
    mma_gemm<0,2><<<gffn, 256, SMEM2>>>(za, zb, DIM, 0, fw1, DIM, 0, G1, nullptr, nullptr, nullptr, HIDN, 0, DIM, 1.f);
    mma_gemm<0,2><<<gffn, 256, SMEM2>>>(za, zb, DIM, 0, fw2, DIM, 0, G2, nullptr, nullptr, nullptr, HIDN, 0, DIM, 1.f);

    // 10) U = silu(G1)*G2 -> single fp16 (FMA exp)
    swiglu_kernel<<<(SEQ * (long)HIDN) / 256, 256>>>(G1, G2, ua);

    // 11) out = U @ W3 + h  (1-product: U single precision)
    dim3 gw3(DIM/128, SEQ/128, 1);
    mma_gemm<0,1><<<gw3, 256, SMEM1>>>(ua, nullptr, HIDN, 0, fw3, HIDN, 0, out, hf, nullptr, nullptr, DIM, 0, HIDN, 1.f);
}

// round 10
// speedup vs baseline: 5.4108x; 1.6597x over previous
#include <cuda_runtime.h>
#include <cuda_fp16.h>
#include <math.h>
#include <stdint.h>

#define SEQ 2048
#define DIM 2048
#define NH 16
#define HDIM 128
#define HIDN 8192
#define EPSV 1e-6f
#define LAMB0 0.8f

typedef __half fp16;

// ---------------- scratch (device globals) ----------------
__device__ float g_h0f[SEQ * DIM];
__device__ float g_vf [SEQ * DIM];
__device__ float g_hf [SEQ * DIM];
__device__ float g_s1 [(size_t)NH * SEQ * SEQ];
__device__ float g_s2 [(size_t)NH * SEQ * SEQ];
__device__ float g_G1 [(size_t)SEQ * HIDN];
__device__ float g_lam[NH];

// fp16 operands (all single precision now)
__device__ fp16 g_h0a[SEQ*DIM];
__device__ fp16 g_za [SEQ*DIM];
__device__ fp16 g_q1a[SEQ*DIM], g_q2a[SEQ*DIM];
__device__ fp16 g_k1 [SEQ*DIM], g_k2 [SEQ*DIM];
__device__ fp16 g_vt [SEQ*DIM];
__device__ fp16 g_oa [SEQ*DIM];
__device__ fp16 g_pa [(size_t)NH*SEQ*SEQ];
__device__ fp16 g_ua [(size_t)SEQ*HIDN];
__device__ fp16 g_fwq1[DIM*DIM], g_fwq2[DIM*DIM];
__device__ fp16 g_fwk1[DIM*DIM], g_fwk2[DIM*DIM];
__device__ fp16 g_fwv [DIM*DIM], g_fwo [DIM*DIM];
__device__ fp16 g_fw1[(size_t)DIM*HIDN], g_fw2[(size_t)DIM*HIDN];
__device__ fp16 g_fw3[(size_t)DIM*HIDN];

// ---------------- helpers ----------------
__device__ __forceinline__ uint32_t smem_u32(const void* p) {
    uint32_t a;
    asm("{ .reg .u64 t; cvta.to.shared.u64 t, %1; cvt.u32.u64 %0, t; }" : "=r"(a) : "l"(p));
    return a;
}
__device__ __forceinline__ void cpa16(uint32_t s, const void* g) {
    asm volatile("cp.async.cg.shared.global [%0], [%1], 16;" :: "r"(s), "l"(g));
}
#define CP_COMMIT() asm volatile("cp.async.commit_group;")
#define CP_WAIT(n)  asm volatile("cp.async.wait_group %0;" :: "n"(n))

__device__ __forceinline__ void ldm4(uint32_t* r, uint32_t addr) {
    asm volatile("ldmatrix.sync.aligned.m8n8.x4.shared.b16 {%0,%1,%2,%3}, [%4];"
        : "=r"(r[0]), "=r"(r[1]), "=r"(r[2]), "=r"(r[3]) : "r"(addr));
}
__device__ __forceinline__ void mma_hf(float* d, const uint32_t* a, uint32_t b0, uint32_t b1) {
    asm volatile("mma.sync.aligned.m16n8k16.row.col.f32.f16.f16.f32 "
        "{%0,%1,%2,%3}, {%4,%5,%6,%7}, {%8,%9}, {%0,%1,%2,%3};"
        : "+f"(d[0]), "+f"(d[1]), "+f"(d[2]), "+f"(d[3])
        : "r"(a[0]), "r"(a[1]), "r"(a[2]), "r"(a[3]), "r"(b0), "r"(b1));
}

// FMA-pipe exp: exp(x) = 2^(x*log2e), exact range reduction, deg-5 poly.
__device__ __forceinline__ float fexp(float x) {
    float y = x * 1.44269504089f;
    y = fmaxf(fminf(y, 126.0f), -125.0f);
    float z = __fadd_rn(y, 12582912.0f);
    float n = __fsub_rn(z, 12582912.0f);
    float f = __fsub_rn(y, n);
    float p =            1.33335581e-3f;
    p = fmaf(p, f, 9.61812911e-3f);
    p = fmaf(p, f, 5.55041087e-2f);
    p = fmaf(p, f, 2.40226507e-1f);
    p = fmaf(p, f, 6.93147181e-1f);
    p = fmaf(p, f, 1.0f);
    int i = __float_as_int(z);
    float s = __int_as_float((i << 23) + 0x3F800000);
    return p * s;
}

// ---------------- fp16 1-product mma.sync GEMM: C = alpha*A.B^T ----------------
// MODE 0: fp32 out (+residual if Rf).
// MODE 2: fp16 out.
// MODE 3: fp16 out = silu(Rf) * acc   (fused SwiGLU epilogue)
template <int MODE>
__global__ __launch_bounds__(256) void mma_gemm(
    const fp16* __restrict__ Ah, int lda, long sA,
    const fp16* __restrict__ B, int ldb, long sB,
    float* __restrict__ Cf, const float* __restrict__ Rf,
    fp16* __restrict__ Ch,
    int ldc, long sC, int K, float alpha)
{
    constexpr int RSB  = 80;               // 32 elems*2B + 8B pad
    constexpr int MATB = 128 * RSB;        // 10240
    constexpr int STG  = 2 * MATB;         // A, B
    extern __shared__ __align__(128) char dsm[];
    const uint32_t sb = smem_u32(dsm);

    const int tid = threadIdx.x;
    const int m0 = blockIdx.y * 128, n0 = blockIdx.x * 128, z = blockIdx.z;

    Ah += (long)z * sA + (long)m0 * lda;
    B  += (long)z * sB + (long)n0 * ldb;

    const int NC = K >> 5;   // KC = 32

    auto load_chunk = [&](int c, int s) {
        const long k0 = (long)c << 5;
        const uint32_t st = sb + (uint32_t)s * STG;
        #pragma unroll
        for (int i = 0; i < 2; i++) {
            int idx = tid + 256 * i;
            int row = idx >> 2;
            int sg  = idx & 3;
            uint32_t so = st + (uint32_t)row * RSB + (uint32_t)sg * 16;
            cpa16(so,        Ah + (long)row * lda + k0 + sg * 8);
            cpa16(so + MATB, B  + (long)row * ldb + k0 + sg * 8);
        }
    };

    const int l  = tid & 31;
    const int wp = tid >> 5;
    const int wm = (wp >> 2) * 64;
    const int wn = (wp & 3) * 32;
    const uint32_t aoff = (uint32_t)(wm + (l & 15)) * RSB + (uint32_t)((l >> 4) * 16);
    const uint32_t boff = (uint32_t)MATB + (uint32_t)(wn + (l & 7) + ((l >> 4) << 3)) * RSB
                        + (uint32_t)(((l >> 3) & 1) * 16);

    float acc[4][4][4];
    #pragma unroll
    for (int a = 0; a < 4; a++)
        #pragma unroll
        for (int b = 0; b < 4; b++)
            #pragma unroll
            for (int c = 0; c < 4; c++) acc[a][b][c] = 0.f;

    load_chunk(0, 0); CP_COMMIT();
    load_chunk(1, 1); CP_COMMIT();
    load_chunk(2, 2); CP_COMMIT();

    for (int c = 0; c < NC; c++) {
        const int s = c & 3;
        const int rem = NC - 1 - c;
        if (rem >= 2)      { CP_WAIT(2); }
        else if (rem == 1) { CP_WAIT(1); }
        else               { CP_WAIT(0); }
        __syncthreads();
        if (c + 3 < NC) { load_chunk(c + 3, (c + 3) & 3); CP_COMMIT(); }

        const uint32_t stg = sb + (uint32_t)s * STG;
        #pragma unroll
        for (int ks = 0; ks < 2; ks++) {
            const uint32_t base = stg + (uint32_t)ks * 32;
            uint32_t ah[4][4], bh[2][4];
            #pragma unroll
            for (int mi = 0; mi < 4; mi++)
                ldm4(ah[mi], base + aoff + (uint32_t)mi * (16 * RSB));
            #pragma unroll
            for (int ng = 0; ng < 2; ng++)
                ldm4(bh[ng], base + boff + (uint32_t)ng * (16 * RSB));

            #pragma unroll
            for (int mi = 0; mi < 4; mi++)
                #pragma unroll
                for (int ni = 0; ni < 4; ni++)
                    mma_hf(acc[mi][ni], ah[mi],
                           bh[ni >> 1][(ni & 1) * 2], bh[ni >> 1][(ni & 1) * 2 + 1]);
        }
    }

    const int qr = l >> 2;
    const int qc = (l & 3) * 2;
    const long cbase = (long)z * sC + (long)m0 * ldc + n0;
    #pragma unroll
    for (int mi = 0; mi < 4; mi++)
        #pragma unroll
        for (int ni = 0; ni < 4; ni++)
            #pragma unroll
            for (int hr = 0; hr < 2; hr++) {
                long off = cbase + (long)(wm + mi * 16 + qr + hr * 8) * ldc + (wn + ni * 8 + qc);
                float v0 = acc[mi][ni][hr * 2 + 0] * alpha;
                float v1 = acc[mi][ni][hr * 2 + 1] * alpha;
                if (MODE == 0) {
                    if (Rf) { v0 += Rf[off]; v1 += Rf[off + 1]; }
                    Cf[off] = v0; Cf[off + 1] = v1;
                } else if (MODE == 2) {
                    Ch[off]     = __float2half(v0);
                    Ch[off + 1] = __float2half(v1);
                } else {
                    float a0 = Rf[off],     s0 = a0 / (1.f + fexp(-a0));
                    float a1 = Rf[off + 1], s1 = a1 / (1.f + fexp(-a1));
                    Ch[off]     = __float2half(s0 * v0);
                    Ch[off + 1] = __float2half(s1 * v1);
                }
            }
}

// ---------------- transpose: [Z,R,C] fp32 -> [Z,C,R] fp16 ----------------
__global__ __launch_bounds__(256) void transpose_half(const float* __restrict__ in,
                                                      fp16* __restrict__ oh,
                                                      int R, int C) {
    const long zb = (long)blockIdx.z * R * C;
    in += zb; oh += zb;
    const int c0 = blockIdx.x * 32, r0 = blockIdx.y * 32;
    __shared__ float t[32][33];
    const int tx = threadIdx.x & 31, ty = threadIdx.x >> 5;
    #pragma unroll
    for (int i = 0; i < 4; i++)
        t[ty + 8*i][tx] = in[(long)(r0 + ty + 8*i) * C + c0 + tx];
    __syncthreads();
    #pragma unroll
    for (int i = 0; i < 4; i++)
        oh[(long)(c0 + ty + 8*i) * R + r0 + tx] = __float2half(t[tx][ty + 8*i]);
}

// ---------------- fused RMSNorm -> optional fp32 + fp16 single ----------------
__global__ __launch_bounds__(256) void rmsnorm_kernel(const float* __restrict__ x,
                                                      const float* __restrict__ g,
                                                      float* __restrict__ yf,
                                                      fp16* __restrict__ ya) {
    __shared__ float sh[8];
    const long row = blockIdx.x;
    const float* xr = x + row * (long)DIM;
    float v[8], ss = 0.f;
    #pragma unroll
    for (int i = 0; i < 8; i++) { v[i] = xr[threadIdx.x + 256*i]; ss += v[i]*v[i]; }
    #pragma unroll
    for (int o = 16; o; o >>= 1) ss += __shfl_xor_sync(0xffffffffu, ss, o);
    if ((threadIdx.x & 31) == 0) sh[threadIdx.x >> 5] = ss;
    __syncthreads();
    float tot = 0.f;
    #pragma unroll
    for (int i = 0; i < 8; i++) tot += sh[i];
    const float sc = rsqrtf(tot * (1.0f / DIM) + EPSV);
    #pragma unroll
    for (int i = 0; i < 8; i++) {
        int c = threadIdx.x + 256*i;
        float y = v[i] * sc * g[c];
        long o = row * (long)DIM + c;
        if (yf) yf[o] = y;
        ya[o] = __float2half(y);
    }
}

// ---------------- lambda ----------------
__global__ void lambda_kernel(const float* __restrict__ lq1, const float* __restrict__ lk1,
                              const float* __restrict__ lq2, const float* __restrict__ lk2,
                              float* __restrict__ lam) {
    __shared__ float s1[128], s2[128];
    int h = blockIdx.x, t = threadIdx.x;
    int i = h * HDIM + t;
    s1[t] = lq1[i] * lk1[i];
    s2[t] = lq2[i] * lk2[i];
    __syncthreads();
    for (int o = 64; o; o >>= 1) {
        if (t < o) { s1[t] += s1[t+o]; s2[t] += s2[t+o]; }
        __syncthreads();
    }
    if (t == 0) lam[h] = expf(s1[0]) - expf(s2[0]) + LAMB0;
}

// ---------------- dual softmax + combine -> P fp16 single ----------------
__global__ __launch_bounds__(256) void softmax_combine(const float* __restrict__ s1,
                                                       const float* __restrict__ s2,
                                                       const float* __restrict__ lam,
                                                       fp16* __restrict__ pa) {
    __shared__ float sh[8];
    const long off = (long)blockIdx.y * SEQ * SEQ + (long)blockIdx.x * SEQ;
    const float* r1 = s1 + off;
    const float* r2 = s2 + off;
    const int t = threadIdx.x;
    float v1[8], v2[8];
    #pragma unroll
    for (int i = 0; i < 8; i++) { v1[i] = r1[t + 256*i]; v2[i] = r2[t + 256*i]; }

    float mm = -1e30f;
    #pragma unroll
    for (int i = 0; i < 8; i++) { mm = fmaxf(mm, v1[i]); mm = fmaxf(mm, v2[i]); }
    #pragma unroll
    for (int o = 16; o; o >>= 1) mm = fmaxf(mm, __shfl_xor_sync(0xffffffffu, mm, o));
    if ((t & 31) == 0) sh[t >> 5] = mm;
    __syncthreads();
    float M = sh[0];
    #pragma unroll
    for (int i = 1; i < 8; i++) M = fmaxf(M, sh[i]);
    __syncthreads();

    float p1 = 0.f, p2 = 0.f;
    #pragma unroll
    for (int i = 0; i < 8; i++) {
        v1[i] = fexp(v1[i] - M); p1 += v1[i];
        v2[i] = fexp(v2[i] - M); p2 += v2[i];
    }
    #pragma unroll
    for (int o = 16; o; o >>= 1) {
        p1 += __shfl_xor_sync(0xffffffffu, p1, o);
        p2 += __shfl_xor_sync(0xffffffffu, p2, o);
    }
    __shared__ float sx[8], sy[8];
    if ((t & 31) == 0) { sx[t >> 5] = p1; sy[t >> 5] = p2; }
    __syncthreads();
    float S1 = 0.f, S2 = 0.f;
    #pragma unroll
    for (int i = 0; i < 8; i++) { S1 += sx[i]; S2 += sy[i]; }

    const float i1 = 1.f / S1;
    const float i2 = lam[blockIdx.y] / S2;
    #pragma unroll
    for (int i = 0; i < 8; i++) {
        long o = off + t + 256*i;
        pa[o] = __float2half(v1[i] * i1 - v2[i] * i2);
    }
}

// ---------------- launcher ----------------
extern "C" void kernel_launch(void* const* d_in, const int* in_sizes, int n_in,
                              void* d_out, int out_size) {
    (void)in_sizes; (void)n_in; (void)out_size;
    const float* x   = (const float*)d_in[0];
    const float* gn  = (const float*)d_in[1];
    const float* Wq1 = (const float*)d_in[2];
    const float* Wq2 = (const float*)d_in[3];
    const float* Wk1 = (const float*)d_in[4];
    const float* Wk2 = (const float*)d_in[5];
    const float* Wv  = (const float*)d_in[6];
    const float* lq1 = (const float*)d_in[7];
    const float* lk1 = (const float*)d_in[8];
    const float* lq2 = (const float*)d_in[9];
    const float* lk2 = (const float*)d_in[10];
    const float* Wo  = (const float*)d_in[11];
    const float* W1  = (const float*)d_in[12];
    const float* W2  = (const float*)d_in[13];
    const float* W3  = (const float*)d_in[14];
    float* out = (float*)d_out;

    const int SMEM = 4 * 2 * 10240;   // 81920
    cudaFuncSetAttribute(mma_gemm<0>, cudaFuncAttributeMaxDynamicSharedMemorySize, SMEM);
    cudaFuncSetAttribute(mma_gemm<2>, cudaFuncAttributeMaxDynamicSharedMemorySize, SMEM);
    cudaFuncSetAttribute(mma_gemm<3>, cudaFuncAttributeMaxDynamicSharedMemorySize, SMEM);

#define SYM(v, s) cudaGetSymbolAddress((void**)&v, s)
    float *h0f, *vf, *hf, *s1, *s2, *G1, *lam;
    SYM(h0f, g_h0f); SYM(vf, g_vf); SYM(hf, g_hf);
    SYM(s1, g_s1); SYM(s2, g_s2); SYM(G1, g_G1); SYM(lam, g_lam);
    fp16 *h0a,*za,*q1a,*q2a,*k1,*k2,*vt,*oa,*pa,*ua;
    fp16 *fwq1,*fwq2,*fwk1,*fwk2,*fwv,*fwo,*fw1,*fw2,*fw3;
    SYM(h0a, g_h0a); SYM(za, g_za);
    SYM(q1a, g_q1a); SYM(q2a, g_q2a);
    SYM(k1, g_k1); SYM(k2, g_k2); SYM(vt, g_vt);
    SYM(oa, g_oa); SYM(pa, g_pa); SYM(ua, g_ua);
    SYM(fwq1, g_fwq1); SYM(fwq2, g_fwq2); SYM(fwk1, g_fwk1); SYM(fwk2, g_fwk2);
    SYM(fwv, g_fwv); SYM(fwo, g_fwo); SYM(fw1, g_fw1); SYM(fw2, g_fw2); SYM(fw3, g_fw3);
#undef SYM

    const long SS = (long)SEQ * SEQ;
    const float qkscale = 0.08838834764831845f; // 1/sqrt(128)

    // weight conversions -> [N,K] K-major fp16
    dim3 gtA(HDIM/32, DIM/32, NH);          // [H,D,DH] -> per-head [DH,D]
    transpose_half<<<gtA, 256>>>(Wq1, fwq1, DIM, HDIM);
    transpose_half<<<gtA, 256>>>(Wq2, fwq2, DIM, HDIM);
    transpose_half<<<gtA, 256>>>(Wk1, fwk1, DIM, HDIM);
    transpose_half<<<gtA, 256>>>(Wk2, fwk2, DIM, HDIM);
    transpose_half<<<gtA, 256>>>(Wv,  fwv,  DIM, HDIM);
    dim3 gtO(DIM/32, DIM/32, 1);
    transpose_half<<<gtO, 256>>>(Wo, fwo, DIM, DIM);
    dim3 gt1(HIDN/32, DIM/32, 1);
    transpose_half<<<gt1, 256>>>(W1, fw1, DIM, HIDN);
    transpose_half<<<gt1, 256>>>(W2, fw2, DIM, HIDN);
    dim3 gt3(DIM/32, HIDN/32, 1);
    transpose_half<<<gt3, 256>>>(W3, fw3, HIDN, DIM);

    // 1) h0 = rmsnorm(x): fp32 + fp16
    rmsnorm_kernel<<<SEQ, 256>>>(x, gn, h0f, h0a);
    lambda_kernel<<<NH, 128>>>(lq1, lk1, lq2, lk2, lam);

    // 2) projections (all fp16 out except v -> fp32 for transpose)
    dim3 gproj(DIM/128, SEQ/128, 1);
    mma_gemm<2><<<gproj, 256, SMEM>>>(h0a, DIM, 0, fwq1, DIM, 0, nullptr, nullptr, q1a, DIM, 0, DIM, 1.f);
    mma_gemm<2><<<gproj, 256, SMEM>>>(h0a, DIM, 0, fwq2, DIM, 0, nullptr, nullptr, q2a, DIM, 0, DIM, 1.f);
    mma_gemm<2><<<gproj, 256, SMEM>>>(h0a, DIM, 0, fwk1, DIM, 0, nullptr, nullptr, k1, DIM, 0, DIM, 1.f);
    mma_gemm<2><<<gproj, 256, SMEM>>>(h0a, DIM, 0, fwk2, DIM, 0, nullptr, nullptr, k2, DIM, 0, DIM, 1.f);
    mma_gemm<0><<<gproj, 256, SMEM>>>(h0a, DIM, 0, fwv,  DIM, 0, vf, nullptr, nullptr, DIM, 0, DIM, 1.f);

    // 3) V^T fp16
    dim3 gtV(DIM/32, SEQ/32, 1);
    transpose_half<<<gtV, 256>>>(vf, vt, SEQ, DIM);

    // 4) scores (fp32 out)
    dim3 gqk(SEQ/128, SEQ/128, NH);
    mma_gemm<0><<<gqk, 256, SMEM>>>(q1a, DIM, HDIM, k1, DIM, HDIM, s1, nullptr, nullptr, SEQ, SS, HDIM, qkscale);
    mma_gemm<0><<<gqk, 256, SMEM>>>(q2a, DIM, HDIM, k2, DIM, HDIM, s2, nullptr, nullptr, SEQ, SS, HDIM, qkscale);

    // 5) P = softmax(S1) - lam*softmax(S2) -> fp16
    dim3 gsm(SEQ, NH);
    softmax_combine<<<gsm, 256>>>(s1, s2, lam, pa);

    // 6) O = P @ V -> fp16
    dim3 gpv(1, SEQ/128, NH);
    mma_gemm<2><<<gpv, 256, SMEM>>>(pa, SEQ, SS, vt, SEQ, (long)HDIM*SEQ, nullptr, nullptr, oa, DIM, HDIM, SEQ, 1.f);

    // 7) h = O @ Wo + h0 (fp32)
    dim3 gwo(DIM/128, SEQ/128, 1);
    mma_gemm<0><<<gwo, 256, SMEM>>>(oa, DIM, 0, fwo, DIM, 0, hf, h0f, nullptr, DIM, 0, DIM, 1.f);

    // 8) z = rmsnorm(h) -> fp16 only
    rmsnorm_kernel<<<SEQ, 256>>>(hf, gn, nullptr, za);

    // 9) G1 fp32; G2 fused with SwiGLU -> ua fp16
    dim3 gffn(HIDN/128, SEQ/128, 1);
    mma_gemm<0><<<gffn, 256, SMEM>>>(za, DIM, 0, fw1, DIM, 0, G1, nullptr, nullptr, HIDN, 0, DIM, 1.f);
    mma_gemm<3><<<gffn, 256, SMEM>>>(za, DIM, 0, fw2, DIM, 0, nullptr, G1, ua, HIDN, 0, DIM, 1.f);

    // 10) out = U @ W3 + h
    dim3 gw3(DIM/128, SEQ/128, 1);
    mma_gemm<0><<<gw3, 256, SMEM>>>(ua, HIDN, 0, fw3, HIDN, 0, out, hf, nullptr, DIM, 0, HIDN, 1.f);
}

// round 11
// speedup vs baseline: 5.8065x; 1.0731x over previous
#include <cuda_runtime.h>
#include <cuda_fp16.h>
#include <math.h>
#include <stdint.h>

#define SEQ 2048
#define DIM 2048
#define NH 16
#define HDIM 128
#define HIDN 8192
#define EPSV 1e-6f
#define LAMB0 0.8f

typedef __half fp16;

// ---------------- scratch ----------------
__device__ float g_h0f[SEQ * DIM];
__device__ float g_vf [SEQ * DIM];
__device__ float g_hf [SEQ * DIM];
__device__ float g_G1 [(size_t)SEQ * HIDN];
__device__ float g_lam[NH];

__device__ fp16 g_h0a[SEQ*DIM];
__device__ fp16 g_za [SEQ*DIM];
__device__ fp16 g_q1a[SEQ*DIM], g_q2a[SEQ*DIM];
__device__ fp16 g_k1 [SEQ*DIM], g_k2 [SEQ*DIM];
__device__ fp16 g_vt [SEQ*DIM];
__device__ fp16 g_oa [SEQ*DIM];
__device__ fp16 g_ua [(size_t)SEQ*HIDN];
__device__ fp16 g_fwq1[DIM*DIM], g_fwq2[DIM*DIM];
__device__ fp16 g_fwk1[DIM*DIM], g_fwk2[DIM*DIM];
__device__ fp16 g_fwv [DIM*DIM], g_fwo [DIM*DIM];
__device__ fp16 g_fw1[(size_t)DIM*HIDN], g_fw2[(size_t)DIM*HIDN];
__device__ fp16 g_fw3[(size_t)DIM*HIDN];

// ---------------- helpers ----------------
__device__ __forceinline__ uint32_t smem_u32(const void* p) {
    uint32_t a;
    asm("{ .reg .u64 t; cvta.to.shared.u64 t, %1; cvt.u32.u64 %0, t; }" : "=r"(a) : "l"(p));
    return a;
}
__device__ __forceinline__ void cpa16(uint32_t s, const void* g) {
    asm volatile("cp.async.cg.shared.global [%0], [%1], 16;" :: "r"(s), "l"(g));
}
#define CP_COMMIT() asm volatile("cp.async.commit_group;")
#define CP_WAIT(n)  asm volatile("cp.async.wait_group %0;" :: "n"(n))

__device__ __forceinline__ void ldm4(uint32_t* r, uint32_t addr) {
    asm volatile("ldmatrix.sync.aligned.m8n8.x4.shared.b16 {%0,%1,%2,%3}, [%4];"
        : "=r"(r[0]), "=r"(r[1]), "=r"(r[2]), "=r"(r[3]) : "r"(addr));
}
__device__ __forceinline__ void mma_hf(float* d, const uint32_t* a, uint32_t b0, uint32_t b1) {
    asm volatile("mma.sync.aligned.m16n8k16.row.col.f32.f16.f16.f32 "
        "{%0,%1,%2,%3}, {%4,%5,%6,%7}, {%8,%9}, {%0,%1,%2,%3};"
        : "+f"(d[0]), "+f"(d[1]), "+f"(d[2]), "+f"(d[3])
        : "r"(a[0]), "r"(a[1]), "r"(a[2]), "r"(a[3]), "r"(b0), "r"(b1));
}

// FMA-pipe exp
__device__ __forceinline__ float fexp(float x) {
    float y = x * 1.44269504089f;
    y = fmaxf(fminf(y, 126.0f), -125.0f);
    float z = __fadd_rn(y, 12582912.0f);
    float n = __fsub_rn(z, 12582912.0f);
    float f = __fsub_rn(y, n);
    float p =            1.33335581e-3f;
    p = fmaf(p, f, 9.61812911e-3f);
    p = fmaf(p, f, 5.55041087e-2f);
    p = fmaf(p, f, 2.40226507e-1f);
    p = fmaf(p, f, 6.93147181e-1f);
    p = fmaf(p, f, 1.0f);
    int i = __float_as_int(z);
    float s = __int_as_float((i << 23) + 0x3F800000);
    return p * s;
}

// ---------------- fp16 1-product GEMM (unchanged engine) ----------------
// MODE 0: fp32 (+residual). MODE 2: fp16. MODE 3: fp16 = silu(Rf)*acc.
template <int MODE>
__global__ __launch_bounds__(256) void mma_gemm(
    const fp16* __restrict__ Ah, int lda, long sA,
    const fp16* __restrict__ B, int ldb, long sB,
    float* __restrict__ Cf, const float* __restrict__ Rf,
    fp16* __restrict__ Ch,
    int ldc, long sC, int K, float alpha)
{
    constexpr int RSB  = 80;
    constexpr int MATB = 128 * RSB;
    constexpr int STG  = 2 * MATB;
    extern __shared__ __align__(128) char dsm[];
    const uint32_t sb = smem_u32(dsm);

    const int tid = threadIdx.x;
    const int m0 = blockIdx.y * 128, n0 = blockIdx.x * 128, z = blockIdx.z;

    Ah += (long)z * sA + (long)m0 * lda;
    B  += (long)z * sB + (long)n0 * ldb;

    const int NC = K >> 5;

    auto load_chunk = [&](int c, int s) {
        const long k0 = (long)c << 5;
        const uint32_t st = sb + (uint32_t)s * STG;
        #pragma unroll
        for (int i = 0; i < 2; i++) {
            int idx = tid + 256 * i;
            int row = idx >> 2;
            int sg  = idx & 3;
            uint32_t so = st + (uint32_t)row * RSB + (uint32_t)sg * 16;
            cpa16(so,        Ah + (long)row * lda + k0 + sg * 8);
            cpa16(so + MATB, B  + (long)row * ldb + k0 + sg * 8);
        }
    };

    const int l  = tid & 31;
    const int wp = tid >> 5;
    const int wm = (wp >> 2) * 64;
    const int wn = (wp & 3) * 32;
    const uint32_t aoff = (uint32_t)(wm + (l & 15)) * RSB + (uint32_t)((l >> 4) * 16);
    const uint32_t boff = (uint32_t)MATB + (uint32_t)(wn + (l & 7) + ((l >> 4) << 3)) * RSB
                        + (uint32_t)(((l >> 3) & 1) * 16);

    float acc[4][4][4];
    #pragma unroll
    for (int a = 0; a < 4; a++)
        #pragma unroll
        for (int b = 0; b < 4; b++)
            #pragma unroll
            for (int c = 0; c < 4; c++) acc[a][b][c] = 0.f;

    load_chunk(0, 0); CP_COMMIT();
    load_chunk(1, 1); CP_COMMIT();
    load_chunk(2, 2); CP_COMMIT();

    for (int c = 0; c < NC; c++) {
        const int s = c & 3;
        const int rem = NC - 1 - c;
        if (rem >= 2)      { CP_WAIT(2); }
        else if (rem == 1) { CP_WAIT(1); }
        else               { CP_WAIT(0); }
        __syncthreads();
        if (c + 3 < NC) { load_chunk(c + 3, (c + 3) & 3); CP_COMMIT(); }

        const uint32_t stg = sb + (uint32_t)s * STG;
        #pragma unroll
        for (int ks = 0; ks < 2; ks++) {
            const uint32_t base = stg + (uint32_t)ks * 32;
            uint32_t ah[4][4], bh[2][4];
            #pragma unroll
            for (int mi = 0; mi < 4; mi++)
                ldm4(ah[mi], base + aoff + (uint32_t)mi * (16 * RSB));
            #pragma unroll
            for (int ng = 0; ng < 2; ng++)
                ldm4(bh[ng], base + boff + (uint32_t)ng * (16 * RSB));
            #pragma unroll
            for (int mi = 0; mi < 4; mi++)
                #pragma unroll
                for (int ni = 0; ni < 4; ni++)
                    mma_hf(acc[mi][ni], ah[mi],
                           bh[ni >> 1][(ni & 1) * 2], bh[ni >> 1][(ni & 1) * 2 + 1]);
        }
    }

    const int qr = l >> 2;
    const int qc = (l & 3) * 2;
    const long cbase = (long)z * sC + (long)m0 * ldc + n0;
    #pragma unroll
    for (int mi = 0; mi < 4; mi++)
        #pragma unroll
        for (int ni = 0; ni < 4; ni++)
            #pragma unroll
            for (int hr = 0; hr < 2; hr++) {
                long off = cbase + (long)(wm + mi * 16 + qr + hr * 8) * ldc + (wn + ni * 8 + qc);
                float v0 = acc[mi][ni][hr * 2 + 0] * alpha;
                float v1 = acc[mi][ni][hr * 2 + 1] * alpha;
                if (MODE == 0) {
                    if (Rf) { v0 += Rf[off]; v1 += Rf[off + 1]; }
                    Cf[off] = v0; Cf[off + 1] = v1;
                } else if (MODE == 2) {
                    Ch[off]     = __float2half(v0);
                    Ch[off + 1] = __float2half(v1);
                } else {
                    float a0 = Rf[off],     s0 = a0 / (1.f + fexp(-a0));
                    float a1 = Rf[off + 1], s1 = a1 / (1.f + fexp(-a1));
                    Ch[off]     = __float2half(s0 * v0);
                    Ch[off + 1] = __float2half(s1 * v1);
                }
            }
}

// ---------------- fused differential flash attention ----------------
// grid (SEQ/128, NH), 256 threads. Q1/Q2 resident; K1/K2/V streamed in 64-row
// tiles, 2-stage. Dual online softmax; out = O1/l1 - lam*O2/l2 (fp16).
struct FlashState { float m[2], l[2]; };

__device__ __forceinline__ void flash_branch(
    uint32_t qbase, int axor, int alo,
    uint32_t kst, uint32_t vst, int bn, int bko,
    FlashState& st, float O[16][4], float qksc)
{
    // Q A-frags (K=128 -> 8 k16 steps)
    uint32_t qa[8][4];
    #pragma unroll
    for (int t = 0; t < 8; t++)
        ldm4(qa[t], qbase + (uint32_t)(((2*t + alo) ^ axor) << 4));

    // S = Q.K^T  (16 q-rows x 64 k-cols per warp)
    float sa[8][4];
    #pragma unroll
    for (int i = 0; i < 8; i++)
        #pragma unroll
        for (int e = 0; e < 4; e++) sa[i][e] = 0.f;
    const int bxor = bn & 7;
    #pragma unroll
    for (int ng = 0; ng < 4; ng++) {
        const uint32_t krow = kst + (uint32_t)(ng*16 + bn) * 256;
        #pragma unroll
        for (int t = 0; t < 8; t++) {
            uint32_t bf[4];
            ldm4(bf, krow + (uint32_t)(((2*t + bko) ^ bxor) << 4));
            mma_hf(sa[2*ng],   qa[t], bf[0], bf[1]);
            mma_hf(sa[2*ng+1], qa[t], bf[2], bf[3]);
        }
    }

    // scale + row max
    float rm0 = -1e30f, rm1 = -1e30f;
    #pragma unroll
    for (int i = 0; i < 8; i++) {
        #pragma unroll
        for (int e = 0; e < 4; e++) sa[i][e] *= qksc;
        rm0 = fmaxf(rm0, fmaxf(sa[i][0], sa[i][1]));
        rm1 = fmaxf(rm1, fmaxf(sa[i][2], sa[i][3]));
    }
    rm0 = fmaxf(rm0, __shfl_xor_sync(0xffffffffu, rm0, 1));
    rm0 = fmaxf(rm0, __shfl_xor_sync(0xffffffffu, rm0, 2));
    rm1 = fmaxf(rm1, __shfl_xor_sync(0xffffffffu, rm1, 1));
    rm1 = fmaxf(rm1, __shfl_xor_sync(0xffffffffu, rm1, 2));

    const float mn0 = fmaxf(st.m[0], rm0), mn1 = fmaxf(st.m[1], rm1);
    const float c0 = fexp(st.m[0] - mn0), c1 = fexp(st.m[1] - mn1);
    #pragma unroll
    for (int d = 0; d < 16; d++) {
        O[d][0] *= c0; O[d][1] *= c0;
        O[d][2] *= c1; O[d][3] *= c1;
    }
    float ps0 = 0.f, ps1 = 0.f;
    #pragma unroll
    for (int i = 0; i < 8; i++) {
        sa[i][0] = fexp(sa[i][0] - mn0); ps0 += sa[i][0];
        sa[i][1] = fexp(sa[i][1] - mn0); ps0 += sa[i][1];
        sa[i][2] = fexp(sa[i][2] - mn1); ps1 += sa[i][2];
        sa[i][3] = fexp(sa[i][3] - mn1); ps1 += sa[i][3];
    }
    ps0 += __shfl_xor_sync(0xffffffffu, ps0, 1);
    ps0 += __shfl_xor_sync(0xffffffffu, ps0, 2);
    ps1 += __shfl_xor_sync(0xffffffffu, ps1, 1);
    ps1 += __shfl_xor_sync(0xffffffffu, ps1, 2);
    st.l[0] = st.l[0] * c0 + ps0;  st.m[0] = mn0;
    st.l[1] = st.l[1] * c1 + ps1;  st.m[1] = mn1;

    // pack P -> A-frags (K = 64 -> 4 k16 steps)
    uint32_t pf[4][4];
    #pragma unroll
    for (int t = 0; t < 4; t++) {
        __half2 h0 = __floats2half2_rn(sa[2*t][0],   sa[2*t][1]);
        __half2 h1 = __floats2half2_rn(sa[2*t][2],   sa[2*t][3]);
        __half2 h2 = __floats2half2_rn(sa[2*t+1][0], sa[2*t+1][1]);
        __half2 h3 = __floats2half2_rn(sa[2*t+1][2], sa[2*t+1][3]);
        pf[t][0] = *(uint32_t*)&h0; pf[t][1] = *(uint32_t*)&h1;
        pf[t][2] = *(uint32_t*)&h2; pf[t][3] = *(uint32_t*)&h3;
    }

    // O += P.V   (V smem: [128 dh rows][64 kseq cols], 128B rows)
    #pragma unroll
    for (int dg = 0; dg < 8; dg++) {
        const uint32_t vrow = vst + (uint32_t)(dg*16 + bn) * 128;
        #pragma unroll
        for (int t = 0; t < 4; t++) {
            uint32_t bf[4];
            ldm4(bf, vrow + (uint32_t)(((2*t + bko) ^ bxor) << 4));
            mma_hf(O[2*dg],   pf[t], bf[0], bf[1]);
            mma_hf(O[2*dg+1], pf[t], bf[2], bf[3]);
        }
    }
}

__global__ __launch_bounds__(256, 1) void flash_diff(
    const fp16* __restrict__ q1, const fp16* __restrict__ q2,
    const fp16* __restrict__ k1g, const fp16* __restrict__ k2g,
    const fp16* __restrict__ vtg, const float* __restrict__ lam,
    fp16* __restrict__ oa)
{
    extern __shared__ __align__(128) char dsm[];
    const uint32_t sb = smem_u32(dsm);
    const int tid = threadIdx.x;
    const int l = tid & 31, w = tid >> 5;
    const int m0 = blockIdx.x * 128;
    const int h  = blockIdx.y;

    // ---- Q tiles (swizzled, resident) ----
    {
        const fp16* gq1 = q1 + (long)m0 * DIM + h * HDIM;
        const fp16* gq2 = q2 + (long)m0 * DIM + h * HDIM;
        #pragma unroll
        for (int i = 0; i < 8; i++) {
            int idx = tid + i * 256;
            int row = idx >> 4, j = idx & 15;
            uint32_t so = (uint32_t)row * 256 + (uint32_t)((j ^ (row & 7)) << 4);
            cpa16(sb + so,         gq1 + (long)row * DIM + j * 8);
            cpa16(sb + 32768 + so, gq2 + (long)row * DIM + j * 8);
        }
    }

    auto load_stage = [&](int kt, int s) {
        const uint32_t st = sb + 65536 + (uint32_t)s * 49152;
        const int kb = kt * 64;
        const fp16* gk1 = k1g + (long)kb * DIM + h * HDIM;
        const fp16* gk2 = k2g + (long)kb * DIM + h * HDIM;
        #pragma unroll
        for (int i = 0; i < 4; i++) {
            int idx = tid + i * 256;
            int row = idx >> 4, j = idx & 15;
            uint32_t so = (uint32_t)row * 256 + (uint32_t)((j ^ (row & 7)) << 4);
            cpa16(st + so,         gk1 + (long)row * DIM + j * 8);
            cpa16(st + 16384 + so, gk2 + (long)row * DIM + j * 8);
        }
        const fp16* gv = vtg + (long)(h * HDIM) * SEQ + kb;
        #pragma unroll
        for (int i = 0; i < 4; i++) {
            int idx = tid + i * 256;
            int row = idx >> 3, j = idx & 7;
            cpa16(st + 32768 + (uint32_t)row * 128 + (uint32_t)((j ^ (row & 7)) << 4),
                  gv + (long)row * SEQ + j * 8);
        }
    };
    load_stage(0, 0); CP_COMMIT();     // G0: Q + stage0
    load_stage(1, 1); CP_COMMIT();     // G1: stage1

    const int arow = w * 16 + (l & 15);
    const int axor = arow & 7;
    const int alo  = l >> 4;
    const uint32_t aQ1 = sb + (uint32_t)arow * 256;
    const uint32_t aQ2 = sb + 32768 + (uint32_t)arow * 256;
    const int bn  = (l & 7) + ((l >> 4) << 3);
    const int bko = (l >> 3) & 1;

    FlashState s1; s1.m[0] = s1.m[1] = -1e30f; s1.l[0] = s1.l[1] = 0.f;
    FlashState s2; s2.m[0] = s2.m[1] = -1e30f; s2.l[0] = s2.l[1] = 0.f;
    float O1[16][4], O2[16][4];
    #pragma unroll
    for (int d = 0; d < 16; d++)
        #pragma unroll
        for (int e = 0; e < 4; e++) { O1[d][e] = 0.f; O2[d][e] = 0.f; }

    const float qksc = 0.08838834764831845f;

    #pragma unroll 1
    for (int kt = 0; kt < 32; kt++) {
        CP_WAIT(1);
        __syncthreads();
        const uint32_t st = sb + 65536 + (uint32_t)(kt & 1) * 49152;
        flash_branch(aQ1, axor, alo, st,         st + 32768, bn, bko, s1, O1, qksc);
        flash_branch(aQ2, axor, alo, st + 16384, st + 32768, bn, bko, s2, O2, qksc);
        __syncthreads();
        if (kt + 2 < 32) load_stage(kt + 2, kt & 1);
        CP_COMMIT();
    }

    // combine + write
    const float lamh = lam[h];
    const float i10 = 1.f / s1.l[0], i11 = 1.f / s1.l[1];
    const float i20 = lamh / s2.l[0], i21 = lamh / s2.l[1];
    const int r0 = m0 + w * 16 + (l >> 2);
    #pragma unroll
    for (int d = 0; d < 16; d++) {
        const int col = h * HDIM + d * 8 + 2 * (l & 3);
        float a0 = O1[d][0] * i10 - O2[d][0] * i20;
        float a1 = O1[d][1] * i10 - O2[d][1] * i20;
        float a2 = O1[d][2] * i11 - O2[d][2] * i21;
        float a3 = O1[d][3] * i11 - O2[d][3] * i21;
        __half2 p0 = __floats2half2_rn(a0, a1);
        __half2 p1 = __floats2half2_rn(a2, a3);
        *(uint32_t*)&oa[(long)r0 * DIM + col]       = *(uint32_t*)&p0;
        *(uint32_t*)&oa[(long)(r0 + 8) * DIM + col] = *(uint32_t*)&p1;
    }
}

// ---------------- transpose: [Z,R,C] fp32 -> [Z,C,R] fp16 ----------------
__global__ __launch_bounds__(256) void transpose_half(const float* __restrict__ in,
                                                      fp16* __restrict__ oh,
                                                      int R, int C) {
    const long zb = (long)blockIdx.z * R * C;
    in += zb; oh += zb;
    const int c0 = blockIdx.x * 32, r0 = blockIdx.y * 32;
    __shared__ float t[32][33];
    const int tx = threadIdx.x & 31, ty = threadIdx.x >> 5;
    #pragma unroll
    for (int i = 0; i < 4; i++)
        t[ty + 8*i][tx] = in[(long)(r0 + ty + 8*i) * C + c0 + tx];
    __syncthreads();
    #pragma unroll
    for (int i = 0; i < 4; i++)
        oh[(long)(c0 + ty + 8*i) * R + r0 + tx] = __float2half(t[tx][ty + 8*i]);
}

// ---------------- RMSNorm ----------------
__global__ __launch_bounds__(256) void rmsnorm_kernel(const float* __restrict__ x,
                                                      const float* __restrict__ g,
                                                      float* __restrict__ yf,
                                                      fp16* __restrict__ ya) {
    __shared__ float sh[8];
    const long row = blockIdx.x;
    const float* xr = x + row * (long)DIM;
    float v[8], ss = 0.f;
    #pragma unroll
    for (int i = 0; i < 8; i++) { v[i] = xr[threadIdx.x + 256*i]; ss += v[i]*v[i]; }
    #pragma unroll
    for (int o = 16; o; o >>= 1) ss += __shfl_xor_sync(0xffffffffu, ss, o);
    if ((threadIdx.x & 31) == 0) sh[threadIdx.x >> 5] = ss;
    __syncthreads();
    float tot = 0.f;
    #pragma unroll
    for (int i = 0; i < 8; i++) tot += sh[i];
    const float sc = rsqrtf(tot * (1.0f / DIM) + EPSV);
    #pragma unroll
    for (int i = 0; i < 8; i++) {
        int c = threadIdx.x + 256*i;
        float y = v[i] * sc * g[c];
        long o = row * (long)DIM + c;
        if (yf) yf[o] = y;
        ya[o] = __float2half(y);
    }
}

// ---------------- lambda ----------------
__global__ void lambda_kernel(const float* __restrict__ lq1, const float* __restrict__ lk1,
                              const float* __restrict__ lq2, const float* __restrict__ lk2,
                              float* __restrict__ lam) {
    __shared__ float s1[128], s2[128];
    int h = blockIdx.x, t = threadIdx.x;
    int i = h * HDIM + t;
    s1[t] = lq1[i] * lk1[i];
    s2[t] = lq2[i] * lk2[i];
    __syncthreads();
    for (int o = 64; o; o >>= 1) {
        if (t < o) { s1[t] += s1[t+o]; s2[t] += s2[t+o]; }
        __syncthreads();
    }
    if (t == 0) lam[h] = expf(s1[0]) - expf(s2[0]) + LAMB0;
}

// ---------------- launcher ----------------
extern "C" void kernel_launch(void* const* d_in, const int* in_sizes, int n_in,
                              void* d_out, int out_size) {
    (void)in_sizes; (void)n_in; (void)out_size;
    const float* x   = (const float*)d_in[0];
    const float* gn  = (const float*)d_in[1];
    const float* Wq1 = (const float*)d_in[2];
    const float* Wq2 = (const float*)d_in[3];
    const float* Wk1 = (const float*)d_in[4];
    const float* Wk2 = (const float*)d_in[5];
    const float* Wv  = (const float*)d_in[6];
    const float* lq1 = (const float*)d_in[7];
    const float* lk1 = (const float*)d_in[8];
    const float* lq2 = (const float*)d_in[9];
    const float* lk2 = (const float*)d_in[10];
    const float* Wo  = (const float*)d_in[11];
    const float* W1  = (const float*)d_in[12];
    const float* W2  = (const float*)d_in[13];
    const float* W3  = (const float*)d_in[14];
    float* out = (float*)d_out;

    const int SMEM  = 4 * 2 * 10240;   // 81920 (GEMM)
    const int FSMEM = 65536 + 2 * 49152; // 163840 (flash)
    cudaFuncSetAttribute(mma_gemm<0>, cudaFuncAttributeMaxDynamicSharedMemorySize, SMEM);
    cudaFuncSetAttribute(mma_gemm<2>, cudaFuncAttributeMaxDynamicSharedMemorySize, SMEM);
    cudaFuncSetAttribute(mma_gemm<3>, cudaFuncAttributeMaxDynamicSharedMemorySize, SMEM);
    cudaFuncSetAttribute(flash_diff,  cudaFuncAttributeMaxDynamicSharedMemorySize, FSMEM);

#define SYM(v, s) cudaGetSymbolAddress((void**)&v, s)
    float *h0f, *vf, *hf, *G1, *lam;
    SYM(h0f, g_h0f); SYM(vf, g_vf); SYM(hf, g_hf); SYM(G1, g_G1); SYM(lam, g_lam);
    fp16 *h0a,*za,*q1a,*q2a,*k1,*k2,*vt,*oa,*ua;
    fp16 *fwq1,*fwq2,*fwk1,*fwk2,*fwv,*fwo,*fw1,*fw2,*fw3;
    SYM(h0a, g_h0a); SYM(za, g_za);
    SYM(q1a, g_q1a); SYM(q2a, g_q2a);
    SYM(k1, g_k1); SYM(k2, g_k2); SYM(vt, g_vt);
    SYM(oa, g_oa); SYM(ua, g_ua);
    SYM(fwq1, g_fwq1); SYM(fwq2, g_fwq2); SYM(fwk1, g_fwk1); SYM(fwk2, g_fwk2);
    SYM(fwv, g_fwv); SYM(fwo, g_fwo); SYM(fw1, g_fw1); SYM(fw2, g_fw2); SYM(fw3, g_fw3);
#undef SYM

    // weight conversions -> [N,K] K-major fp16
    dim3 gtA(HDIM/32, DIM/32, NH);
    transpose_half<<<gtA, 256>>>(Wq1, fwq1, DIM, HDIM);
    transpose_half<<<gtA, 256>>>(Wq2, fwq2, DIM, HDIM);
    transpose_half<<<gtA, 256>>>(Wk1, fwk1, DIM, HDIM);
    transpose_half<<<gtA, 256>>>(Wk2, fwk2, DIM, HDIM);
    transpose_half<<<gtA, 256>>>(Wv,  fwv,  DIM, HDIM);
    dim3 gtO(DIM/32, DIM/32, 1);
    transpose_half<<<gtO, 256>>>(Wo, fwo, DIM, DIM);
    dim3 gt1(HIDN/32, DIM/32, 1);
    transpose_half<<<gt1, 256>>>(W1, fw1, DIM, HIDN);
    transpose_half<<<gt1, 256>>>(W2, fw2, DIM, HIDN);
    dim3 gt3(DIM/32, HIDN/32, 1);
    transpose_half<<<gt3, 256>>>(W3, fw3, HIDN, DIM);

    // 1) h0 = rmsnorm(x)
    rmsnorm_kernel<<<SEQ, 256>>>(x, gn, h0f, h0a);
    lambda_kernel<<<NH, 128>>>(lq1, lk1, lq2, lk2, lam);

    // 2) projections
    dim3 gproj(DIM/128, SEQ/128, 1);
    mma_gemm<2><<<gproj, 256, SMEM>>>(h0a, DIM, 0, fwq1, DIM, 0, nullptr, nullptr, q1a, DIM, 0, DIM, 1.f);
    mma_gemm<2><<<gproj, 256, SMEM>>>(h0a, DIM, 0, fwq2, DIM, 0, nullptr, nullptr, q2a, DIM, 0, DIM, 1.f);
    mma_gemm<2><<<gproj, 256, SMEM>>>(h0a, DIM, 0, fwk1, DIM, 0, nullptr, nullptr, k1, DIM, 0, DIM, 1.f);
    mma_gemm<2><<<gproj, 256, SMEM>>>(h0a, DIM, 0, fwk2, DIM, 0, nullptr, nullptr, k2, DIM, 0, DIM, 1.f);
    mma_gemm<0><<<gproj, 256, SMEM>>>(h0a, DIM, 0, fwv,  DIM, 0, vf, nullptr, nullptr, DIM, 0, DIM, 1.f);

    // 3) V^T fp16
    dim3 gtV(DIM/32, SEQ/32, 1);
    transpose_half<<<gtV, 256>>>(vf, vt, SEQ, DIM);

    // 4-6) fused differential flash attention -> oa
    dim3 gfl(SEQ/128, NH);
    flash_diff<<<gfl, 256, FSMEM>>>(q1a, q2a, k1, k2, vt, lam, oa);

    // 7) h = O @ Wo + h0
    dim3 gwo(DIM/128, SEQ/128, 1);
    mma_gemm<0><<<gwo, 256, SMEM>>>(oa, DIM, 0, fwo, DIM, 0, hf, h0f, nullptr, DIM, 0, DIM, 1.f);

    // 8) z = rmsnorm(h)
    rmsnorm_kernel<<<SEQ, 256>>>(hf, gn, nullptr, za);

    // 9) G1; G2 fused with SwiGLU -> ua
    dim3 gffn(HIDN/128, SEQ/128, 1);
    mma_gemm<0><<<gffn, 256, SMEM>>>(za, DIM, 0, fw1, DIM, 0, G1, nullptr, nullptr, HIDN, 0, DIM, 1.f);
    mma_gemm<3><<<gffn, 256, SMEM>>>(za, DIM, 0, fw2, DIM, 0, nullptr, G1, ua, HIDN, 0, DIM, 1.f);

    // 10) out = U @ W3 + h
    dim3 gw3(DIM/128, SEQ/128, 1);
    mma_gemm<0><<<gw3, 256, SMEM>>>(ua, HIDN, 0, fw3, HIDN, 0, out, hf, nullptr, DIM, 0, HIDN, 1.f);
}

// round 12
// speedup vs baseline: 5.8463x; 1.0068x over previous
#include <cuda_runtime.h>
#include <cuda_fp16.h>
#include <math.h>
#include <stdint.h>

#define SEQ 2048
#define DIM 2048
#define NH 16
#define HDIM 128
#define HIDN 8192
#define EPSV 1e-6f
#define LAMB0 0.8f

typedef __half fp16;

// ---------------- scratch ----------------
__device__ float g_h0f[SEQ * DIM];
__device__ float g_hf [SEQ * DIM];
__device__ float g_lam[NH];

__device__ fp16 g_h0a[SEQ*DIM];
__device__ fp16 g_za [SEQ*DIM];
__device__ fp16 g_q1a[SEQ*DIM], g_q2a[SEQ*DIM];
__device__ fp16 g_k1 [SEQ*DIM], g_k2 [SEQ*DIM];
__device__ fp16 g_vr [SEQ*DIM];                 // V row-major fp16
__device__ fp16 g_vt [SEQ*DIM];                 // V^T fp16
__device__ fp16 g_oa [SEQ*DIM];
__device__ fp16 g_g1h[(size_t)SEQ*HIDN];
__device__ fp16 g_ua [(size_t)SEQ*HIDN];
__device__ fp16 g_fwq1[DIM*DIM], g_fwq2[DIM*DIM];
__device__ fp16 g_fwk1[DIM*DIM], g_fwk2[DIM*DIM];
__device__ fp16 g_fwv [DIM*DIM], g_fwo [DIM*DIM];
__device__ fp16 g_fw1[(size_t)DIM*HIDN], g_fw2[(size_t)DIM*HIDN];
__device__ fp16 g_fw3[(size_t)DIM*HIDN];

// ---------------- helpers ----------------
__device__ __forceinline__ uint32_t smem_u32(const void* p) {
    uint32_t a;
    asm("{ .reg .u64 t; cvta.to.shared.u64 t, %1; cvt.u32.u64 %0, t; }" : "=r"(a) : "l"(p));
    return a;
}
__device__ __forceinline__ void cpa16(uint32_t s, const void* g) {
    asm volatile("cp.async.cg.shared.global [%0], [%1], 16;" :: "r"(s), "l"(g));
}
#define CP_COMMIT() asm volatile("cp.async.commit_group;")
#define CP_WAIT(n)  asm volatile("cp.async.wait_group %0;" :: "n"(n))

__device__ __forceinline__ void ldm4(uint32_t* r, uint32_t addr) {
    asm volatile("ldmatrix.sync.aligned.m8n8.x4.shared.b16 {%0,%1,%2,%3}, [%4];"
        : "=r"(r[0]), "=r"(r[1]), "=r"(r[2]), "=r"(r[3]) : "r"(addr));
}
__device__ __forceinline__ void mma_hf(float* d, const uint32_t* a, uint32_t b0, uint32_t b1) {
    asm volatile("mma.sync.aligned.m16n8k16.row.col.f32.f16.f16.f32 "
        "{%0,%1,%2,%3}, {%4,%5,%6,%7}, {%8,%9}, {%0,%1,%2,%3};"
        : "+f"(d[0]), "+f"(d[1]), "+f"(d[2]), "+f"(d[3])
        : "r"(a[0]), "r"(a[1]), "r"(a[2]), "r"(a[3]), "r"(b0), "r"(b1));
}

// FMA-pipe exp
__device__ __forceinline__ float fexp(float x) {
    float y = x * 1.44269504089f;
    y = fmaxf(fminf(y, 126.0f), -125.0f);
    float z = __fadd_rn(y, 12582912.0f);
    float n = __fsub_rn(z, 12582912.0f);
    float f = __fsub_rn(y, n);
    float p =            1.33335581e-3f;
    p = fmaf(p, f, 9.61812911e-3f);
    p = fmaf(p, f, 5.55041087e-2f);
    p = fmaf(p, f, 2.40226507e-1f);
    p = fmaf(p, f, 6.93147181e-1f);
    p = fmaf(p, f, 1.0f);
    int i = __float_as_int(z);
    float s = __int_as_float((i << 23) + 0x3F800000);
    return p * s;
}

// ---------------- fp16 1-product GEMM ----------------
// MODE 0: fp32 (+residual Rf). MODE 2: fp16. MODE 3: fp16 = silu(Rh)*acc (Rh fp16).
template <int MODE>
__global__ __launch_bounds__(256, 2) void mma_gemm(
    const fp16* __restrict__ Ah, int lda, long sA,
    const fp16* __restrict__ B, int ldb, long sB,
    float* __restrict__ Cf, const float* __restrict__ Rf, const fp16* __restrict__ Rh,
    fp16* __restrict__ Ch,
    int ldc, long sC, int K, float alpha)
{
    constexpr int RSB  = 80;
    constexpr int MATB = 128 * RSB;
    constexpr int STG  = 2 * MATB;
    extern __shared__ __align__(128) char dsm[];
    const uint32_t sb = smem_u32(dsm);

    const int tid = threadIdx.x;
    const int m0 = blockIdx.y * 128, n0 = blockIdx.x * 128, z = blockIdx.z;

    Ah += (long)z * sA + (long)m0 * lda;
    B  += (long)z * sB + (long)n0 * ldb;

    const int NC = K >> 5;

    auto load_chunk = [&](int c, int s) {
        const long k0 = (long)c << 5;
        const uint32_t st = sb + (uint32_t)s * STG;
        #pragma unroll
        for (int i = 0; i < 2; i++) {
            int idx = tid + 256 * i;
            int row = idx >> 2;
            int sg  = idx & 3;
            uint32_t so = st + (uint32_t)row * RSB + (uint32_t)sg * 16;
            cpa16(so,        Ah + (long)row * lda + k0 + sg * 8);
            cpa16(so + MATB, B  + (long)row * ldb + k0 + sg * 8);
        }
    };

    const int l  = tid & 31;
    const int wp = tid >> 5;
    const int wm = (wp >> 2) * 64;
    const int wn = (wp & 3) * 32;
    const uint32_t aoff = (uint32_t)(wm + (l & 15)) * RSB + (uint32_t)((l >> 4) * 16);
    const uint32_t boff = (uint32_t)MATB + (uint32_t)(wn + (l & 7) + ((l >> 4) << 3)) * RSB
                        + (uint32_t)(((l >> 3) & 1) * 16);

    float acc[4][4][4];
    #pragma unroll
    for (int a = 0; a < 4; a++)
        #pragma unroll
        for (int b = 0; b < 4; b++)
            #pragma unroll
            for (int c = 0; c < 4; c++) acc[a][b][c] = 0.f;

    load_chunk(0, 0); CP_COMMIT();
    load_chunk(1, 1); CP_COMMIT();
    load_chunk(2, 2); CP_COMMIT();

    for (int c = 0; c < NC; c++) {
        const int s = c & 3;
        const int rem = NC - 1 - c;
        if (rem >= 2)      { CP_WAIT(2); }
        else if (rem == 1) { CP_WAIT(1); }
        else               { CP_WAIT(0); }
        __syncthreads();
        if (c + 3 < NC) { load_chunk(c + 3, (c + 3) & 3); CP_COMMIT(); }

        const uint32_t stg = sb + (uint32_t)s * STG;
        #pragma unroll
        for (int ks = 0; ks < 2; ks++) {
            const uint32_t base = stg + (uint32_t)ks * 32;
            uint32_t ah[4][4], bh[2][4];
            #pragma unroll
            for (int mi = 0; mi < 4; mi++)
                ldm4(ah[mi], base + aoff + (uint32_t)mi * (16 * RSB));
            #pragma unroll
            for (int ng = 0; ng < 2; ng++)
                ldm4(bh[ng], base + boff + (uint32_t)ng * (16 * RSB));
            #pragma unroll
            for (int mi = 0; mi < 4; mi++)
                #pragma unroll
                for (int ni = 0; ni < 4; ni++)
                    mma_hf(acc[mi][ni], ah[mi],
                           bh[ni >> 1][(ni & 1) * 2], bh[ni >> 1][(ni & 1) * 2 + 1]);
        }
    }

    const int qr = l >> 2;
    const int qc = (l & 3) * 2;
    const long cbase = (long)z * sC + (long)m0 * ldc + n0;
    #pragma unroll
    for (int mi = 0; mi < 4; mi++)
        #pragma unroll
        for (int ni = 0; ni < 4; ni++)
            #pragma unroll
            for (int hr = 0; hr < 2; hr++) {
                long off = cbase + (long)(wm + mi * 16 + qr + hr * 8) * ldc + (wn + ni * 8 + qc);
                float v0 = acc[mi][ni][hr * 2 + 0] * alpha;
                float v1 = acc[mi][ni][hr * 2 + 1] * alpha;
                if (MODE == 0) {
                    if (Rf) { v0 += Rf[off]; v1 += Rf[off + 1]; }
                    Cf[off] = v0; Cf[off + 1] = v1;
                } else if (MODE == 2) {
                    Ch[off]     = __float2half(v0);
                    Ch[off + 1] = __float2half(v1);
                } else {
                    float a0 = __half2float(Rh[off]),     s0 = a0 / (1.f + fexp(-a0));
                    float a1 = __half2float(Rh[off + 1]), s1 = a1 / (1.f + fexp(-a1));
                    Ch[off]     = __float2half(s0 * v0);
                    Ch[off + 1] = __float2half(s1 * v1);
                }
            }
}

// ---------------- fused differential flash attention ----------------
struct FlashState { float m[2], l[2]; };

// compute S for one branch -> pf frags + state/O rescale
__device__ __forceinline__ void flash_score(
    uint32_t qbase, int axor, int alo,
    uint32_t kst, int bn, int bko,
    FlashState& st, float O[16][4], uint32_t pf[4][4], float qksc)
{
    uint32_t qa[8][4];
    #pragma unroll
    for (int t = 0; t < 8; t++)
        ldm4(qa[t], qbase + (uint32_t)(((2*t + alo) ^ axor) << 4));

    float sa[8][4];
    #pragma unroll
    for (int i = 0; i < 8; i++)
        #pragma unroll
        for (int e = 0; e < 4; e++) sa[i][e] = 0.f;
    const int bxor = bn & 7;
    #pragma unroll
    for (int ng = 0; ng < 4; ng++) {
        const uint32_t krow = kst + (uint32_t)(ng*16 + bn) * 256;
        #pragma unroll
        for (int t = 0; t < 8; t++) {
            uint32_t bf[4];
            ldm4(bf, krow + (uint32_t)(((2*t + bko) ^ bxor) << 4));
            mma_hf(sa[2*ng],   qa[t], bf[0], bf[1]);
            mma_hf(sa[2*ng+1], qa[t], bf[2], bf[3]);
        }
    }

    float rm0 = -1e30f, rm1 = -1e30f;
    #pragma unroll
    for (int i = 0; i < 8; i++) {
        #pragma unroll
        for (int e = 0; e < 4; e++) sa[i][e] *= qksc;
        rm0 = fmaxf(rm0, fmaxf(sa[i][0], sa[i][1]));
        rm1 = fmaxf(rm1, fmaxf(sa[i][2], sa[i][3]));
    }
    rm0 = fmaxf(rm0, __shfl_xor_sync(0xffffffffu, rm0, 1));
    rm0 = fmaxf(rm0, __shfl_xor_sync(0xffffffffu, rm0, 2));
    rm1 = fmaxf(rm1, __shfl_xor_sync(0xffffffffu, rm1, 1));
    rm1 = fmaxf(rm1, __shfl_xor_sync(0xffffffffu, rm1, 2));

    const float mn0 = fmaxf(st.m[0], rm0), mn1 = fmaxf(st.m[1], rm1);
    const float c0 = fexp(st.m[0] - mn0), c1 = fexp(st.m[1] - mn1);
    #pragma unroll
    for (int d = 0; d < 16; d++) {
        O[d][0] *= c0; O[d][1] *= c0;
        O[d][2] *= c1; O[d][3] *= c1;
    }
    float ps0 = 0.f, ps1 = 0.f;
    #pragma unroll
    for (int i = 0; i < 8; i++) {
        sa[i][0] = fexp(sa[i][0] - mn0); ps0 += sa[i][0];
        sa[i][1] = fexp(sa[i][1] - mn0); ps0 += sa[i][1];
        sa[i][2] = fexp(sa[i][2] - mn1); ps1 += sa[i][2];
        sa[i][3] = fexp(sa[i][3] - mn1); ps1 += sa[i][3];
    }
    ps0 += __shfl_xor_sync(0xffffffffu, ps0, 1);
    ps0 += __shfl_xor_sync(0xffffffffu, ps0, 2);
    ps1 += __shfl_xor_sync(0xffffffffu, ps1, 1);
    ps1 += __shfl_xor_sync(0xffffffffu, ps1, 2);
    st.l[0] = st.l[0] * c0 + ps0;  st.m[0] = mn0;
    st.l[1] = st.l[1] * c1 + ps1;  st.m[1] = mn1;

    #pragma unroll
    for (int t = 0; t < 4; t++) {
        __half2 h0 = __floats2half2_rn(sa[2*t][0],   sa[2*t][1]);
        __half2 h1 = __floats2half2_rn(sa[2*t][2],   sa[2*t][3]);
        __half2 h2 = __floats2half2_rn(sa[2*t+1][0], sa[2*t+1][1]);
        __half2 h3 = __floats2half2_rn(sa[2*t+1][2], sa[2*t+1][3]);
        pf[t][0] = *(uint32_t*)&h0; pf[t][1] = *(uint32_t*)&h1;
        pf[t][2] = *(uint32_t*)&h2; pf[t][3] = *(uint32_t*)&h3;
    }
}

__global__ __launch_bounds__(256, 1) void flash_diff(
    const fp16* __restrict__ q1, const fp16* __restrict__ q2,
    const fp16* __restrict__ k1g, const fp16* __restrict__ k2g,
    const fp16* __restrict__ vtg, const float* __restrict__ lam,
    fp16* __restrict__ oa)
{
    extern __shared__ __align__(128) char dsm[];
    const uint32_t sb = smem_u32(dsm);
    const int tid = threadIdx.x;
    const int l = tid & 31, w = tid >> 5;
    const int m0 = blockIdx.x * 128;
    const int h  = blockIdx.y;

    {
        const fp16* gq1 = q1 + (long)m0 * DIM + h * HDIM;
        const fp16* gq2 = q2 + (long)m0 * DIM + h * HDIM;
        #pragma unroll
        for (int i = 0; i < 8; i++) {
            int idx = tid + i * 256;
            int row = idx >> 4, j = idx & 15;
            uint32_t so = (uint32_t)row * 256 + (uint32_t)((j ^ (row & 7)) << 4);
            cpa16(sb + so,         gq1 + (long)row * DIM + j * 8);
            cpa16(sb + 32768 + so, gq2 + (long)row * DIM + j * 8);
        }
    }

    auto load_stage = [&](int kt, int s) {
        const uint32_t st = sb + 65536 + (uint32_t)s * 49152;
        const int kb = kt * 64;
        const fp16* gk1 = k1g + (long)kb * DIM + h * HDIM;
        const fp16* gk2 = k2g + (long)kb * DIM + h * HDIM;
        #pragma unroll
        for (int i = 0; i < 4; i++) {
            int idx = tid + i * 256;
            int row = idx >> 4, j = idx & 15;
            uint32_t so = (uint32_t)row * 256 + (uint32_t)((j ^ (row & 7)) << 4);
            cpa16(st + so,         gk1 + (long)row * DIM + j * 8);
            cpa16(st + 16384 + so, gk2 + (long)row * DIM + j * 8);
        }
        const fp16* gv = vtg + (long)(h * HDIM) * SEQ + kb;
        #pragma unroll
        for (int i = 0; i < 4; i++) {
            int idx = tid + i * 256;
            int row = idx >> 3, j = idx & 7;
            cpa16(st + 32768 + (uint32_t)row * 128 + (uint32_t)((j ^ (row & 7)) << 4),
                  gv + (long)row * SEQ + j * 8);
        }
    };
    load_stage(0, 0); CP_COMMIT();
    load_stage(1, 1); CP_COMMIT();

    const int arow = w * 16 + (l & 15);
    const int axor = arow & 7;
    const int alo  = l >> 4;
    const uint32_t aQ1 = sb + (uint32_t)arow * 256;
    const uint32_t aQ2 = sb + 32768 + (uint32_t)arow * 256;
    const int bn  = (l & 7) + ((l >> 4) << 3);
    const int bko = (l >> 3) & 1;
    const int bxor = bn & 7;

    FlashState s1; s1.m[0] = s1.m[1] = -1e30f; s1.l[0] = s1.l[1] = 0.f;
    FlashState s2; s2.m[0] = s2.m[1] = -1e30f; s2.l[0] = s2.l[1] = 0.f;
    float O1[16][4], O2[16][4];
    #pragma unroll
    for (int d = 0; d < 16; d++)
        #pragma unroll
        for (int e = 0; e < 4; e++) { O1[d][e] = 0.f; O2[d][e] = 0.f; }

    const float qksc = 0.08838834764831845f;

    #pragma unroll 1
    for (int kt = 0; kt < 32; kt++) {
        CP_WAIT(1);
        __syncthreads();
        const uint32_t st = sb + 65536 + (uint32_t)(kt & 1) * 49152;
        uint32_t pf1[4][4], pf2[4][4];
        flash_score(aQ1, axor, alo, st,         bn, bko, s1, O1, pf1, qksc);
        flash_score(aQ2, axor, alo, st + 16384, bn, bko, s2, O2, pf2, qksc);
        // shared V loop: one frag load feeds both branches
        const uint32_t vst = st + 32768;
        #pragma unroll
        for (int dg = 0; dg < 8; dg++) {
            const uint32_t vrow = vst + (uint32_t)(dg*16 + bn) * 128;
            #pragma unroll
            for (int t = 0; t < 4; t++) {
                uint32_t bf[4];
                ldm4(bf, vrow + (uint32_t)(((2*t + bko) ^ bxor) << 4));
                mma_hf(O1[2*dg],   pf1[t], bf[0], bf[1]);
                mma_hf(O1[2*dg+1], pf1[t], bf[2], bf[3]);
                mma_hf(O2[2*dg],   pf2[t], bf[0], bf[1]);
                mma_hf(O2[2*dg+1], pf2[t], bf[2], bf[3]);
            }
        }
        __syncthreads();
        if (kt + 2 < 32) load_stage(kt + 2, kt & 1);
        CP_COMMIT();
    }

    const float lamh = lam[h];
    const float i10 = 1.f / s1.l[0], i11 = 1.f / s1.l[1];
    const float i20 = lamh / s2.l[0], i21 = lamh / s2.l[1];
    const int r0 = m0 + w * 16 + (l >> 2);
    #pragma unroll
    for (int d = 0; d < 16; d++) {
        const int col = h * HDIM + d * 8 + 2 * (l & 3);
        float a0 = O1[d][0] * i10 - O2[d][0] * i20;
        float a1 = O1[d][1] * i10 - O2[d][1] * i20;
        float a2 = O1[d][2] * i11 - O2[d][2] * i21;
        float a3 = O1[d][3] * i11 - O2[d][3] * i21;
        __half2 p0 = __floats2half2_rn(a0, a1);
        __half2 p1 = __floats2half2_rn(a2, a3);
        *(uint32_t*)&oa[(long)r0 * DIM + col]       = *(uint32_t*)&p0;
        *(uint32_t*)&oa[(long)(r0 + 8) * DIM + col] = *(uint32_t*)&p1;
    }
}

// ---------------- transpose fp32 -> fp16 ----------------
__global__ __launch_bounds__(256) void transpose_half(const float* __restrict__ in,
                                                      fp16* __restrict__ oh,
                                                      int R, int C) {
    const long zb = (long)blockIdx.z * R * C;
    in += zb; oh += zb;
    const int c0 = blockIdx.x * 32, r0 = blockIdx.y * 32;
    __shared__ float t[32][33];
    const int tx = threadIdx.x & 31, ty = threadIdx.x >> 5;
    #pragma unroll
    for (int i = 0; i < 4; i++)
        t[ty + 8*i][tx] = in[(long)(r0 + ty + 8*i) * C + c0 + tx];
    __syncthreads();
    #pragma unroll
    for (int i = 0; i < 4; i++)
        oh[(long)(c0 + ty + 8*i) * R + r0 + tx] = __float2half(t[tx][ty + 8*i]);
}

// ---------------- transpose fp16 -> fp16 ----------------
__global__ __launch_bounds__(256) void transpose_hh(const fp16* __restrict__ in,
                                                    fp16* __restrict__ oh,
                                                    int R, int C) {
    const int c0 = blockIdx.x * 32, r0 = blockIdx.y * 32;
    __shared__ fp16 t[32][34];
    const int tx = threadIdx.x & 31, ty = threadIdx.x >> 5;
    #pragma unroll
    for (int i = 0; i < 4; i++)
        t[ty + 8*i][tx] = in[(long)(r0 + ty + 8*i) * C + c0 + tx];
    __syncthreads();
    #pragma unroll
    for (int i = 0; i < 4; i++)
        oh[(long)(c0 + ty + 8*i) * R + r0 + tx] = t[tx][ty + 8*i];
}

// ---------------- RMSNorm ----------------
__global__ __launch_bounds__(256) void rmsnorm_kernel(const float* __restrict__ x,
                                                      const float* __restrict__ g,
                                                      float* __restrict__ yf,
                                                      fp16* __restrict__ ya) {
    __shared__ float sh[8];
    const long row = blockIdx.x;
    const float* xr = x + row * (long)DIM;
    float v[8], ss = 0.f;
    #pragma unroll
    for (int i = 0; i < 8; i++) { v[i] = xr[threadIdx.x + 256*i]; ss += v[i]*v[i]; }
    #pragma unroll
    for (int o = 16; o; o >>= 1) ss += __shfl_xor_sync(0xffffffffu, ss, o);
    if ((threadIdx.x & 31) == 0) sh[threadIdx.x >> 5] = ss;
    __syncthreads();
    float tot = 0.f;
    #pragma unroll
    for (int i = 0; i < 8; i++) tot += sh[i];
    const float sc = rsqrtf(tot * (1.0f / DIM) + EPSV);
    #pragma unroll
    for (int i = 0; i < 8; i++) {
        int c = threadIdx.x + 256*i;
        float y = v[i] * sc * g[c];
        long o = row * (long)DIM + c;
        if (yf) yf[o] = y;
        ya[o] = __float2half(y);
    }
}

// ---------------- lambda ----------------
__global__ void lambda_kernel(const float* __restrict__ lq1, const float* __restrict__ lk1,
                              const float* __restrict__ lq2, const float* __restrict__ lk2,
                              float* __restrict__ lam) {
    __shared__ float s1[128], s2[128];
    int h = blockIdx.x, t = threadIdx.x;
    int i = h * HDIM + t;
    s1[t] = lq1[i] * lk1[i];
    s2[t] = lq2[i] * lk2[i];
    __syncthreads();
    for (int o = 64; o; o >>= 1) {
        if (t < o) { s1[t] += s1[t+o]; s2[t] += s2[t+o]; }
        __syncthreads();
    }
    if (t == 0) lam[h] = expf(s1[0]) - expf(s2[0]) + LAMB0;
}

// ---------------- launcher ----------------
extern "C" void kernel_launch(void* const* d_in, const int* in_sizes, int n_in,
                              void* d_out, int out_size) {
    (void)in_sizes; (void)n_in; (void)out_size;
    const float* x   = (const float*)d_in[0];
    const float* gn  = (const float*)d_in[1];
    const float* Wq1 = (const float*)d_in[2];
    const float* Wq2 = (const float*)d_in[3];
    const float* Wk1 = (const float*)d_in[4];
    const float* Wk2 = (const float*)d_in[5];
    const float* Wv  = (const float*)d_in[6];
    const float* lq1 = (const float*)d_in[7];
    const float* lk1 = (const float*)d_in[8];
    const float* lq2 = (const float*)d_in[9];
    const float* lk2 = (const float*)d_in[10];
    const float* Wo  = (const float*)d_in[11];
    const float* W1  = (const float*)d_in[12];
    const float* W2  = (const float*)d_in[13];
    const float* W3  = (const float*)d_in[14];
    float* out = (float*)d_out;

    const int SMEM  = 4 * 2 * 10240;      // 81920 (GEMM)
    const int FSMEM = 65536 + 2 * 49152;  // 163840 (flash)
    cudaFuncSetAttribute(mma_gemm<0>, cudaFuncAttributeMaxDynamicSharedMemorySize, SMEM);
    cudaFuncSetAttribute(mma_gemm<2>, cudaFuncAttributeMaxDynamicSharedMemorySize, SMEM);
    cudaFuncSetAttribute(mma_gemm<3>, cudaFuncAttributeMaxDynamicSharedMemorySize, SMEM);
    cudaFuncSetAttribute(flash_diff,  cudaFuncAttributeMaxDynamicSharedMemorySize, FSMEM);

#define SYM(v, s) cudaGetSymbolAddress((void**)&v, s)
    float *h0f, *hf, *lam;
    SYM(h0f, g_h0f); SYM(hf, g_hf); SYM(lam, g_lam);
    fp16 *h0a,*za,*q1a,*q2a,*k1,*k2,*vr,*vt,*oa,*g1h,*ua;
    fp16 *fwq1,*fwq2,*fwk1,*fwk2,*fwv,*fwo,*fw1,*fw2,*fw3;
    SYM(h0a, g_h0a); SYM(za, g_za);
    SYM(q1a, g_q1a); SYM(q2a, g_q2a);
    SYM(k1, g_k1); SYM(k2, g_k2); SYM(vr, g_vr); SYM(vt, g_vt);
    SYM(oa, g_oa); SYM(g1h, g_g1h); SYM(ua, g_ua);
    SYM(fwq1, g_fwq1); SYM(fwq2, g_fwq2); SYM(fwk1, g_fwk1); SYM(fwk2, g_fwk2);
    SYM(fwv, g_fwv); SYM(fwo, g_fwo); SYM(fw1, g_fw1); SYM(fw2, g_fw2); SYM(fw3, g_fw3);
#undef SYM

    // weight conversions -> [N,K] K-major fp16
    dim3 gtA(HDIM/32, DIM/32, NH);
    transpose_half<<<gtA, 256>>>(Wq1, fwq1, DIM, HDIM);
    transpose_half<<<gtA, 256>>>(Wq2, fwq2, DIM, HDIM);
    transpose_half<<<gtA, 256>>>(Wk1, fwk1, DIM, HDIM);
    transpose_half<<<gtA, 256>>>(Wk2, fwk2, DIM, HDIM);
    transpose_half<<<gtA, 256>>>(Wv,  fwv,  DIM, HDIM);
    dim3 gtO(DIM/32, DIM/32, 1);
    transpose_half<<<gtO, 256>>>(Wo, fwo, DIM, DIM);
    dim3 gt1(HIDN/32, DIM/32, 1);
    transpose_half<<<gt1, 256>>>(W1, fw1, DIM, HIDN);
    transpose_half<<<gt1, 256>>>(W2, fw2, DIM, HIDN);
    dim3 gt3(DIM/32, HIDN/32, 1);
    transpose_half<<<gt3, 256>>>(W3, fw3, HIDN, DIM);

    // 1) h0 = rmsnorm(x)
    rmsnorm_kernel<<<SEQ, 256>>>(x, gn, h0f, h0a);
    lambda_kernel<<<NH, 128>>>(lq1, lk1, lq2, lk2, lam);

    // 2) projections (all fp16 out; V fp16 row-major)
    dim3 gproj(DIM/128, SEQ/128, 1);
    mma_gemm<2><<<gproj, 256, SMEM>>>(h0a, DIM, 0, fwq1, DIM, 0, nullptr, nullptr, nullptr, q1a, DIM, 0, DIM, 1.f);
    mma_gemm<2><<<gproj, 256, SMEM>>>(h0a, DIM, 0, fwq2, DIM, 0, nullptr, nullptr, nullptr, q2a, DIM, 0, DIM, 1.f);
    mma_gemm<2><<<gproj, 256, SMEM>>>(h0a, DIM, 0, fwk1, DIM, 0, nullptr, nullptr, nullptr, k1, DIM, 0, DIM, 1.f);
    mma_gemm<2><<<gproj, 256, SMEM>>>(h0a, DIM, 0, fwk2, DIM, 0, nullptr, nullptr, nullptr, k2, DIM, 0, DIM, 1.f);
    mma_gemm<2><<<gproj, 256, SMEM>>>(h0a, DIM, 0, fwv,  DIM, 0, nullptr, nullptr, nullptr, vr, DIM, 0, DIM, 1.f);

    // 3) V^T fp16->fp16
    dim3 gtV(DIM/32, SEQ/32, 1);
    transpose_hh<<<gtV, 256>>>(vr, vt, SEQ, DIM);

    // 4-6) fused differential flash attention -> oa
    dim3 gfl(SEQ/128, NH);
    flash_diff<<<gfl, 256, FSMEM>>>(q1a, q2a, k1, k2, vt, lam, oa);

    // 7) h = O @ Wo + h0
    dim3 gwo(DIM/128, SEQ/128, 1);
    mma_gemm<0><<<gwo, 256, SMEM>>>(oa, DIM, 0, fwo, DIM, 0, hf, h0f, nullptr, nullptr, DIM, 0, DIM, 1.f);

    // 8) z = rmsnorm(h)
    rmsnorm_kernel<<<SEQ, 256>>>(hf, gn, nullptr, za);

    // 9) G1 fp16; G2 fused with SwiGLU(G1) -> ua
    dim3 gffn(HIDN/128, SEQ/128, 1);
    mma_gemm<2><<<gffn, 256, SMEM>>>(za, DIM, 0, fw1, DIM, 0, nullptr, nullptr, nullptr, g1h, HIDN, 0, DIM, 1.f);
    mma_gemm<3><<<gffn, 256, SMEM>>>(za, DIM, 0, fw2, DIM, 0, nullptr, nullptr, g1h, ua, HIDN, 0, DIM, 1.f);

    // 10) out = U @ W3 + h
    dim3 gw3(DIM/128, SEQ/128, 1);
    mma_gemm<0><<<gw3, 256, SMEM>>>(ua, HIDN, 0, fw3, HIDN, 0, out, hf, nullptr, nullptr, DIM, 0, HIDN, 1.f);
}

// round 13
// speedup vs baseline: 6.1104x; 1.0452x over previous
#include <cuda_runtime.h>
#include <cuda_fp16.h>
#include <math.h>
#include <stdint.h>

#define SEQ 2048
#define DIM 2048
#define NH 16
#define HDIM 128
#define HIDN 8192
#define EPSV 1e-6f
#define LAMB0 0.8f

typedef __half fp16;

// ---------------- scratch ----------------
__device__ float g_h0f[SEQ * DIM];
__device__ float g_hf [SEQ * DIM];
__device__ float g_lam[NH];

__device__ fp16 g_h0a[SEQ*DIM];
__device__ fp16 g_za [SEQ*DIM];
__device__ fp16 g_qk [(size_t)4*SEQ*DIM];        // q1,q2,k1,k2 slices
__device__ fp16 g_vt [SEQ*DIM];                  // V^T [H*DH, SEQ]
__device__ fp16 g_o1 [SEQ*DIM], g_o2[SEQ*DIM];
__device__ fp16 g_oa [SEQ*DIM];
__device__ fp16 g_g1h[(size_t)SEQ*HIDN];
__device__ fp16 g_ua [(size_t)SEQ*HIDN];
__device__ fp16 g_fwqkv[(size_t)5*DIM*DIM];      // Wq1,Wq2,Wk1,Wk2,Wv transposed
__device__ fp16 g_fwo [DIM*DIM];
__device__ fp16 g_fw12[(size_t)2*DIM*HIDN];
__device__ fp16 g_fw3[(size_t)DIM*HIDN];

// ---------------- helpers ----------------
__device__ __forceinline__ uint32_t smem_u32(const void* p) {
    uint32_t a;
    asm("{ .reg .u64 t; cvta.to.shared.u64 t, %1; cvt.u32.u64 %0, t; }" : "=r"(a) : "l"(p));
    return a;
}
__device__ __forceinline__ void cpa16(uint32_t s, const void* g) {
    asm volatile("cp.async.cg.shared.global [%0], [%1], 16;" :: "r"(s), "l"(g));
}
#define CP_COMMIT() asm volatile("cp.async.commit_group;")
#define CP_WAIT(n)  asm volatile("cp.async.wait_group %0;" :: "n"(n))

__device__ __forceinline__ void ldm4(uint32_t* r, uint32_t addr) {
    asm volatile("ldmatrix.sync.aligned.m8n8.x4.shared.b16 {%0,%1,%2,%3}, [%4];"
        : "=r"(r[0]), "=r"(r[1]), "=r"(r[2]), "=r"(r[3]) : "r"(addr));
}
__device__ __forceinline__ void mma_hf(float* d, const uint32_t* a, uint32_t b0, uint32_t b1) {
    asm volatile("mma.sync.aligned.m16n8k16.row.col.f32.f16.f16.f32 "
        "{%0,%1,%2,%3}, {%4,%5,%6,%7}, {%8,%9}, {%0,%1,%2,%3};"
        : "+f"(d[0]), "+f"(d[1]), "+f"(d[2]), "+f"(d[3])
        : "r"(a[0]), "r"(a[1]), "r"(a[2]), "r"(a[3]), "r"(b0), "r"(b1));
}

// FMA-pipe exp
__device__ __forceinline__ float fexp(float x) {
    float y = x * 1.44269504089f;
    y = fmaxf(fminf(y, 126.0f), -125.0f);
    float z = __fadd_rn(y, 12582912.0f);
    float n = __fsub_rn(z, 12582912.0f);
    float f = __fsub_rn(y, n);
    float p =            1.33335581e-3f;
    p = fmaf(p, f, 9.61812911e-3f);
    p = fmaf(p, f, 5.55041087e-2f);
    p = fmaf(p, f, 2.40226507e-1f);
    p = fmaf(p, f, 6.93147181e-1f);
    p = fmaf(p, f, 1.0f);
    int i = __float_as_int(z);
    float s = __int_as_float((i << 23) + 0x3F800000);
    return p * s;
}

// ---------------- fp16 1-product GEMM ----------------
// MODE 0: fp32 (+residual Rf). MODE 2: fp16. MODE 3: fp16 = silu(Rh)*acc.
template <int MODE>
__global__ __launch_bounds__(256) void mma_gemm(
    const fp16* __restrict__ Ah, int lda, long sA,
    const fp16* __restrict__ B, int ldb, long sB,
    float* __restrict__ Cf, const float* __restrict__ Rf, const fp16* __restrict__ Rh,
    fp16* __restrict__ Ch,
    int ldc, long sC, int K, float alpha)
{
    constexpr int RSB  = 80;
    constexpr int MATB = 128 * RSB;
    constexpr int STG  = 2 * MATB;
    extern __shared__ __align__(128) char dsm[];
    const uint32_t sb = smem_u32(dsm);

    const int tid = threadIdx.x;
    const int m0 = blockIdx.y * 128, n0 = blockIdx.x * 128, z = blockIdx.z;

    Ah += (long)z * sA + (long)m0 * lda;
    B  += (long)z * sB + (long)n0 * ldb;

    const int NC = K >> 5;

    auto load_chunk = [&](int c, int s) {
        const long k0 = (long)c << 5;
        const uint32_t st = sb + (uint32_t)s * STG;
        #pragma unroll
        for (int i = 0; i < 2; i++) {
            int idx = tid + 256 * i;
            int row = idx >> 2;
            int sg  = idx & 3;
            uint32_t so = st + (uint32_t)row * RSB + (uint32_t)sg * 16;
            cpa16(so,        Ah + (long)row * lda + k0 + sg * 8);
            cpa16(so + MATB, B  + (long)row * ldb + k0 + sg * 8);
        }
    };

    const int l  = tid & 31;
    const int wp = tid >> 5;
    const int wm = (wp >> 2) * 64;
    const int wn = (wp & 3) * 32;
    const uint32_t aoff = (uint32_t)(wm + (l & 15)) * RSB + (uint32_t)((l >> 4) * 16);
    const uint32_t boff = (uint32_t)MATB + (uint32_t)(wn + (l & 7) + ((l >> 4) << 3)) * RSB
                        + (uint32_t)(((l >> 3) & 1) * 16);

    float acc[4][4][4];
    #pragma unroll
    for (int a = 0; a < 4; a++)
        #pragma unroll
        for (int b = 0; b < 4; b++)
            #pragma unroll
            for (int c = 0; c < 4; c++) acc[a][b][c] = 0.f;

    load_chunk(0, 0); CP_COMMIT();
    load_chunk(1, 1); CP_COMMIT();
    load_chunk(2, 2); CP_COMMIT();

    for (int c = 0; c < NC; c++) {
        const int s = c & 3;
        const int rem = NC - 1 - c;
        if (rem >= 2)      { CP_WAIT(2); }
        else if (rem == 1) { CP_WAIT(1); }
        else               { CP_WAIT(0); }
        __syncthreads();
        if (c + 3 < NC) { load_chunk(c + 3, (c + 3) & 3); CP_COMMIT(); }

        const uint32_t stg = sb + (uint32_t)s * STG;
        #pragma unroll
        for (int ks = 0; ks < 2; ks++) {
            const uint32_t base = stg + (uint32_t)ks * 32;
            uint32_t ah[4][4], bh[2][4];
            #pragma unroll
            for (int mi = 0; mi < 4; mi++)
                ldm4(ah[mi], base + aoff + (uint32_t)mi * (16 * RSB));
            #pragma unroll
            for (int ng = 0; ng < 2; ng++)
                ldm4(bh[ng], base + boff + (uint32_t)ng * (16 * RSB));
            #pragma unroll
            for (int mi = 0; mi < 4; mi++)
                #pragma unroll
                for (int ni = 0; ni < 4; ni++)
                    mma_hf(acc[mi][ni], ah[mi],
                           bh[ni >> 1][(ni & 1) * 2], bh[ni >> 1][(ni & 1) * 2 + 1]);
        }
    }

    const int qr = l >> 2;
    const int qc = (l & 3) * 2;
    const long cbase = (long)z * sC + (long)m0 * ldc + n0;
    #pragma unroll
    for (int mi = 0; mi < 4; mi++)
        #pragma unroll
        for (int ni = 0; ni < 4; ni++)
            #pragma unroll
            for (int hr = 0; hr < 2; hr++) {
                long off = cbase + (long)(wm + mi * 16 + qr + hr * 8) * ldc + (wn + ni * 8 + qc);
                float v0 = acc[mi][ni][hr * 2 + 0] * alpha;
                float v1 = acc[mi][ni][hr * 2 + 1] * alpha;
                if (MODE == 0) {
                    if (Rf) { v0 += Rf[off]; v1 += Rf[off + 1]; }
                    Cf[off] = v0; Cf[off + 1] = v1;
                } else if (MODE == 2) {
                    Ch[off]     = __float2half(v0);
                    Ch[off + 1] = __float2half(v1);
                } else {
                    float a0 = __half2float(Rh[off]),     s0 = a0 / (1.f + fexp(-a0));
                    float a1 = __half2float(Rh[off + 1]), s1 = a1 / (1.f + fexp(-a1));
                    Ch[off]     = __float2half(s0 * v0);
                    Ch[off + 1] = __float2half(s1 * v1);
                }
            }
}

// ---------------- single-branch flash attention ----------------
// grid (SEQ/128, NH), 256 thr. Q resident (32KB), K+V 2-stage (2x32KB).
// Writes normalized softmax(QK^T*sc)@V as fp16 [SEQ, H*DH].
__global__ __launch_bounds__(256, 1) void flash_branch(
    const fp16* __restrict__ qg, const fp16* __restrict__ kg,
    const fp16* __restrict__ vtg, fp16* __restrict__ ob)
{
    extern __shared__ __align__(128) char dsm[];
    const uint32_t sb = smem_u32(dsm);
    const int tid = threadIdx.x;
    const int l = tid & 31, w = tid >> 5;
    const int m0 = blockIdx.x * 128;
    const int h  = blockIdx.y;

    {   // Q tile 128x128 (rows 256B, XOR-chunk swizzle)
        const fp16* gq = qg + (long)m0 * DIM + h * HDIM;
        #pragma unroll
        for (int i = 0; i < 8; i++) {
            int idx = tid + i * 256;
            int row = idx >> 4, j = idx & 15;
            cpa16(sb + (uint32_t)row * 256 + (uint32_t)((j ^ (row & 7)) << 4),
                  gq + (long)row * DIM + j * 8);
        }
    }

    auto load_stage = [&](int kt, int s) {
        const uint32_t st = sb + 32768 + (uint32_t)s * 32768;
        const int kb = kt * 64;
        const fp16* gk = kg + (long)kb * DIM + h * HDIM;
        #pragma unroll
        for (int i = 0; i < 4; i++) {
            int idx = tid + i * 256;
            int row = idx >> 4, j = idx & 15;
            cpa16(st + (uint32_t)row * 256 + (uint32_t)((j ^ (row & 7)) << 4),
                  gk + (long)row * DIM + j * 8);
        }
        const fp16* gv = vtg + (long)(h * HDIM) * SEQ + kb;
        #pragma unroll
        for (int i = 0; i < 4; i++) {
            int idx = tid + i * 256;
            int row = idx >> 3, j = idx & 7;
            cpa16(st + 16384 + (uint32_t)row * 128 + (uint32_t)((j ^ (row & 7)) << 4),
                  gv + (long)row * SEQ + j * 8);
        }
    };
    load_stage(0, 0); CP_COMMIT();
    load_stage(1, 1); CP_COMMIT();

    const int arow = w * 16 + (l & 15);
    const int axor = arow & 7;
    const int alo  = l >> 4;
    const uint32_t aQ = sb + (uint32_t)arow * 256;
    const int bn  = (l & 7) + ((l >> 4) << 3);
    const int bko = (l >> 3) & 1;
    const int bxor = bn & 7;

    float m0s = -1e30f, m1s = -1e30f, l0s = 0.f, l1s = 0.f;
    float O[16][4];
    #pragma unroll
    for (int d = 0; d < 16; d++)
        #pragma unroll
        for (int e = 0; e < 4; e++) O[d][e] = 0.f;

    const float qksc = 0.08838834764831845f;

    #pragma unroll 1
    for (int kt = 0; kt < 32; kt++) {
        CP_WAIT(1);
        __syncthreads();
        const uint32_t st = sb + 32768 + (uint32_t)(kt & 1) * 32768;

        // ---- S = Q.K^T ----
        float sa[8][4];
        #pragma unroll
        for (int i = 0; i < 8; i++)
            #pragma unroll
            for (int e = 0; e < 4; e++) sa[i][e] = 0.f;
        {
            uint32_t qa[8][4];
            #pragma unroll
            for (int t = 0; t < 8; t++)
                ldm4(qa[t], aQ + (uint32_t)(((2*t + alo) ^ axor) << 4));
            #pragma unroll
            for (int ng = 0; ng < 4; ng++) {
                const uint32_t krow = st + (uint32_t)(ng*16 + bn) * 256;
                #pragma unroll
                for (int t = 0; t < 8; t++) {
                    uint32_t bf[4];
                    ldm4(bf, krow + (uint32_t)(((2*t + bko) ^ bxor) << 4));
                    mma_hf(sa[2*ng],   qa[t], bf[0], bf[1]);
                    mma_hf(sa[2*ng+1], qa[t], bf[2], bf[3]);
                }
            }
        }

        // ---- online softmax ----
        float rm0 = -1e30f, rm1 = -1e30f;
        #pragma unroll
        for (int i = 0; i < 8; i++) {
            #pragma unroll
            for (int e = 0; e < 4; e++) sa[i][e] *= qksc;
            rm0 = fmaxf(rm0, fmaxf(sa[i][0], sa[i][1]));
            rm1 = fmaxf(rm1, fmaxf(sa[i][2], sa[i][3]));
        }
        rm0 = fmaxf(rm0, __shfl_xor_sync(0xffffffffu, rm0, 1));
        rm0 = fmaxf(rm0, __shfl_xor_sync(0xffffffffu, rm0, 2));
        rm1 = fmaxf(rm1, __shfl_xor_sync(0xffffffffu, rm1, 1));
        rm1 = fmaxf(rm1, __shfl_xor_sync(0xffffffffu, rm1, 2));
        const float mn0 = fmaxf(m0s, rm0), mn1 = fmaxf(m1s, rm1);
        const float c0 = fexp(m0s - mn0), c1 = fexp(m1s - mn1);
        #pragma unroll
        for (int d = 0; d < 16; d++) {
            O[d][0] *= c0; O[d][1] *= c0;
            O[d][2] *= c1; O[d][3] *= c1;
        }
        float ps0 = 0.f, ps1 = 0.f;
        #pragma unroll
        for (int i = 0; i < 8; i++) {
            sa[i][0] = fexp(sa[i][0] - mn0); ps0 += sa[i][0];
            sa[i][1] = fexp(sa[i][1] - mn0); ps0 += sa[i][1];
            sa[i][2] = fexp(sa[i][2] - mn1); ps1 += sa[i][2];
            sa[i][3] = fexp(sa[i][3] - mn1); ps1 += sa[i][3];
        }
        ps0 += __shfl_xor_sync(0xffffffffu, ps0, 1);
        ps0 += __shfl_xor_sync(0xffffffffu, ps0, 2);
        ps1 += __shfl_xor_sync(0xffffffffu, ps1, 1);
        ps1 += __shfl_xor_sync(0xffffffffu, ps1, 2);
        l0s = l0s * c0 + ps0;  m0s = mn0;
        l1s = l1s * c1 + ps1;  m1s = mn1;

        // ---- pack P ----
        uint32_t pf[4][4];
        #pragma unroll
        for (int t = 0; t < 4; t++) {
            __half2 h0 = __floats2half2_rn(sa[2*t][0],   sa[2*t][1]);
            __half2 h1 = __floats2half2_rn(sa[2*t][2],   sa[2*t][3]);
            __half2 h2 = __floats2half2_rn(sa[2*t+1][0], sa[2*t+1][1]);
            __half2 h3 = __floats2half2_rn(sa[2*t+1][2], sa[2*t+1][3]);
            pf[t][0] = *(uint32_t*)&h0; pf[t][1] = *(uint32_t*)&h1;
            pf[t][2] = *(uint32_t*)&h2; pf[t][3] = *(uint32_t*)&h3;
        }

        // ---- O += P.V ----
        const uint32_t vst = st + 16384;
        #pragma unroll
        for (int dg = 0; dg < 8; dg++) {
            const uint32_t vrow = vst + (uint32_t)(dg*16 + bn) * 128;
            #pragma unroll
            for (int t = 0; t < 4; t++) {
                uint32_t bf[4];
                ldm4(bf, vrow + (uint32_t)(((2*t + bko) ^ bxor) << 4));
                mma_hf(O[2*dg],   pf[t], bf[0], bf[1]);
                mma_hf(O[2*dg+1], pf[t], bf[2], bf[3]);
            }
        }
        __syncthreads();
        if (kt + 2 < 32) load_stage(kt + 2, kt & 1);
        CP_COMMIT();
    }

    const float i0 = 1.f / l0s, i1 = 1.f / l1s;
    const int r0 = m0 + w * 16 + (l >> 2);
    #pragma unroll
    for (int d = 0; d < 16; d++) {
        const int col = h * HDIM + d * 8 + 2 * (l & 3);
        __half2 p0 = __floats2half2_rn(O[d][0] * i0, O[d][1] * i0);
        __half2 p1 = __floats2half2_rn(O[d][2] * i1, O[d][3] * i1);
        *(uint32_t*)&ob[(long)r0 * DIM + col]       = *(uint32_t*)&p0;
        *(uint32_t*)&ob[(long)(r0 + 8) * DIM + col] = *(uint32_t*)&p1;
    }
}

// ---------------- combine: oa = o1 - lam[h]*o2 ----------------
__global__ __launch_bounds__(256) void combine_kernel(
    const fp16* __restrict__ o1, const fp16* __restrict__ o2,
    const float* __restrict__ lam, fp16* __restrict__ oa)
{
    long i = (long)blockIdx.x * 256 + threadIdx.x;   // half2 index
    int h = (int)((i * 2) % DIM) / HDIM;
    float lm = lam[h];
    __half2 a = ((const __half2*)o1)[i];
    __half2 b = ((const __half2*)o2)[i];
    float2 af = __half22float2(a), bf = __half22float2(b);
    __half2 r = __floats2half2_rn(af.x - lm * bf.x, af.y - lm * bf.y);
    ((__half2*)oa)[i] = r;
}

// ---------------- batched QKV weight transpose: 5 x [H,D,DH] -> [5][H*DH, D] ----------------
__global__ __launch_bounds__(256) void wt5_kernel(
    const float* __restrict__ w0, const float* __restrict__ w1,
    const float* __restrict__ w2, const float* __restrict__ w3,
    const float* __restrict__ w4, fp16* __restrict__ outb)
{
    const int z = blockIdx.z;
    const int m = z >> 4, h = z & 15;
    const float* in = (m == 0 ? w0 : m == 1 ? w1 : m == 2 ? w2 : m == 3 ? w3 : w4)
                    + (long)h * DIM * HDIM;
    fp16* oh = outb + (long)m * DIM * DIM + (long)h * HDIM * DIM;
    const int c0 = blockIdx.x * 32, r0 = blockIdx.y * 32;   // c in [0,HDIM), r in [0,DIM)
    __shared__ float t[32][33];
    const int tx = threadIdx.x & 31, ty = threadIdx.x >> 5;
    #pragma unroll
    for (int i = 0; i < 4; i++)
        t[ty + 8*i][tx] = in[(long)(r0 + ty + 8*i) * HDIM + c0 + tx];
    __syncthreads();
    #pragma unroll
    for (int i = 0; i < 4; i++)
        oh[(long)(c0 + ty + 8*i) * DIM + r0 + tx] = __float2half(t[tx][ty + 8*i]);
}

// ---------------- generic fp32 -> fp16 transpose (z batches same-shape, in/out strided) ----------------
__global__ __launch_bounds__(256) void transpose_half2(
    const float* __restrict__ inA, const float* __restrict__ inB,
    fp16* __restrict__ outb, int R, int C)
{
    const int z = blockIdx.z;
    const float* in = (z == 0) ? inA : inB;
    fp16* oh = outb + (long)z * R * C;
    const int c0 = blockIdx.x * 32, r0 = blockIdx.y * 32;
    __shared__ float t[32][33];
    const int tx = threadIdx.x & 31, ty = threadIdx.x >> 5;
    #pragma unroll
    for (int i = 0; i < 4; i++)
        t[ty + 8*i][tx] = in[(long)(r0 + ty + 8*i) * C + c0 + tx];
    __syncthreads();
    #pragma unroll
    for (int i = 0; i < 4; i++)
        oh[(long)(c0 + ty + 8*i) * R + r0 + tx] = __float2half(t[tx][ty + 8*i]);
}

// ---------------- RMSNorm ----------------
__global__ __launch_bounds__(256) void rmsnorm_kernel(const float* __restrict__ x,
                                                      const float* __restrict__ g,
                                                      float* __restrict__ yf,
                                                      fp16* __restrict__ ya) {
    __shared__ float sh[8];
    const long row = blockIdx.x;
    const float* xr = x + row * (long)DIM;
    float v[8], ss = 0.f;
    #pragma unroll
    for (int i = 0; i < 8; i++) { v[i] = xr[threadIdx.x + 256*i]; ss += v[i]*v[i]; }
    #pragma unroll
    for (int o = 16; o; o >>= 1) ss += __shfl_xor_sync(0xffffffffu, ss, o);
    if ((threadIdx.x & 31) == 0) sh[threadIdx.x >> 5] = ss;
    __syncthreads();
    float tot = 0.f;
    #pragma unroll
    for (int i = 0; i < 8; i++) tot += sh[i];
    const float sc = rsqrtf(tot * (1.0f / DIM) + EPSV);
    #pragma unroll
    for (int i = 0; i < 8; i++) {
        int c = threadIdx.x + 256*i;
        float y = v[i] * sc * g[c];
        long o = row * (long)DIM + c;
        if (yf) yf[o] = y;
        ya[o] = __float2half(y);
    }
}

// ---------------- lambda ----------------
__global__ void lambda_kernel(const float* __restrict__ lq1, const float* __restrict__ lk1,
                              const float* __restrict__ lq2, const float* __restrict__ lk2,
                              float* __restrict__ lam) {
    __shared__ float s1[128], s2[128];
    int h = blockIdx.x, t = threadIdx.x;
    int i = h * HDIM + t;
    s1[t] = lq1[i] * lk1[i];
    s2[t] = lq2[i] * lk2[i];
    __syncthreads();
    for (int o = 64; o; o >>= 1) {
        if (t < o) { s1[t] += s1[t+o]; s2[t] += s2[t+o]; }
        __syncthreads();
    }
    if (t == 0) lam[h] = expf(s1[0]) - expf(s2[0]) + LAMB0;
}

// ---------------- launcher ----------------
extern "C" void kernel_launch(void* const* d_in, const int* in_sizes, int n_in,
                              void* d_out, int out_size) {
    (void)in_sizes; (void)n_in; (void)out_size;
    const float* x   = (const float*)d_in[0];
    const float* gn  = (const float*)d_in[1];
    const float* Wq1 = (const float*)d_in[2];
    const float* Wq2 = (const float*)d_in[3];
    const float* Wk1 = (const float*)d_in[4];
    const float* Wk2 = (const float*)d_in[5];
    const float* Wv  = (const float*)d_in[6];
    const float* lq1 = (const float*)d_in[7];
    const float* lk1 = (const float*)d_in[8];
    const float* lq2 = (const float*)d_in[9];
    const float* lk2 = (const float*)d_in[10];
    const float* Wo  = (const float*)d_in[11];
    const float* W1  = (const float*)d_in[12];
    const float* W2  = (const float*)d_in[13];
    const float* W3  = (const float*)d_in[14];
    float* out = (float*)d_out;

    const int SMEM  = 4 * 2 * 10240;   // 81920 (GEMM)
    const int FSMEM = 32768 + 2 * 32768; // 98304 (flash branch)
    cudaFuncSetAttribute(mma_gemm<0>, cudaFuncAttributeMaxDynamicSharedMemorySize, SMEM);
    cudaFuncSetAttribute(mma_gemm<2>, cudaFuncAttributeMaxDynamicSharedMemorySize, SMEM);
    cudaFuncSetAttribute(mma_gemm<3>, cudaFuncAttributeMaxDynamicSharedMemorySize, SMEM);
    cudaFuncSetAttribute(flash_branch, cudaFuncAttributeMaxDynamicSharedMemorySize, FSMEM);

#define SYM(v, s) cudaGetSymbolAddress((void**)&v, s)
    float *h0f, *hf, *lam;
    SYM(h0f, g_h0f); SYM(hf, g_hf); SYM(lam, g_lam);
    fp16 *h0a,*za,*qk,*vt,*o1,*o2,*oa,*g1h,*ua;
    fp16 *fwqkv,*fwo,*fw12,*fw3;
    SYM(h0a, g_h0a); SYM(za, g_za); SYM(qk, g_qk); SYM(vt, g_vt);
    SYM(o1, g_o1); SYM(o2, g_o2); SYM(oa, g_oa); SYM(g1h, g_g1h); SYM(ua, g_ua);
    SYM(fwqkv, g_fwqkv); SYM(fwo, g_fwo); SYM(fw12, g_fw12); SYM(fw3, g_fw3);
#undef SYM

    const long SD = (long)SEQ * DIM;
    const long DD = (long)DIM * DIM;
    fp16* q1 = qk;
    fp16* q2 = qk + SD;
    fp16* k1 = qk + 2 * SD;
    fp16* k2 = qk + 3 * SD;
    fp16* fwv = fwqkv + 4 * DD;
    fp16* fw1 = fw12;
    fp16* fw2 = fw12 + (long)DIM * HIDN;

    // ---- pre-flash (exactly 5 launches so flash_b2 is launch #6 for ncu -s 5) ----
    // 1) batched QKV weight transpose
    dim3 g5(HDIM/32, DIM/32, 5 * NH);
    wt5_kernel<<<g5, 256>>>(Wq1, Wq2, Wk1, Wk2, Wv, fwqkv);
    // 2) h0 = rmsnorm(x)
    rmsnorm_kernel<<<SEQ, 256>>>(x, gn, h0f, h0a);
    // 3) q1,q2,k1,k2 batched projection (z = 4)
    dim3 gproj(DIM/128, SEQ/128, 4);
    mma_gemm<2><<<gproj, 256, SMEM>>>(h0a, DIM, 0, fwqkv, DIM, DD, nullptr, nullptr, nullptr, qk, DIM, SD, DIM, 1.f);
    // 4) V^T directly: C[hd, s] = fwv[hd,:] . h0a[s,:]
    dim3 gvt(SEQ/128, DIM/128, 1);
    mma_gemm<2><<<gvt, 256, SMEM>>>(fwv, DIM, 0, h0a, DIM, 0, nullptr, nullptr, nullptr, vt, SEQ, 0, DIM, 1.f);
    // 5-6) flash branches
    dim3 gfl(SEQ/128, NH);
    flash_branch<<<gfl, 256, FSMEM>>>(q1, k1, vt, o1);
    flash_branch<<<gfl, 256, FSMEM>>>(q2, k2, vt, o2);

    // lambda + combine
    lambda_kernel<<<NH, 128>>>(lq1, lk1, lq2, lk2, lam);
    combine_kernel<<<(SEQ * DIM / 2) / 256, 256>>>(o1, o2, lam, oa);

    // Wo transpose + h = O @ Wo + h0
    dim3 gtO(DIM/32, DIM/32, 1);
    transpose_half2<<<gtO, 256>>>(Wo, Wo, fwo, DIM, DIM);
    dim3 gwo(DIM/128, SEQ/128, 1);
    mma_gemm<0><<<gwo, 256, SMEM>>>(oa, DIM, 0, fwo, DIM, 0, hf, h0f, nullptr, nullptr, DIM, 0, DIM, 1.f);

    // z = rmsnorm(h)
    rmsnorm_kernel<<<SEQ, 256>>>(hf, gn, nullptr, za);

    // FFN weight transposes (batched W1,W2) + GEMMs
    dim3 gt12(HIDN/32, DIM/32, 2);
    transpose_half2<<<gt12, 256>>>(W1, W2, fw12, DIM, HIDN);
    dim3 gt3(DIM/32, HIDN/32, 1);
    transpose_half2<<<gt3, 256>>>(W3, W3, fw3, HIDN, DIM);

    dim3 gffn(HIDN/128, SEQ/128, 1);
    mma_gemm<2><<<gffn, 256, SMEM>>>(za, DIM, 0, fw1, DIM, 0, nullptr, nullptr, nullptr, g1h, HIDN, 0, DIM, 1.f);
    mma_gemm<3><<<gffn, 256, SMEM>>>(za, DIM, 0, fw2, DIM, 0, nullptr, nullptr, g1h, ua, HIDN, 0, DIM, 1.f);

    // out = U @ W3 + h
    dim3 gw3(DIM/128, SEQ/128, 1);
    mma_gemm<0><<<gw3, 256, SMEM>>>(ua, HIDN, 0, fw3, HIDN, 0, out, hf, nullptr, nullptr, DIM, 0, HIDN, 1.f);
}